// round 6
// baseline (speedup 1.0000x reference)
#include <cuda_runtime.h>
#include <cuda_bf16.h>
#include <math.h>
#include <stdint.h>

#define S_LEN 2048
#define HID 1280
#define NH 16
#define HD 80
#define INTER 3420
#define NLAYER 8
#define WIN 64
#define MERGED 5120      // 4*HID
#define OUTDIM 3584
#define MTOK 512         // 2048/4
#define HID2 (HID / 2)       // 640 pairs
#define INTER2 (INTER / 2)   // 1710 pairs

// ---------------- scratch (device globals; no allocation allowed) ----------------
__device__ float g_hs  [S_LEN * HID];
__device__ float g_qkv [S_LEN * 3 * HID];
__device__ float g_q   [NH * S_LEN * HD];
__device__ float g_k   [NH * S_LEN * HD];
__device__ float g_v   [NH * S_LEN * HD];
__device__ float g_gate[S_LEN * INTER];
// packed bf16x3 operands (uint2 = {big bf16x2, small bf16x2} covering 2 k-values)
__device__ uint2 g_w1[2560 * 5120];   // qkv_w / fc1_w
__device__ uint2 g_w2[2560 * 3584];   // proj_w / fc2_w
__device__ uint2 g_w3[HID2 * INTER];  // gate_w
__device__ uint2 g_w4[HID2 * INTER];  // up_w
__device__ uint2 g_w5[INTER2 * HID];  // down_w
__device__ uint2 g_xpk  [S_LEN * HID2];
__device__ uint2 g_attpk[S_LEN * HID2];   // also reused as fc1 output (512*2560)
__device__ uint2 g_gatepk[S_LEN * INTER2];

// ---------------- packing helpers ----------------
__device__ __forceinline__ void split_bf16(float x, uint16_t& b, uint16_t& s) {
    __nv_bfloat16 hb = __float2bfloat16(x);
    float r = x - __bfloat162float(hb);
    __nv_bfloat16 hs = __float2bfloat16(r);
    b = *(uint16_t*)&hb;
    s = *(uint16_t*)&hs;
}

__device__ __forceinline__ uint2 pack_pair(float lo, float hi) {
    uint16_t bl, sl, bh, sh;
    split_bf16(lo, bl, sl);
    split_bf16(hi, bh, sh);
    return make_uint2((uint32_t)bl | ((uint32_t)bh << 16),
                      (uint32_t)sl | ((uint32_t)sh << 16));
}

// ---------------- elementwise kernels ----------------
__global__ void copy_k(const float* __restrict__ src, float* __restrict__ dst, int n) {
    int i = blockIdx.x * blockDim.x + threadIdx.x;
    if (i < n) dst[i] = src[i];
}

// convert weights [K][N] fp32 -> [K/2][N] packed uint2 (pairs along K)
__global__ void convert_w_k(const float* __restrict__ W, uint2* __restrict__ out,
                            int K2, int N) {
    long idx = (long)blockIdx.x * blockDim.x + threadIdx.x;
    if (idx >= (long)K2 * N) return;
    int p = (int)(idx / N);
    int c = (int)(idx - (long)p * N);
    out[idx] = pack_pair(W[(long)(2 * p) * N + c], W[(long)(2 * p + 1) * N + c]);
}

// RMSNorm + pack: one block per row of 1280, output packed pairs
__global__ void __launch_bounds__(256) rmsnorm_pack_k(const float* __restrict__ x,
                                                      const float* __restrict__ w,
                                                      uint2* __restrict__ y) {
    int row = blockIdx.x;
    const float* xr = x + (long)row * HID;
    float ss = 0.f;
    for (int i = threadIdx.x; i < HID; i += 256) { float v = xr[i]; ss += v * v; }
    __shared__ float red[8];
    for (int o = 16; o > 0; o >>= 1) ss += __shfl_xor_sync(0xffffffffu, ss, o);
    if ((threadIdx.x & 31) == 0) red[threadIdx.x >> 5] = ss;
    __syncthreads();
    if (threadIdx.x < 32) {
        float v = (threadIdx.x < 8) ? red[threadIdx.x] : 0.f;
        for (int o = 4; o > 0; o >>= 1) v += __shfl_xor_sync(0xffffffffu, v, o);
        if (threadIdx.x == 0) red[0] = v;
    }
    __syncthreads();
    float inv = rsqrtf(red[0] / (float)HID + 1e-6f);
    for (int j = threadIdx.x; j < HID2; j += 256) {
        float v0 = xr[2 * j] * inv * w[2 * j];
        float v1 = xr[2 * j + 1] * inv * w[2 * j + 1];
        y[(long)row * HID2 + j] = pack_pair(v0, v1);
    }
}

// Split qkv [S, 3*HID] -> q,k,v [H,S,D] with RoPE on q,k
__global__ void rope_split_k(const float* __restrict__ qkv,
                             const float* __restrict__ cs,
                             const float* __restrict__ sn,
                             float* __restrict__ gq, float* __restrict__ gk,
                             float* __restrict__ gv) {
    int idx = blockIdx.x * blockDim.x + threadIdx.x;
    if (idx >= S_LEN * HID) return;
    int d = idx % HD;
    int h = (idx / HD) % NH;
    int s = idx / HID;
    const float* base = qkv + (long)s * (3 * HID);
    float c = cs[s * HD + d];
    float si = sn[s * HD + d];
    int f = h * HD + d;
    float qv = base[f];
    float kv = base[HID + f];
    float vv = base[2 * HID + f];
    int dr = (d < HD / 2) ? (d + HD / 2) : (d - HD / 2);
    float sgn = (d < HD / 2) ? -1.f : 1.f;
    float qr = sgn * base[h * HD + dr];
    float kr = sgn * base[HID + h * HD + dr];
    long o = ((long)h * S_LEN + s) * HD + d;
    gq[o] = qv * c + qr * si;
    gk[o] = kv * c + kr * si;
    gv[o] = vv;
}

// ---------------- flash attention (full or 64-window), packed output ----------------
__global__ void __launch_bounds__(256) attn_k(const float* __restrict__ Q,
                                              const float* __restrict__ K,
                                              const float* __restrict__ V,
                                              const float* __restrict__ mask,
                                              int windowed,
                                              uint2* __restrict__ Opk) {
    __shared__ float Ks[64][HD];
    __shared__ float Vs[64][HD];
    int h = blockIdx.y;
    int q0 = blockIdx.x * 64;
    int tid = threadIdx.x;
    int qi = tid >> 2;
    int part = tid & 3;
    int d0 = part * 20;
    int q = q0 + qi;

    const float* Qb = Q + ((long)h * S_LEN + q) * HD;
    float qr[20];
#pragma unroll
    for (int i = 0; i < 20; ++i) qr[i] = Qb[d0 + i];

    float m = -3.0e38f, l = 0.f;
    float oacc[20];
#pragma unroll
    for (int i = 0; i < 20; ++i) oacc[i] = 0.f;

    int kvs = windowed ? q0 : 0;
    int kve = windowed ? q0 + 64 : S_LEN;
    const float scale = 0.11180339887498949f; // 1/sqrt(80)
    const float NEG = -3.0e38f;

    for (int kv0 = kvs; kv0 < kve; kv0 += 64) {
        __syncthreads();
        const float* Kb = K + ((long)h * S_LEN + kv0) * HD;
        const float* Vb = V + ((long)h * S_LEN + kv0) * HD;
        for (int i = tid; i < 64 * HD; i += 256) {
            Ks[i / HD][i % HD] = Kb[i];
            Vs[i / HD][i % HD] = Vb[i];
        }
        __syncthreads();
#pragma unroll 1
        for (int jc = 0; jc < 4; ++jc) {
            float sc[16];
#pragma unroll
            for (int jj = 0; jj < 16; ++jj) {
                int j = jc * 16 + jj;
                float a = 0.f;
#pragma unroll
                for (int dd = 0; dd < 20; ++dd) a += qr[dd] * Ks[j][d0 + dd];
                a += __shfl_xor_sync(0xffffffffu, a, 1);
                a += __shfl_xor_sync(0xffffffffu, a, 2);
                float mv;
                if (windowed)
                    mv = mask[(((long)(q0 >> 6) * 64 + qi) * 64) + j];
                else
                    mv = mask[(long)q * S_LEN + (kv0 + j)];
                sc[jj] = a * scale + (1.f - mv) * NEG;
            }
            float tmax = sc[0];
#pragma unroll
            for (int jj = 1; jj < 16; ++jj) tmax = fmaxf(tmax, sc[jj]);
            float mn = fmaxf(m, tmax);
            float corr = expf(m - mn);
#pragma unroll
            for (int dd = 0; dd < 20; ++dd) oacc[dd] *= corr;
            float ls = 0.f;
#pragma unroll
            for (int jj = 0; jj < 16; ++jj) {
                int j = jc * 16 + jj;
                float p = expf(sc[jj] - mn);
                ls += p;
#pragma unroll
                for (int dd = 0; dd < 20; ++dd) oacc[dd] += p * Vs[j][d0 + dd];
            }
            l = l * corr + ls;
            m = mn;
        }
    }
    float invl = 1.f / l;
    long obase = (long)q * HID2 + h * (HD / 2) + part * 10;
#pragma unroll
    for (int p = 0; p < 10; ++p)
        Opk[obase + p] = pack_pair(oacc[2 * p] * invl, oacc[2 * p + 1] * invl);
}

// ---------------- bf16x3 tensor-core GEMM on pre-packed operands ----------------
// C[M,N] = epi(A @ B + bias)  A: [M][K2] uint2 pairs, B: [K2][N] uint2 pairs
// EPI: 0 none, 1 SiLU, 2 GELU, 3 += res, 4 *= res.  PACK: output packed uint2.
// Block 128x128, BK=32 (16 pairs), 256 thr (8 warps 2x4), warp tile 64x32.
#define GBM 128
#define GBN 128
#define KP 16        // pairs per k-tile
#define ASTR 20      // A smem stride in uint2 (16 + 4 pad)
#define BSTR 132     // B smem stride in uint2

__device__ __forceinline__ void mma_bf16(float c[4], uint32_t a0, uint32_t a1,
                                         uint32_t a2, uint32_t a3,
                                         uint32_t b0, uint32_t b1) {
    asm volatile(
        "mma.sync.aligned.m16n8k16.row.col.f32.bf16.bf16.f32 "
        "{%0,%1,%2,%3}, {%4,%5,%6,%7}, {%8,%9}, {%0,%1,%2,%3};"
        : "+f"(c[0]), "+f"(c[1]), "+f"(c[2]), "+f"(c[3])
        : "r"(a0), "r"(a1), "r"(a2), "r"(a3), "r"(b0), "r"(b1));
}

template <int EPI, bool PACK>
__global__ void __launch_bounds__(256, 2) mmagemm_k(const uint2* __restrict__ A,
                                                    const uint2* __restrict__ B,
                                                    const float* __restrict__ bias,
                                                    const float* __restrict__ res,
                                                    void* __restrict__ Cout,
                                                    int M, int N, int K2) {
    __shared__ uint2 As[GBM][ASTR];
    __shared__ uint2 Bs[KP][BSTR];

    int tid = threadIdx.x;
    int lane = tid & 31;
    int warp = tid >> 5;
    int warpM = warp & 1;     // 64-row half
    int warpN = warp >> 1;    // 32-col quarter
    int g = lane >> 2;        // 0..7
    int tg = lane & 3;        // 0..3

    int bmBase = blockIdx.y * GBM;
    int bnBase = blockIdx.x * GBN;

    float acc[4][4][4];
#pragma unroll
    for (int mi = 0; mi < 4; ++mi)
#pragma unroll
        for (int ni = 0; ni < 4; ++ni)
#pragma unroll
            for (int r = 0; r < 4; ++r) acc[mi][ni][r] = 0.f;

    // A staging: row = tid&127, pair-offset = (tid>>7)*8 (8 uint2 per thread)
    int arow = tid & 127;
    int ah = (tid >> 7) * 8;
    const uint2* Ap = A + (long)(bmBase + arow) * K2 + ah;
    // B staging: pair-rows tid>>5 (+8), cols (tid&31)*4 (4 uint2 per row)
    int bp = tid >> 5;
    int bc = (tid & 31) * 4;
    int gbc = bnBase + bc;

    int ntile = (K2 + KP - 1) / KP;
    for (int t = 0; t < ntile; ++t) {
        int tp = t * KP;
        // --- stage A ---
#pragma unroll
        for (int j = 0; j < 8; ++j) {
            uint2 v = make_uint2(0u, 0u);
            if (tp + ah + j < K2) v = Ap[tp + j];
            As[arow][ah + j] = v;
        }
        // --- stage B ---
#pragma unroll
        for (int rr = 0; rr < 2; ++rr) {
            int pr = bp + rr * 8;
            int p = tp + pr;
            const uint2* Bp = B + (long)p * N;
#pragma unroll
            for (int c = 0; c < 4; ++c) {
                uint2 v = make_uint2(0u, 0u);
                if (p < K2 && gbc + c < N) v = Bp[gbc + c];
                Bs[pr][bc + c] = v;
            }
        }
        __syncthreads();

        // --- compute: 2 chunks of 8 pairs (k16 each) ---
#pragma unroll
        for (int ck = 0; ck < 2; ++ck) {
            int c8 = ck * 8;
            uint2 b0[4], b1[4];
#pragma unroll
            for (int ni = 0; ni < 4; ++ni) {
                int n = warpN * 32 + ni * 8 + g;
                b0[ni] = Bs[c8 + tg][n];
                b1[ni] = Bs[c8 + tg + 4][n];
            }
#pragma unroll
            for (int mi = 0; mi < 4; ++mi) {
                int m = warpM * 64 + mi * 16 + g;
                uint2 a0 = As[m][c8 + tg];
                uint2 a1 = As[m + 8][c8 + tg];
                uint2 a2 = As[m][c8 + tg + 4];
                uint2 a3 = As[m + 8][c8 + tg + 4];
#pragma unroll
                for (int ni = 0; ni < 4; ++ni)
                    mma_bf16(acc[mi][ni], a0.x, a1.x, a2.x, a3.x, b0[ni].x, b1[ni].x);
#pragma unroll
                for (int ni = 0; ni < 4; ++ni)
                    mma_bf16(acc[mi][ni], a0.x, a1.x, a2.x, a3.x, b0[ni].y, b1[ni].y);
#pragma unroll
                for (int ni = 0; ni < 4; ++ni)
                    mma_bf16(acc[mi][ni], a0.y, a1.y, a2.y, a3.y, b0[ni].x, b1[ni].x);
            }
        }
        __syncthreads();
    }

    // ---- epilogue ----  c0=(g,2tg) c1=(g,2tg+1) c2=(g+8,2tg) c3=(g+8,2tg+1)
    float* Cf = (float*)Cout;
    uint2* Cp = (uint2*)Cout;
#pragma unroll
    for (int mi = 0; mi < 4; ++mi) {
        int row0 = bmBase + warpM * 64 + mi * 16 + g;
#pragma unroll
        for (int ni = 0; ni < 4; ++ni) {
            int col = bnBase + warpN * 32 + ni * 8 + 2 * tg;
            if (col >= N) continue;
            float b0 = bias[col], b1 = bias[col + 1];
#pragma unroll
            for (int rh = 0; rh < 2; ++rh) {
                int row = row0 + rh * 8;
                float v0 = acc[mi][ni][rh * 2 + 0] + b0;
                float v1 = acc[mi][ni][rh * 2 + 1] + b1;
                if (EPI == 1) {
                    v0 = v0 / (1.f + expf(-v0));
                    v1 = v1 / (1.f + expf(-v1));
                } else if (EPI == 2) {
                    v0 = 0.5f * v0 * (1.f + erff(v0 * 0.70710678118654752f));
                    v1 = 0.5f * v1 * (1.f + erff(v1 * 0.70710678118654752f));
                } else if (EPI == 3) {
                    v0 += res[(long)row * N + col];
                    v1 += res[(long)row * N + col + 1];
                } else if (EPI == 4) {
                    v0 *= res[(long)row * N + col];
                    v1 *= res[(long)row * N + col + 1];
                }
                if (PACK) {
                    Cp[(long)row * (N / 2) + col / 2] = pack_pair(v0, v1);
                } else {
                    Cf[(long)row * N + col] = v0;
                    Cf[(long)row * N + col + 1] = v1;
                }
            }
        }
    }
}

// ---------------- host ----------------
static inline dim3 gemm_grid(int M, int N) { return dim3((N + GBN - 1) / GBN, M / GBM); }

static inline void conv_w(const float* W, uint2* out, int K2, int N) {
    long n = (long)K2 * N;
    convert_w_k<<<(unsigned)((n + 255) / 256), 256>>>(W, out, K2, N);
}

extern "C" void kernel_launch(void* const* d_in, const int* in_sizes, int n_in,
                              void* d_out, int out_size) {
    const float* in_hs   = (const float*)d_in[0];
    const float* fmask   = (const float*)d_in[1];
    const float* wmask   = (const float*)d_in[2];
    const float* cosd    = (const float*)d_in[3];
    const float* sind    = (const float*)d_in[4];
    const float* norm1_w = (const float*)d_in[5];
    const float* norm2_w = (const float*)d_in[6];
    const float* qkv_w   = (const float*)d_in[7];
    const float* qkv_b   = (const float*)d_in[8];
    const float* proj_w  = (const float*)d_in[9];
    const float* proj_b  = (const float*)d_in[10];
    const float* gate_w  = (const float*)d_in[11];
    const float* gate_b  = (const float*)d_in[12];
    const float* up_w    = (const float*)d_in[13];
    const float* up_b    = (const float*)d_in[14];
    const float* down_w  = (const float*)d_in[15];
    const float* down_b  = (const float*)d_in[16];
    const float* ln_q_w  = (const float*)d_in[17];
    const float* fc1_w   = (const float*)d_in[18];
    const float* fc1_b   = (const float*)d_in[19];
    const float* fc2_w   = (const float*)d_in[20];
    const float* fc2_b   = (const float*)d_in[21];
    float* out = (float*)d_out;

    float *hs, *qkv, *q, *k, *v, *gate;
    uint2 *w1, *w2, *w3, *w4, *w5, *xpk, *attpk, *gatepk;
    cudaGetSymbolAddress((void**)&hs, g_hs);
    cudaGetSymbolAddress((void**)&qkv, g_qkv);
    cudaGetSymbolAddress((void**)&q, g_q);
    cudaGetSymbolAddress((void**)&k, g_k);
    cudaGetSymbolAddress((void**)&v, g_v);
    cudaGetSymbolAddress((void**)&gate, g_gate);
    cudaGetSymbolAddress((void**)&w1, g_w1);
    cudaGetSymbolAddress((void**)&w2, g_w2);
    cudaGetSymbolAddress((void**)&w3, g_w3);
    cudaGetSymbolAddress((void**)&w4, g_w4);
    cudaGetSymbolAddress((void**)&w5, g_w5);
    cudaGetSymbolAddress((void**)&xpk, g_xpk);
    cudaGetSymbolAddress((void**)&attpk, g_attpk);
    cudaGetSymbolAddress((void**)&gatepk, g_gatepk);

    const int nhid = S_LEN * HID;
    copy_k<<<(nhid + 255) / 256, 256>>>(in_hs, hs, nhid);

    for (int i = 0; i < NLAYER; ++i) {
        int full = (i == 3 || i == 7) ? 1 : 0;
        // convert this layer's weights to packed bf16x3
        conv_w(qkv_w + (long)i * HID * 3 * HID, w1, HID2, 3 * HID);
        conv_w(proj_w + (long)i * HID * HID, w2, HID2, HID);
        conv_w(gate_w + (long)i * HID * INTER, w3, HID2, INTER);
        conv_w(up_w + (long)i * HID * INTER, w4, HID2, INTER);
        conv_w(down_w + (long)i * INTER * HID, w5, INTER2, HID);

        rmsnorm_pack_k<<<S_LEN, 256>>>(hs, norm1_w + (long)i * HID, xpk);
        mmagemm_k<0, false><<<gemm_grid(S_LEN, 3 * HID), 256>>>(
            xpk, w1, qkv_b + (long)i * 3 * HID, nullptr, qkv, S_LEN, 3 * HID, HID2);
        rope_split_k<<<(nhid + 255) / 256, 256>>>(qkv, cosd, sind, q, k, v);
        attn_k<<<dim3(S_LEN / 64, NH), 256>>>(q, k, v, full ? fmask : wmask,
                                              full ? 0 : 1, attpk);
        mmagemm_k<3, false><<<gemm_grid(S_LEN, HID), 256>>>(
            attpk, w2, proj_b + (long)i * HID, hs, hs, S_LEN, HID, HID2);
        rmsnorm_pack_k<<<S_LEN, 256>>>(hs, norm2_w + (long)i * HID, xpk);
        // gate = silu(x @ gate_w + gate_b)   (fp32, used as res below)
        mmagemm_k<1, false><<<gemm_grid(S_LEN, INTER), 256>>>(
            xpk, w3, gate_b + (long)i * INTER, nullptr, gate, S_LEN, INTER, HID2);
        // gatepk = pack((x @ up_w + up_b) * gate)
        mmagemm_k<4, true><<<gemm_grid(S_LEN, INTER), 256>>>(
            xpk, w4, up_b + (long)i * INTER, gate, gatepk, S_LEN, INTER, HID2);
        // hs += gatepk @ down_w + down_b
        mmagemm_k<3, false><<<gemm_grid(S_LEN, HID), 256>>>(
            gatepk, w5, down_b + (long)i * HID, hs, hs, S_LEN, HID, INTER2);
    }

    // patch merger
    conv_w(fc1_w, w1, MERGED / 2, MERGED);
    conv_w(fc2_w, w2, MERGED / 2, OUTDIM);
    rmsnorm_pack_k<<<S_LEN, 256>>>(hs, ln_q_w, xpk);   // viewed as [512][2560] pairs
    mmagemm_k<2, true><<<gemm_grid(MTOK, MERGED), 256>>>(
        xpk, w1, fc1_b, nullptr, attpk, MTOK, MERGED, MERGED / 2);
    mmagemm_k<0, false><<<gemm_grid(MTOK, OUTDIM), 256>>>(
        attpk, w2, fc2_b, nullptr, out, MTOK, OUTDIM, MERGED / 2);
}

// round 7
// speedup vs baseline: 1.2955x; 1.2955x over previous
#include <cuda_runtime.h>
#include <cuda_bf16.h>
#include <math.h>
#include <stdint.h>

#define S_LEN 2048
#define HID 1280
#define NH 16
#define HD 80
#define INTER 3420
#define NLAYER 8
#define WIN 64
#define MERGED 5120      // 4*HID
#define OUTDIM 3584
#define MTOK 512         // 2048/4
#define HID2 (HID / 2)       // 640 pairs
#define INTER2 (INTER / 2)   // 1710 pairs

// ---------------- scratch (device globals; no allocation allowed) ----------------
__device__ float g_hs  [S_LEN * HID];
__device__ float g_qkv [S_LEN * 3 * HID];
__device__ float g_q   [NH * S_LEN * HD];
__device__ float g_k   [NH * S_LEN * HD];
__device__ float g_v   [NH * S_LEN * HD];
__device__ float g_gate[S_LEN * INTER];
// packed bf16x3 operands (uint2 = {big bf16x2, small bf16x2} covering 2 k-values)
__device__ uint2 g_w1[2560 * 5120];   // qkv_w / fc1_w
__device__ uint2 g_w2[2560 * 3584];   // proj_w / fc2_w
__device__ uint2 g_w3[HID2 * INTER];  // gate_w
__device__ uint2 g_w4[HID2 * INTER];  // up_w
__device__ uint2 g_w5[INTER2 * HID];  // down_w
__device__ uint2 g_xpk  [S_LEN * HID2];
__device__ uint2 g_attpk[S_LEN * HID2];   // also reused as fc1 output (512*2560)
__device__ uint2 g_gatepk[S_LEN * INTER2];

// ---------------- packing helpers ----------------
__device__ __forceinline__ void split_bf16(float x, uint16_t& b, uint16_t& s) {
    __nv_bfloat16 hb = __float2bfloat16(x);
    float r = x - __bfloat162float(hb);
    __nv_bfloat16 hs = __float2bfloat16(r);
    b = *(uint16_t*)&hb;
    s = *(uint16_t*)&hs;
}

__device__ __forceinline__ uint2 pack_pair(float lo, float hi) {
    uint16_t bl, sl, bh, sh;
    split_bf16(lo, bl, sl);
    split_bf16(hi, bh, sh);
    return make_uint2((uint32_t)bl | ((uint32_t)bh << 16),
                      (uint32_t)sl | ((uint32_t)sh << 16));
}

// ---------------- elementwise kernels ----------------
__global__ void copy_k(const float* __restrict__ src, float* __restrict__ dst, int n) {
    int i = blockIdx.x * blockDim.x + threadIdx.x;
    if (i < n) dst[i] = src[i];
}

// convert weights [K][N] fp32 -> [K/2][N] packed uint2 (pairs along K)
__global__ void convert_w_k(const float* __restrict__ W, uint2* __restrict__ out,
                            int K2, int N) {
    long idx = (long)blockIdx.x * blockDim.x + threadIdx.x;
    if (idx >= (long)K2 * N) return;
    int p = (int)(idx / N);
    int c = (int)(idx - (long)p * N);
    out[idx] = pack_pair(W[(long)(2 * p) * N + c], W[(long)(2 * p + 1) * N + c]);
}

// RMSNorm + pack: one block per row of 1280, output packed pairs
__global__ void __launch_bounds__(256) rmsnorm_pack_k(const float* __restrict__ x,
                                                      const float* __restrict__ w,
                                                      uint2* __restrict__ y) {
    int row = blockIdx.x;
    const float* xr = x + (long)row * HID;
    float ss = 0.f;
    for (int i = threadIdx.x; i < HID; i += 256) { float v = xr[i]; ss += v * v; }
    __shared__ float red[8];
    for (int o = 16; o > 0; o >>= 1) ss += __shfl_xor_sync(0xffffffffu, ss, o);
    if ((threadIdx.x & 31) == 0) red[threadIdx.x >> 5] = ss;
    __syncthreads();
    if (threadIdx.x < 32) {
        float v = (threadIdx.x < 8) ? red[threadIdx.x] : 0.f;
        for (int o = 4; o > 0; o >>= 1) v += __shfl_xor_sync(0xffffffffu, v, o);
        if (threadIdx.x == 0) red[0] = v;
    }
    __syncthreads();
    float inv = rsqrtf(red[0] / (float)HID + 1e-6f);
    for (int j = threadIdx.x; j < HID2; j += 256) {
        float v0 = xr[2 * j] * inv * w[2 * j];
        float v1 = xr[2 * j + 1] * inv * w[2 * j + 1];
        y[(long)row * HID2 + j] = pack_pair(v0, v1);
    }
}

// Split qkv [S, 3*HID] -> q,k,v [H,S,D] with RoPE on q,k
__global__ void rope_split_k(const float* __restrict__ qkv,
                             const float* __restrict__ cs,
                             const float* __restrict__ sn,
                             float* __restrict__ gq, float* __restrict__ gk,
                             float* __restrict__ gv) {
    int idx = blockIdx.x * blockDim.x + threadIdx.x;
    if (idx >= S_LEN * HID) return;
    int d = idx % HD;
    int h = (idx / HD) % NH;
    int s = idx / HID;
    const float* base = qkv + (long)s * (3 * HID);
    float c = cs[s * HD + d];
    float si = sn[s * HD + d];
    int f = h * HD + d;
    float qv = base[f];
    float kv = base[HID + f];
    float vv = base[2 * HID + f];
    int dr = (d < HD / 2) ? (d + HD / 2) : (d - HD / 2);
    float sgn = (d < HD / 2) ? -1.f : 1.f;
    float qr = sgn * base[h * HD + dr];
    float kr = sgn * base[HID + h * HD + dr];
    long o = ((long)h * S_LEN + s) * HD + d;
    gq[o] = qv * c + qr * si;
    gk[o] = kv * c + kr * si;
    gv[o] = vv;
}

// ---------------- flash attention (full or 64-window), packed output ----------------
__global__ void __launch_bounds__(256) attn_k(const float* __restrict__ Q,
                                              const float* __restrict__ K,
                                              const float* __restrict__ V,
                                              const float* __restrict__ mask,
                                              int windowed,
                                              uint2* __restrict__ Opk) {
    __shared__ float Ks[64][HD];
    __shared__ float Vs[64][HD];
    int h = blockIdx.y;
    int q0 = blockIdx.x * 64;
    int tid = threadIdx.x;
    int qi = tid >> 2;
    int part = tid & 3;
    int d0 = part * 20;
    int q = q0 + qi;

    const float* Qb = Q + ((long)h * S_LEN + q) * HD;
    float qr[20];
#pragma unroll
    for (int i = 0; i < 20; ++i) qr[i] = Qb[d0 + i];

    float m = -3.0e38f, l = 0.f;
    float oacc[20];
#pragma unroll
    for (int i = 0; i < 20; ++i) oacc[i] = 0.f;

    int kvs = windowed ? q0 : 0;
    int kve = windowed ? q0 + 64 : S_LEN;
    const float scale = 0.11180339887498949f; // 1/sqrt(80)
    const float NEG = -3.0e38f;

    for (int kv0 = kvs; kv0 < kve; kv0 += 64) {
        __syncthreads();
        const float* Kb = K + ((long)h * S_LEN + kv0) * HD;
        const float* Vb = V + ((long)h * S_LEN + kv0) * HD;
        for (int i = tid; i < 64 * HD; i += 256) {
            Ks[i / HD][i % HD] = Kb[i];
            Vs[i / HD][i % HD] = Vb[i];
        }
        __syncthreads();
#pragma unroll 1
        for (int jc = 0; jc < 4; ++jc) {
            float sc[16];
#pragma unroll
            for (int jj = 0; jj < 16; ++jj) {
                int j = jc * 16 + jj;
                float a = 0.f;
#pragma unroll
                for (int dd = 0; dd < 20; ++dd) a += qr[dd] * Ks[j][d0 + dd];
                a += __shfl_xor_sync(0xffffffffu, a, 1);
                a += __shfl_xor_sync(0xffffffffu, a, 2);
                float mv;
                if (windowed)
                    mv = mask[(((long)(q0 >> 6) * 64 + qi) * 64) + j];
                else
                    mv = mask[(long)q * S_LEN + (kv0 + j)];
                sc[jj] = a * scale + (1.f - mv) * NEG;
            }
            float tmax = sc[0];
#pragma unroll
            for (int jj = 1; jj < 16; ++jj) tmax = fmaxf(tmax, sc[jj]);
            float mn = fmaxf(m, tmax);
            float corr = expf(m - mn);
#pragma unroll
            for (int dd = 0; dd < 20; ++dd) oacc[dd] *= corr;
            float ls = 0.f;
#pragma unroll
            for (int jj = 0; jj < 16; ++jj) {
                int j = jc * 16 + jj;
                float p = expf(sc[jj] - mn);
                ls += p;
#pragma unroll
                for (int dd = 0; dd < 20; ++dd) oacc[dd] += p * Vs[j][d0 + dd];
            }
            l = l * corr + ls;
            m = mn;
        }
    }
    float invl = 1.f / l;
    long obase = (long)q * HID2 + h * (HD / 2) + part * 10;
#pragma unroll
    for (int p = 0; p < 10; ++p)
        Opk[obase + p] = pack_pair(oacc[2 * p] * invl, oacc[2 * p + 1] * invl);
}

// ---------------- bf16x3 tensor-core GEMM on pre-packed operands ----------------
// C[M,N] = epi(A @ B + bias)  A: [M][K2] uint2 pairs, B: [K2][N] uint2 pairs
// EPI: 0 none, 1 SiLU, 2 GELU, 3 += res, 4 *= res.  PACK: output packed uint2.
// Block 128x128, BK=32 (KP=16 pairs), 256 thr (8 warps 2x4), warp tile 64x32.
// smem k-major [pair][col] stride 132 uint2 -> conflict-free STS.64 / LDS.64.
#define GBM 128
#define GBN 128
#define KP 16        // pairs per k-tile
#define SSTRU 132    // smem row stride in uint2

__device__ __forceinline__ void mma_bf16(float c[4], uint32_t a0, uint32_t a1,
                                         uint32_t a2, uint32_t a3,
                                         uint32_t b0, uint32_t b1) {
    asm volatile(
        "mma.sync.aligned.m16n8k16.row.col.f32.bf16.bf16.f32 "
        "{%0,%1,%2,%3}, {%4,%5,%6,%7}, {%8,%9}, {%0,%1,%2,%3};"
        : "+f"(c[0]), "+f"(c[1]), "+f"(c[2]), "+f"(c[3])
        : "r"(a0), "r"(a1), "r"(a2), "r"(a3), "r"(b0), "r"(b1));
}

template <int EPI, bool PACK>
__global__ void __launch_bounds__(256, 2) mmagemm_k(const uint2* __restrict__ A,
                                                    const uint2* __restrict__ B,
                                                    const float* __restrict__ bias,
                                                    const float* __restrict__ res,
                                                    void* __restrict__ Cout,
                                                    int M, int N, int K2) {
    __shared__ uint2 As[KP][SSTRU];
    __shared__ uint2 Bs[KP][SSTRU];

    int tid = threadIdx.x;
    int lane = tid & 31;
    int warp = tid >> 5;
    int warpM = warp & 1;     // 64-row half
    int warpN = warp >> 1;    // 32-col quarter
    int g = lane >> 2;        // 0..7
    int tg = lane & 3;        // 0..3

    int bmBase = blockIdx.y * GBM;
    int bnBase = blockIdx.x * GBN;

    float acc[4][4][4];
#pragma unroll
    for (int mi = 0; mi < 4; ++mi)
#pragma unroll
        for (int ni = 0; ni < 4; ++ni)
#pragma unroll
            for (int r = 0; r < 4; ++r) acc[mi][ni][r] = 0.f;

    // A staging: row = tid&127, pair-offset half = (tid>>7)*8 (8 uint2 per thread)
    int arow = tid & 127;
    int ah = (tid >> 7) * 8;
    const uint2* Ap = A + (long)(bmBase + arow) * K2 + ah;
    // B staging: pair-rows tid>>5 (+8); cols lane + 32c (coalesced, conflict-free)
    int bp = tid >> 5;

    int ntile = (K2 + KP - 1) / KP;
    for (int t = 0; t < ntile; ++t) {
        int tp = t * KP;
        // --- stage A: 8 pairs of row arow -> As[ah+j][arow] ---
        if (tp + KP <= K2) {
            const uint4* Ap4 = (const uint4*)(Ap + tp);
#pragma unroll
            for (int j4 = 0; j4 < 4; ++j4) {
                uint4 v = Ap4[j4];
                As[ah + 2 * j4][arow] = make_uint2(v.x, v.y);
                As[ah + 2 * j4 + 1][arow] = make_uint2(v.z, v.w);
            }
        } else {
#pragma unroll
            for (int j = 0; j < 8; ++j) {
                uint2 v = make_uint2(0u, 0u);
                if (tp + ah + j < K2) v = Ap[tp + j];
                As[ah + j][arow] = v;
            }
        }
        // --- stage B: rows bp, bp+8; cols lane+32c ---
#pragma unroll
        for (int rr = 0; rr < 2; ++rr) {
            int pr = bp + rr * 8;
            int p = tp + pr;
            const uint2* Bp = B + (long)p * N + bnBase;
#pragma unroll
            for (int c = 0; c < 4; ++c) {
                int col = lane + 32 * c;
                uint2 v = make_uint2(0u, 0u);
                if (p < K2 && bnBase + col < N) v = Bp[col];
                Bs[pr][col] = v;
            }
        }
        __syncthreads();

        // --- compute: 2 chunks of 8 pairs (k16 each) ---
#pragma unroll
        for (int ck = 0; ck < 2; ++ck) {
            int c8 = ck * 8;
            uint2 b0[4], b1[4];
#pragma unroll
            for (int ni = 0; ni < 4; ++ni) {
                int n = warpN * 32 + ni * 8 + g;
                b0[ni] = Bs[c8 + tg][n];
                b1[ni] = Bs[c8 + tg + 4][n];
            }
#pragma unroll
            for (int mi = 0; mi < 4; ++mi) {
                int m = warpM * 64 + mi * 16 + g;
                uint2 a0 = As[c8 + tg][m];
                uint2 a1 = As[c8 + tg][m + 8];
                uint2 a2 = As[c8 + tg + 4][m];
                uint2 a3 = As[c8 + tg + 4][m + 8];
#pragma unroll
                for (int ni = 0; ni < 4; ++ni)
                    mma_bf16(acc[mi][ni], a0.x, a1.x, a2.x, a3.x, b0[ni].x, b1[ni].x);
#pragma unroll
                for (int ni = 0; ni < 4; ++ni)
                    mma_bf16(acc[mi][ni], a0.x, a1.x, a2.x, a3.x, b0[ni].y, b1[ni].y);
#pragma unroll
                for (int ni = 0; ni < 4; ++ni)
                    mma_bf16(acc[mi][ni], a0.y, a1.y, a2.y, a3.y, b0[ni].x, b1[ni].x);
            }
        }
        __syncthreads();
    }

    // ---- epilogue ----  c0=(g,2tg) c1=(g,2tg+1) c2=(g+8,2tg) c3=(g+8,2tg+1)
    float* Cf = (float*)Cout;
    uint2* Cp = (uint2*)Cout;
#pragma unroll
    for (int mi = 0; mi < 4; ++mi) {
        int row0 = bmBase + warpM * 64 + mi * 16 + g;
#pragma unroll
        for (int ni = 0; ni < 4; ++ni) {
            int col = bnBase + warpN * 32 + ni * 8 + 2 * tg;
            if (col >= N) continue;
            float b0 = bias[col], b1 = bias[col + 1];
#pragma unroll
            for (int rh = 0; rh < 2; ++rh) {
                int row = row0 + rh * 8;
                float v0 = acc[mi][ni][rh * 2 + 0] + b0;
                float v1 = acc[mi][ni][rh * 2 + 1] + b1;
                if (EPI == 1) {
                    v0 = v0 / (1.f + expf(-v0));
                    v1 = v1 / (1.f + expf(-v1));
                } else if (EPI == 2) {
                    v0 = 0.5f * v0 * (1.f + erff(v0 * 0.70710678118654752f));
                    v1 = 0.5f * v1 * (1.f + erff(v1 * 0.70710678118654752f));
                } else if (EPI == 3) {
                    v0 += res[(long)row * N + col];
                    v1 += res[(long)row * N + col + 1];
                } else if (EPI == 4) {
                    v0 *= res[(long)row * N + col];
                    v1 *= res[(long)row * N + col + 1];
                }
                if (PACK) {
                    Cp[(long)row * (N / 2) + col / 2] = pack_pair(v0, v1);
                } else {
                    Cf[(long)row * N + col] = v0;
                    Cf[(long)row * N + col + 1] = v1;
                }
            }
        }
    }
}

// ---------------- host ----------------
static inline dim3 gemm_grid(int M, int N) { return dim3((N + GBN - 1) / GBN, M / GBM); }

static inline void conv_w(const float* W, uint2* out, int K2, int N) {
    long n = (long)K2 * N;
    convert_w_k<<<(unsigned)((n + 255) / 256), 256>>>(W, out, K2, N);
}

extern "C" void kernel_launch(void* const* d_in, const int* in_sizes, int n_in,
                              void* d_out, int out_size) {
    const float* in_hs   = (const float*)d_in[0];
    const float* fmask   = (const float*)d_in[1];
    const float* wmask   = (const float*)d_in[2];
    const float* cosd    = (const float*)d_in[3];
    const float* sind    = (const float*)d_in[4];
    const float* norm1_w = (const float*)d_in[5];
    const float* norm2_w = (const float*)d_in[6];
    const float* qkv_w   = (const float*)d_in[7];
    const float* qkv_b   = (const float*)d_in[8];
    const float* proj_w  = (const float*)d_in[9];
    const float* proj_b  = (const float*)d_in[10];
    const float* gate_w  = (const float*)d_in[11];
    const float* gate_b  = (const float*)d_in[12];
    const float* up_w    = (const float*)d_in[13];
    const float* up_b    = (const float*)d_in[14];
    const float* down_w  = (const float*)d_in[15];
    const float* down_b  = (const float*)d_in[16];
    const float* ln_q_w  = (const float*)d_in[17];
    const float* fc1_w   = (const float*)d_in[18];
    const float* fc1_b   = (const float*)d_in[19];
    const float* fc2_w   = (const float*)d_in[20];
    const float* fc2_b   = (const float*)d_in[21];
    float* out = (float*)d_out;

    float *hs, *qkv, *q, *k, *v, *gate;
    uint2 *w1, *w2, *w3, *w4, *w5, *xpk, *attpk, *gatepk;
    cudaGetSymbolAddress((void**)&hs, g_hs);
    cudaGetSymbolAddress((void**)&qkv, g_qkv);
    cudaGetSymbolAddress((void**)&q, g_q);
    cudaGetSymbolAddress((void**)&k, g_k);
    cudaGetSymbolAddress((void**)&v, g_v);
    cudaGetSymbolAddress((void**)&gate, g_gate);
    cudaGetSymbolAddress((void**)&w1, g_w1);
    cudaGetSymbolAddress((void**)&w2, g_w2);
    cudaGetSymbolAddress((void**)&w3, g_w3);
    cudaGetSymbolAddress((void**)&w4, g_w4);
    cudaGetSymbolAddress((void**)&w5, g_w5);
    cudaGetSymbolAddress((void**)&xpk, g_xpk);
    cudaGetSymbolAddress((void**)&attpk, g_attpk);
    cudaGetSymbolAddress((void**)&gatepk, g_gatepk);

    const int nhid = S_LEN * HID;
    copy_k<<<(nhid + 255) / 256, 256>>>(in_hs, hs, nhid);

    for (int i = 0; i < NLAYER; ++i) {
        int full = (i == 3 || i == 7) ? 1 : 0;
        // convert this layer's weights to packed bf16x3
        conv_w(qkv_w + (long)i * HID * 3 * HID, w1, HID2, 3 * HID);
        conv_w(proj_w + (long)i * HID * HID, w2, HID2, HID);
        conv_w(gate_w + (long)i * HID * INTER, w3, HID2, INTER);
        conv_w(up_w + (long)i * HID * INTER, w4, HID2, INTER);
        conv_w(down_w + (long)i * INTER * HID, w5, INTER2, HID);

        rmsnorm_pack_k<<<S_LEN, 256>>>(hs, norm1_w + (long)i * HID, xpk);
        mmagemm_k<0, false><<<gemm_grid(S_LEN, 3 * HID), 256>>>(
            xpk, w1, qkv_b + (long)i * 3 * HID, nullptr, qkv, S_LEN, 3 * HID, HID2);
        rope_split_k<<<(nhid + 255) / 256, 256>>>(qkv, cosd, sind, q, k, v);
        attn_k<<<dim3(S_LEN / 64, NH), 256>>>(q, k, v, full ? fmask : wmask,
                                              full ? 0 : 1, attpk);
        mmagemm_k<3, false><<<gemm_grid(S_LEN, HID), 256>>>(
            attpk, w2, proj_b + (long)i * HID, hs, hs, S_LEN, HID, HID2);
        rmsnorm_pack_k<<<S_LEN, 256>>>(hs, norm2_w + (long)i * HID, xpk);
        // gate = silu(x @ gate_w + gate_b)   (fp32, used as res below)
        mmagemm_k<1, false><<<gemm_grid(S_LEN, INTER), 256>>>(
            xpk, w3, gate_b + (long)i * INTER, nullptr, gate, S_LEN, INTER, HID2);
        // gatepk = pack((x @ up_w + up_b) * gate)
        mmagemm_k<4, true><<<gemm_grid(S_LEN, INTER), 256>>>(
            xpk, w4, up_b + (long)i * INTER, gate, gatepk, S_LEN, INTER, HID2);
        // hs += gatepk @ down_w + down_b
        mmagemm_k<3, false><<<gemm_grid(S_LEN, HID), 256>>>(
            gatepk, w5, down_b + (long)i * HID, hs, hs, S_LEN, HID, INTER2);
    }

    // patch merger
    conv_w(fc1_w, w1, MERGED / 2, MERGED);
    conv_w(fc2_w, w2, MERGED / 2, OUTDIM);
    rmsnorm_pack_k<<<S_LEN, 256>>>(hs, ln_q_w, xpk);   // viewed as [512][2560] pairs
    mmagemm_k<2, true><<<gemm_grid(MTOK, MERGED), 256>>>(
        xpk, w1, fc1_b, nullptr, attpk, MTOK, MERGED, MERGED / 2);
    mmagemm_k<0, false><<<gemm_grid(MTOK, OUTDIM), 256>>>(
        attpk, w2, fc2_b, nullptr, out, MTOK, OUTDIM, MERGED / 2);
}

// round 8
// speedup vs baseline: 1.5671x; 1.2096x over previous
#include <cuda_runtime.h>
#include <cuda_bf16.h>
#include <math.h>
#include <stdint.h>

#define S_LEN 2048
#define HID 1280
#define NH 16
#define HD 80
#define INTER 3420
#define NLAYER 8
#define WIN 64
#define MERGED 5120      // 4*HID
#define OUTDIM 3584
#define MTOK 512         // 2048/4
#define HID2 (HID / 2)       // 640 pairs
#define INTER2 (INTER / 2)   // 1710 pairs

// ---------------- scratch (device globals; no allocation allowed) ----------------
__device__ float g_hs  [S_LEN * HID];
__device__ float g_qkv [S_LEN * 3 * HID];
__device__ float g_q   [NH * S_LEN * HD];
__device__ float g_k   [NH * S_LEN * HD];
__device__ float g_v   [NH * S_LEN * HD];
__device__ float g_gate[S_LEN * INTER];
// packed bf16x3 operands (uint2 = {big bf16x2, small bf16x2} covering 2 k-values)
// weights: [K2 pairs][N]; activations: K-MAJOR [K2 pairs][M]
__device__ uint2 g_w1[2560 * 5120];   // qkv_w / fc1_w
__device__ uint2 g_w2[2560 * 3584];   // proj_w / fc2_w
__device__ uint2 g_w3[HID2 * INTER];  // gate_w
__device__ uint2 g_w4[HID2 * INTER];  // up_w
__device__ uint2 g_w5[INTER2 * HID];  // down_w
__device__ uint2 g_xpk  [2560 * 2048];    // rmsnorm out (k-major; big enough for merger view)
__device__ uint2 g_attpk[2560 * 2048];    // attn out / fc1 out (k-major)
__device__ uint2 g_gatepk[INTER2 * S_LEN];

// ---------------- packing helpers ----------------
__device__ __forceinline__ void split_bf16(float x, uint16_t& b, uint16_t& s) {
    __nv_bfloat16 hb = __float2bfloat16(x);
    float r = x - __bfloat162float(hb);
    __nv_bfloat16 hs = __float2bfloat16(r);
    b = *(uint16_t*)&hb;
    s = *(uint16_t*)&hs;
}

__device__ __forceinline__ uint2 pack_pair(float lo, float hi) {
    uint16_t bl, sl, bh, sh;
    split_bf16(lo, bl, sl);
    split_bf16(hi, bh, sh);
    return make_uint2((uint32_t)bl | ((uint32_t)bh << 16),
                      (uint32_t)sl | ((uint32_t)sh << 16));
}

// ---------------- elementwise kernels ----------------
__global__ void copy_k(const float* __restrict__ src, float* __restrict__ dst, int n) {
    int i = blockIdx.x * blockDim.x + threadIdx.x;
    if (i < n) dst[i] = src[i];
}

// convert weights [K][N] fp32 -> [K/2][N] packed uint2 (pairs along K)
__global__ void convert_w_k(const float* __restrict__ W, uint2* __restrict__ out,
                            int K2, int N) {
    long idx = (long)blockIdx.x * blockDim.x + threadIdx.x;
    if (idx >= (long)K2 * N) return;
    int p = (int)(idx / N);
    int c = (int)(idx - (long)p * N);
    out[idx] = pack_pair(W[(long)(2 * p) * N + c], W[(long)(2 * p + 1) * N + c]);
}

// RMSNorm + pack, K-MAJOR output.
// MERGER=false: y[j * 2048 + row]  (j = pair index over 640)
// MERGER=true : merger view [512 x 5120]: y[((row&3)*640 + j) * 512 + (row>>2)]
template <bool MERGER>
__global__ void __launch_bounds__(256) rmsnorm_pack_k(const float* __restrict__ x,
                                                      const float* __restrict__ w,
                                                      uint2* __restrict__ y) {
    int row = blockIdx.x;
    const float* xr = x + (long)row * HID;
    float ss = 0.f;
    for (int i = threadIdx.x; i < HID; i += 256) { float v = xr[i]; ss += v * v; }
    __shared__ float red[8];
    for (int o = 16; o > 0; o >>= 1) ss += __shfl_xor_sync(0xffffffffu, ss, o);
    if ((threadIdx.x & 31) == 0) red[threadIdx.x >> 5] = ss;
    __syncthreads();
    if (threadIdx.x < 32) {
        float v = (threadIdx.x < 8) ? red[threadIdx.x] : 0.f;
        for (int o = 4; o > 0; o >>= 1) v += __shfl_xor_sync(0xffffffffu, v, o);
        if (threadIdx.x == 0) red[0] = v;
    }
    __syncthreads();
    float inv = rsqrtf(red[0] / (float)HID + 1e-6f);
    for (int j = threadIdx.x; j < HID2; j += 256) {
        float v0 = xr[2 * j] * inv * w[2 * j];
        float v1 = xr[2 * j + 1] * inv * w[2 * j + 1];
        uint2 pk = pack_pair(v0, v1);
        if (MERGER)
            y[((long)((row & 3) * HID2 + j)) * MTOK + (row >> 2)] = pk;
        else
            y[(long)j * S_LEN + row] = pk;
    }
}

// Split qkv [S, 3*HID] -> q,k,v [H,S,D] with RoPE on q,k
__global__ void rope_split_k(const float* __restrict__ qkv,
                             const float* __restrict__ cs,
                             const float* __restrict__ sn,
                             float* __restrict__ gq, float* __restrict__ gk,
                             float* __restrict__ gv) {
    int idx = blockIdx.x * blockDim.x + threadIdx.x;
    if (idx >= S_LEN * HID) return;
    int d = idx % HD;
    int h = (idx / HD) % NH;
    int s = idx / HID;
    const float* base = qkv + (long)s * (3 * HID);
    float c = cs[s * HD + d];
    float si = sn[s * HD + d];
    int f = h * HD + d;
    float qv = base[f];
    float kv = base[HID + f];
    float vv = base[2 * HID + f];
    int dr = (d < HD / 2) ? (d + HD / 2) : (d - HD / 2);
    float sgn = (d < HD / 2) ? -1.f : 1.f;
    float qr = sgn * base[h * HD + dr];
    float kr = sgn * base[HID + h * HD + dr];
    long o = ((long)h * S_LEN + s) * HD + d;
    gq[o] = qv * c + qr * si;
    gk[o] = kv * c + kr * si;
    gv[o] = vv;
}

// ---------------- flash attention (full or 64-window), k-major packed output ----------------
__global__ void __launch_bounds__(256) attn_k(const float* __restrict__ Q,
                                              const float* __restrict__ K,
                                              const float* __restrict__ V,
                                              const float* __restrict__ mask,
                                              int windowed,
                                              uint2* __restrict__ Opk) {
    __shared__ float Ks[64][HD];
    __shared__ float Vs[64][HD];
    int h = blockIdx.y;
    int q0 = blockIdx.x * 64;
    int tid = threadIdx.x;
    int qi = tid >> 2;
    int part = tid & 3;
    int d0 = part * 20;
    int q = q0 + qi;

    const float* Qb = Q + ((long)h * S_LEN + q) * HD;
    float qr[20];
#pragma unroll
    for (int i = 0; i < 20; ++i) qr[i] = Qb[d0 + i];

    float m = -3.0e38f, l = 0.f;
    float oacc[20];
#pragma unroll
    for (int i = 0; i < 20; ++i) oacc[i] = 0.f;

    int kvs = windowed ? q0 : 0;
    int kve = windowed ? q0 + 64 : S_LEN;
    const float scale = 0.11180339887498949f; // 1/sqrt(80)
    const float NEG = -3.0e38f;

    for (int kv0 = kvs; kv0 < kve; kv0 += 64) {
        __syncthreads();
        const float* Kb = K + ((long)h * S_LEN + kv0) * HD;
        const float* Vb = V + ((long)h * S_LEN + kv0) * HD;
        for (int i = tid; i < 64 * HD; i += 256) {
            Ks[i / HD][i % HD] = Kb[i];
            Vs[i / HD][i % HD] = Vb[i];
        }
        __syncthreads();
#pragma unroll 1
        for (int jc = 0; jc < 4; ++jc) {
            float sc[16];
#pragma unroll
            for (int jj = 0; jj < 16; ++jj) {
                int j = jc * 16 + jj;
                float a = 0.f;
#pragma unroll
                for (int dd = 0; dd < 20; ++dd) a += qr[dd] * Ks[j][d0 + dd];
                a += __shfl_xor_sync(0xffffffffu, a, 1);
                a += __shfl_xor_sync(0xffffffffu, a, 2);
                float mv;
                if (windowed)
                    mv = mask[(((long)(q0 >> 6) * 64 + qi) * 64) + j];
                else
                    mv = mask[(long)q * S_LEN + (kv0 + j)];
                sc[jj] = a * scale + (1.f - mv) * NEG;
            }
            float tmax = sc[0];
#pragma unroll
            for (int jj = 1; jj < 16; ++jj) tmax = fmaxf(tmax, sc[jj]);
            float mn = fmaxf(m, tmax);
            float corr = expf(m - mn);
#pragma unroll
            for (int dd = 0; dd < 20; ++dd) oacc[dd] *= corr;
            float ls = 0.f;
#pragma unroll
            for (int jj = 0; jj < 16; ++jj) {
                int j = jc * 16 + jj;
                float p = expf(sc[jj] - mn);
                ls += p;
#pragma unroll
                for (int dd = 0; dd < 20; ++dd) oacc[dd] += p * Vs[j][d0 + dd];
            }
            l = l * corr + ls;
            m = mn;
        }
    }
    float invl = 1.f / l;
    // k-major: pair = h*40 + part*10 + p, row = q
#pragma unroll
    for (int p = 0; p < 10; ++p)
        Opk[((long)(h * (HD / 2) + part * 10 + p)) * S_LEN + q] =
            pack_pair(oacc[2 * p] * invl, oacc[2 * p + 1] * invl);
}

// ---------------- bf16x3 tensor-core GEMM, cp.async double-buffered ----------------
// C[M,N] = epi(A @ B + bias)   A: K-MAJOR [K2][M] uint2, B: [K2][N] uint2
// EPI: 0 none, 1 SiLU, 2 GELU, 3 += res, 4 *= res.  PACK: k-major packed output.
// Block 128x128, BK=32 (KP=16 pairs), 256 thr (8 warps 2x4), warp tile 64x32.
#define GBM 128
#define GBN 128
#define KP 16
#define SSTRU 132
#define TILEU (KP * SSTRU)
#define STAGEU (2 * TILEU)
#define GEMM_SMEM_BYTES (2 * STAGEU * (int)sizeof(uint2))   // 67584

__device__ __forceinline__ void cp16(uint32_t dst, const void* src, int sz) {
    asm volatile("cp.async.cg.shared.global [%0], [%1], 16, %2;"
                 :: "r"(dst), "l"(src), "r"(sz));
}
__device__ __forceinline__ void cp_commit() { asm volatile("cp.async.commit_group;" ::: "memory"); }
__device__ __forceinline__ void cp_wait1()  { asm volatile("cp.async.wait_group 1;" ::: "memory"); }

__device__ __forceinline__ void mma_bf16(float c[4], uint32_t a0, uint32_t a1,
                                         uint32_t a2, uint32_t a3,
                                         uint32_t b0, uint32_t b1) {
    asm volatile(
        "mma.sync.aligned.m16n8k16.row.col.f32.bf16.bf16.f32 "
        "{%0,%1,%2,%3}, {%4,%5,%6,%7}, {%8,%9}, {%0,%1,%2,%3};"
        : "+f"(c[0]), "+f"(c[1]), "+f"(c[2]), "+f"(c[3])
        : "r"(a0), "r"(a1), "r"(a2), "r"(a3), "r"(b0), "r"(b1));
}

template <int EPI, bool PACK>
__global__ void __launch_bounds__(256, 2) mmagemm_k(const uint2* __restrict__ A,
                                                    const uint2* __restrict__ B,
                                                    const float* __restrict__ bias,
                                                    const float* __restrict__ res,
                                                    void* __restrict__ Cout,
                                                    int M, int N, int K2) {
    extern __shared__ uint2 smp[];
    uint32_t smem_base = (uint32_t)__cvta_generic_to_shared(smp);

    int tid = threadIdx.x;
    int lane = tid & 31;
    int warp = tid >> 5;
    int warpM = warp & 1;
    int warpN = warp >> 1;
    int g = lane >> 2;
    int tg = lane & 3;

    int bmBase = blockIdx.y * GBM;
    int bnBase = blockIdx.x * GBN;

    float acc[4][4][4];
#pragma unroll
    for (int mi = 0; mi < 4; ++mi)
#pragma unroll
        for (int ni = 0; ni < 4; ++ni)
#pragma unroll
            for (int r = 0; r < 4; ++r) acc[mi][ni][r] = 0.f;

    // staging: thread -> pair-row spr = tid>>4 (0..15), col-u4 base scu = tid&15
    int spr = tid >> 4;
    int scu = tid & 15;
    const uint2* Abase = A + bmBase;
    const uint2* Bbase = B + bnBase;

    int ntile = (K2 + KP - 1) / KP;

    auto stage = [&](int t, int s) {
        int p = t * KP + spr;
        const uint2* Ar = Abase + (long)p * M;
        const uint2* Br = Bbase + (long)p * N;
        uint32_t aoff = smem_base + (uint32_t)((s * STAGEU + spr * SSTRU) * 8);
        uint32_t boff = aoff + TILEU * 8;
        int kok = (p < K2) ? 16 : 0;
#pragma unroll
        for (int c = 0; c < 4; ++c) {
            int cu = scu + 16 * c;          // colu4: 2 uint2 per cp16
            cp16(aoff + cu * 16, Ar + 2 * cu, kok);   // M multiple of 128 -> col in-bounds
            int n0 = bnBase + 2 * cu;
            int sz = (kok == 0) ? 0 : ((n0 + 1 < N) ? 16 : ((n0 < N) ? 8 : 0));
            cp16(boff + cu * 16, Br + 2 * cu, sz);
        }
    };

    stage(0, 0);
    cp_commit();
    if (ntile > 1) stage(1, 1);
    cp_commit();

    for (int t = 0; t < ntile; ++t) {
        cp_wait1();
        __syncthreads();
        int s = t & 1;
        const uint2 (*As)[SSTRU] = (const uint2(*)[SSTRU])(smp + s * STAGEU);
        const uint2 (*Bs)[SSTRU] = (const uint2(*)[SSTRU])(smp + s * STAGEU + TILEU);

#pragma unroll
        for (int ck = 0; ck < 2; ++ck) {
            int c8 = ck * 8;
            uint2 b0[4], b1[4];
#pragma unroll
            for (int ni = 0; ni < 4; ++ni) {
                int n = warpN * 32 + ni * 8 + g;
                b0[ni] = Bs[c8 + tg][n];
                b1[ni] = Bs[c8 + tg + 4][n];
            }
#pragma unroll
            for (int mi = 0; mi < 4; ++mi) {
                int m = warpM * 64 + mi * 16 + g;
                uint2 a0 = As[c8 + tg][m];
                uint2 a1 = As[c8 + tg][m + 8];
                uint2 a2 = As[c8 + tg + 4][m];
                uint2 a3 = As[c8 + tg + 4][m + 8];
#pragma unroll
                for (int ni = 0; ni < 4; ++ni)
                    mma_bf16(acc[mi][ni], a0.x, a1.x, a2.x, a3.x, b0[ni].x, b1[ni].x);
#pragma unroll
                for (int ni = 0; ni < 4; ++ni)
                    mma_bf16(acc[mi][ni], a0.x, a1.x, a2.x, a3.x, b0[ni].y, b1[ni].y);
#pragma unroll
                for (int ni = 0; ni < 4; ++ni)
                    mma_bf16(acc[mi][ni], a0.y, a1.y, a2.y, a3.y, b0[ni].x, b1[ni].x);
            }
        }
        __syncthreads();
        if (t + 2 < ntile) stage(t + 2, s);
        cp_commit();
    }

    // ---- epilogue ----  c0=(g,2tg) c1=(g,2tg+1) c2=(g+8,2tg) c3=(g+8,2tg+1)
    float* Cf = (float*)Cout;
    uint2* Cp = (uint2*)Cout;
#pragma unroll
    for (int mi = 0; mi < 4; ++mi) {
        int row0 = bmBase + warpM * 64 + mi * 16 + g;
#pragma unroll
        for (int ni = 0; ni < 4; ++ni) {
            int col = bnBase + warpN * 32 + ni * 8 + 2 * tg;
            if (col >= N) continue;
            float b0 = bias[col], b1 = bias[col + 1];
#pragma unroll
            for (int rh = 0; rh < 2; ++rh) {
                int row = row0 + rh * 8;
                float v0 = acc[mi][ni][rh * 2 + 0] + b0;
                float v1 = acc[mi][ni][rh * 2 + 1] + b1;
                if (EPI == 1) {
                    v0 = v0 / (1.f + expf(-v0));
                    v1 = v1 / (1.f + expf(-v1));
                } else if (EPI == 2) {
                    v0 = 0.5f * v0 * (1.f + erff(v0 * 0.70710678118654752f));
                    v1 = 0.5f * v1 * (1.f + erff(v1 * 0.70710678118654752f));
                } else if (EPI == 3) {
                    v0 += res[(long)row * N + col];
                    v1 += res[(long)row * N + col + 1];
                } else if (EPI == 4) {
                    v0 *= res[(long)row * N + col];
                    v1 *= res[(long)row * N + col + 1];
                }
                if (PACK) {
                    Cp[(long)(col >> 1) * M + row] = pack_pair(v0, v1);
                } else {
                    Cf[(long)row * N + col] = v0;
                    Cf[(long)row * N + col + 1] = v1;
                }
            }
        }
    }
}

// ---------------- host ----------------
static inline dim3 gemm_grid(int M, int N) { return dim3((N + GBN - 1) / GBN, M / GBM); }

template <int EPI, bool PACK>
static void launch_gemm(const uint2* A, const uint2* B, const float* bias,
                        const float* res, void* C, int M, int N, int K2) {
    cudaFuncSetAttribute(mmagemm_k<EPI, PACK>,
                         cudaFuncAttributeMaxDynamicSharedMemorySize, GEMM_SMEM_BYTES);
    mmagemm_k<EPI, PACK><<<gemm_grid(M, N), 256, GEMM_SMEM_BYTES>>>(
        A, B, bias, res, C, M, N, K2);
}

static inline void conv_w(const float* W, uint2* out, int K2, int N) {
    long n = (long)K2 * N;
    convert_w_k<<<(unsigned)((n + 255) / 256), 256>>>(W, out, K2, N);
}

extern "C" void kernel_launch(void* const* d_in, const int* in_sizes, int n_in,
                              void* d_out, int out_size) {
    const float* in_hs   = (const float*)d_in[0];
    const float* fmask   = (const float*)d_in[1];
    const float* wmask   = (const float*)d_in[2];
    const float* cosd    = (const float*)d_in[3];
    const float* sind    = (const float*)d_in[4];
    const float* norm1_w = (const float*)d_in[5];
    const float* norm2_w = (const float*)d_in[6];
    const float* qkv_w   = (const float*)d_in[7];
    const float* qkv_b   = (const float*)d_in[8];
    const float* proj_w  = (const float*)d_in[9];
    const float* proj_b  = (const float*)d_in[10];
    const float* gate_w  = (const float*)d_in[11];
    const float* gate_b  = (const float*)d_in[12];
    const float* up_w    = (const float*)d_in[13];
    const float* up_b    = (const float*)d_in[14];
    const float* down_w  = (const float*)d_in[15];
    const float* down_b  = (const float*)d_in[16];
    const float* ln_q_w  = (const float*)d_in[17];
    const float* fc1_w   = (const float*)d_in[18];
    const float* fc1_b   = (const float*)d_in[19];
    const float* fc2_w   = (const float*)d_in[20];
    const float* fc2_b   = (const float*)d_in[21];
    float* out = (float*)d_out;

    float *hs, *qkv, *q, *k, *v, *gate;
    uint2 *w1, *w2, *w3, *w4, *w5, *xpk, *attpk, *gatepk;
    cudaGetSymbolAddress((void**)&hs, g_hs);
    cudaGetSymbolAddress((void**)&qkv, g_qkv);
    cudaGetSymbolAddress((void**)&q, g_q);
    cudaGetSymbolAddress((void**)&k, g_k);
    cudaGetSymbolAddress((void**)&v, g_v);
    cudaGetSymbolAddress((void**)&gate, g_gate);
    cudaGetSymbolAddress((void**)&w1, g_w1);
    cudaGetSymbolAddress((void**)&w2, g_w2);
    cudaGetSymbolAddress((void**)&w3, g_w3);
    cudaGetSymbolAddress((void**)&w4, g_w4);
    cudaGetSymbolAddress((void**)&w5, g_w5);
    cudaGetSymbolAddress((void**)&xpk, g_xpk);
    cudaGetSymbolAddress((void**)&attpk, g_attpk);
    cudaGetSymbolAddress((void**)&gatepk, g_gatepk);

    const int nhid = S_LEN * HID;
    copy_k<<<(nhid + 255) / 256, 256>>>(in_hs, hs, nhid);   // launch 1

    for (int i = 0; i < NLAYER; ++i) {
        int full = (i == 3 || i == 7) ? 1 : 0;
        conv_w(qkv_w + (long)i * HID * 3 * HID, w1, HID2, 3 * HID);   // 2
        conv_w(proj_w + (long)i * HID * HID, w2, HID2, HID);          // 3
        conv_w(gate_w + (long)i * HID * INTER, w3, HID2, INTER);     // 4
        rmsnorm_pack_k<false><<<S_LEN, 256>>>(hs, norm1_w + (long)i * HID, xpk);  // 5
        // launch 6 (ncu -s 5 -c 1 captures this): qkv GEMM
        launch_gemm<0, false>(xpk, w1, qkv_b + (long)i * 3 * HID, nullptr,
                              qkv, S_LEN, 3 * HID, HID2);
        conv_w(up_w + (long)i * HID * INTER, w4, HID2, INTER);
        conv_w(down_w + (long)i * INTER * HID, w5, INTER2, HID);
        rope_split_k<<<(nhid + 255) / 256, 256>>>(qkv, cosd, sind, q, k, v);
        attn_k<<<dim3(S_LEN / 64, NH), 256>>>(q, k, v, full ? fmask : wmask,
                                              full ? 0 : 1, attpk);
        launch_gemm<3, false>(attpk, w2, proj_b + (long)i * HID, hs,
                              hs, S_LEN, HID, HID2);
        rmsnorm_pack_k<false><<<S_LEN, 256>>>(hs, norm2_w + (long)i * HID, xpk);
        launch_gemm<1, false>(xpk, w3, gate_b + (long)i * INTER, nullptr,
                              gate, S_LEN, INTER, HID2);
        launch_gemm<4, true>(xpk, w4, up_b + (long)i * INTER, gate,
                             gatepk, S_LEN, INTER, HID2);
        launch_gemm<3, false>(gatepk, w5, down_b + (long)i * HID, hs,
                              hs, S_LEN, HID, INTER2);
    }

    // patch merger
    conv_w(fc1_w, w1, MERGED / 2, MERGED);
    conv_w(fc2_w, w2, MERGED / 2, OUTDIM);
    rmsnorm_pack_k<true><<<S_LEN, 256>>>(hs, ln_q_w, xpk);   // merger view [512 x 5120]
    launch_gemm<2, true>(xpk, w1, fc1_b, nullptr, attpk, MTOK, MERGED, MERGED / 2);
    launch_gemm<0, false>(attpk, w2, fc2_b, nullptr, out, MTOK, OUTDIM, MERGED / 2);
}

// round 9
// speedup vs baseline: 1.6689x; 1.0650x over previous
#include <cuda_runtime.h>
#include <cuda_bf16.h>
#include <math.h>
#include <stdint.h>

#define S_LEN 2048
#define HID 1280
#define NH 16
#define HD 80
#define INTER 3420
#define NLAYER 8
#define WIN 64
#define MERGED 5120      // 4*HID
#define OUTDIM 3584
#define MTOK 512         // 2048/4
#define HID2 (HID / 2)       // 640 pairs
#define INTER2 (INTER / 2)   // 1710 pairs

// ---------------- scratch (device globals; no allocation allowed) ----------------
__device__ float g_hs  [S_LEN * HID];
__device__ float g_qkv [S_LEN * 3 * HID];
__device__ float g_q   [NH * S_LEN * HD];
__device__ float g_k   [NH * S_LEN * HD];
__device__ float g_v   [NH * S_LEN * HD];
__device__ float g_gate[S_LEN * INTER];
// packed bf16x3 operands (uint2 = {big bf16x2, small bf16x2} covering 2 k-values)
// weights: [K2 pairs][N] per layer, all layers contiguous; activations: K-MAJOR [K2][M]
__device__ uint2 g_wqkv [NLAYER * HID2 * 3 * HID];
__device__ uint2 g_wproj[NLAYER * HID2 * HID];
__device__ uint2 g_wgate[NLAYER * HID2 * INTER];
__device__ uint2 g_wup  [NLAYER * HID2 * INTER];
__device__ uint2 g_wdown[NLAYER * INTER2 * HID];
__device__ uint2 g_wfc1 [2560 * MERGED];
__device__ uint2 g_wfc2 [2560 * OUTDIM];
__device__ uint2 g_xpk  [2560 * 2048];
__device__ uint2 g_attpk[2560 * 2048];
__device__ uint2 g_gatepk[INTER2 * S_LEN];

// ---------------- packing helpers ----------------
__device__ __forceinline__ void split_bf16(float x, uint16_t& b, uint16_t& s) {
    __nv_bfloat16 hb = __float2bfloat16(x);
    float r = x - __bfloat162float(hb);
    __nv_bfloat16 hs = __float2bfloat16(r);
    b = *(uint16_t*)&hb;
    s = *(uint16_t*)&hs;
}

__device__ __forceinline__ uint2 pack_pair(float lo, float hi) {
    uint16_t bl, sl, bh, sh;
    split_bf16(lo, bl, sl);
    split_bf16(hi, bh, sh);
    return make_uint2((uint32_t)bl | ((uint32_t)bh << 16),
                      (uint32_t)sl | ((uint32_t)sh << 16));
}

// ---------------- elementwise kernels ----------------
__global__ void copy_k(const float* __restrict__ src, float* __restrict__ dst, int n) {
    int i = blockIdx.x * blockDim.x + threadIdx.x;
    if (i < n) dst[i] = src[i];
}

// convert weights [K][N] fp32 -> [K/2][N] packed uint2 (pairs along K).
// Works across stacked layers since per-layer K is even.
__global__ void convert_w_k(const float* __restrict__ W, uint2* __restrict__ out,
                            long total, int N) {
    long idx = (long)blockIdx.x * blockDim.x + threadIdx.x;
    if (idx >= total) return;
    long p = idx / N;
    int c = (int)(idx - p * N);
    out[idx] = pack_pair(W[(2 * p) * N + c], W[(2 * p + 1) * N + c]);
}

// RMSNorm + pack, K-MAJOR output.
// MERGER=false: y[j * 2048 + row]
// MERGER=true : merger view [512 x 5120]: y[((row&3)*640 + j) * 512 + (row>>2)]
template <bool MERGER>
__global__ void __launch_bounds__(256) rmsnorm_pack_k(const float* __restrict__ x,
                                                      const float* __restrict__ w,
                                                      uint2* __restrict__ y) {
    int row = blockIdx.x;
    const float* xr = x + (long)row * HID;
    float ss = 0.f;
    for (int i = threadIdx.x; i < HID; i += 256) { float v = xr[i]; ss += v * v; }
    __shared__ float red[8];
    for (int o = 16; o > 0; o >>= 1) ss += __shfl_xor_sync(0xffffffffu, ss, o);
    if ((threadIdx.x & 31) == 0) red[threadIdx.x >> 5] = ss;
    __syncthreads();
    if (threadIdx.x < 32) {
        float v = (threadIdx.x < 8) ? red[threadIdx.x] : 0.f;
        for (int o = 4; o > 0; o >>= 1) v += __shfl_xor_sync(0xffffffffu, v, o);
        if (threadIdx.x == 0) red[0] = v;
    }
    __syncthreads();
    float inv = rsqrtf(red[0] / (float)HID + 1e-6f);
    for (int j = threadIdx.x; j < HID2; j += 256) {
        float v0 = xr[2 * j] * inv * w[2 * j];
        float v1 = xr[2 * j + 1] * inv * w[2 * j + 1];
        uint2 pk = pack_pair(v0, v1);
        if (MERGER)
            y[((long)((row & 3) * HID2 + j)) * MTOK + (row >> 2)] = pk;
        else
            y[(long)j * S_LEN + row] = pk;
    }
}

// Split qkv [S, 3*HID] -> q,k,v [H,S,D] with RoPE on q,k
__global__ void rope_split_k(const float* __restrict__ qkv,
                             const float* __restrict__ cs,
                             const float* __restrict__ sn,
                             float* __restrict__ gq, float* __restrict__ gk,
                             float* __restrict__ gv) {
    int idx = blockIdx.x * blockDim.x + threadIdx.x;
    if (idx >= S_LEN * HID) return;
    int d = idx % HD;
    int h = (idx / HD) % NH;
    int s = idx / HID;
    const float* base = qkv + (long)s * (3 * HID);
    float c = cs[s * HD + d];
    float si = sn[s * HD + d];
    int f = h * HD + d;
    float qv = base[f];
    float kv = base[HID + f];
    float vv = base[2 * HID + f];
    int dr = (d < HD / 2) ? (d + HD / 2) : (d - HD / 2);
    float sgn = (d < HD / 2) ? -1.f : 1.f;
    float qr = sgn * base[h * HD + dr];
    float kr = sgn * base[HID + h * HD + dr];
    long o = ((long)h * S_LEN + s) * HD + d;
    gq[o] = qv * c + qr * si;
    gk[o] = kv * c + kr * si;
    gv[o] = vv;
}

// ---------------- flash attention (full or 64-window), k-major packed output ----------------
__global__ void __launch_bounds__(256) attn_k(const float* __restrict__ Q,
                                              const float* __restrict__ K,
                                              const float* __restrict__ V,
                                              const float* __restrict__ mask,
                                              int windowed,
                                              uint2* __restrict__ Opk) {
    __shared__ float Ks[64][HD];
    __shared__ float Vs[64][HD];
    int h = blockIdx.y;
    int q0 = blockIdx.x * 64;
    int tid = threadIdx.x;
    int qi = tid >> 2;
    int part = tid & 3;
    int d0 = part * 20;
    int q = q0 + qi;

    const float* Qb = Q + ((long)h * S_LEN + q) * HD;
    float qr[20];
#pragma unroll
    for (int i = 0; i < 20; ++i) qr[i] = Qb[d0 + i];

    float m = -3.0e38f, l = 0.f;
    float oacc[20];
#pragma unroll
    for (int i = 0; i < 20; ++i) oacc[i] = 0.f;

    int kvs = windowed ? q0 : 0;
    int kve = windowed ? q0 + 64 : S_LEN;
    const float scale = 0.11180339887498949f; // 1/sqrt(80)
    const float NEG = -3.0e38f;

    for (int kv0 = kvs; kv0 < kve; kv0 += 64) {
        __syncthreads();
        const float* Kb = K + ((long)h * S_LEN + kv0) * HD;
        const float* Vb = V + ((long)h * S_LEN + kv0) * HD;
        for (int i = tid; i < 64 * HD; i += 256) {
            Ks[i / HD][i % HD] = Kb[i];
            Vs[i / HD][i % HD] = Vb[i];
        }
        __syncthreads();
#pragma unroll 1
        for (int jc = 0; jc < 4; ++jc) {
            float sc[16];
#pragma unroll
            for (int jj = 0; jj < 16; ++jj) {
                int j = jc * 16 + jj;
                float a = 0.f;
#pragma unroll
                for (int dd = 0; dd < 20; ++dd) a += qr[dd] * Ks[j][d0 + dd];
                a += __shfl_xor_sync(0xffffffffu, a, 1);
                a += __shfl_xor_sync(0xffffffffu, a, 2);
                float mv;
                if (windowed)
                    mv = mask[(((long)(q0 >> 6) * 64 + qi) * 64) + j];
                else
                    mv = mask[(long)q * S_LEN + (kv0 + j)];
                sc[jj] = a * scale + (1.f - mv) * NEG;
            }
            float tmax = sc[0];
#pragma unroll
            for (int jj = 1; jj < 16; ++jj) tmax = fmaxf(tmax, sc[jj]);
            float mn = fmaxf(m, tmax);
            float corr = expf(m - mn);
#pragma unroll
            for (int dd = 0; dd < 20; ++dd) oacc[dd] *= corr;
            float ls = 0.f;
#pragma unroll
            for (int jj = 0; jj < 16; ++jj) {
                int j = jc * 16 + jj;
                float p = expf(sc[jj] - mn);
                ls += p;
#pragma unroll
                for (int dd = 0; dd < 20; ++dd) oacc[dd] += p * Vs[j][d0 + dd];
            }
            l = l * corr + ls;
            m = mn;
        }
    }
    float invl = 1.f / l;
#pragma unroll
    for (int p = 0; p < 10; ++p)
        Opk[((long)(h * (HD / 2) + part * 10 + p)) * S_LEN + q] =
            pack_pair(oacc[2 * p] * invl, oacc[2 * p + 1] * invl);
}

// ---------------- bf16x3 tensor-core GEMM, cp.async double-buffered ----------------
// C[M,N] = epi(A @ B + bias)   A: K-MAJOR [K2][M] uint2, B: [K2][N] uint2
// EPI: 0 none, 1 SiLU, 2 GELU, 3 += res, 4 *= res.  PACK: k-major packed output.
// BM in {128,64}: block BMx128, BK=32 (KP=16 pairs), 256 thr (8 warps 2x4).
#define GBN 128
#define KP 16

__device__ __forceinline__ void cp16(uint32_t dst, const void* src, int sz) {
    asm volatile("cp.async.cg.shared.global [%0], [%1], 16, %2;"
                 :: "r"(dst), "l"(src), "r"(sz));
}
__device__ __forceinline__ void cp_commit() { asm volatile("cp.async.commit_group;" ::: "memory"); }
__device__ __forceinline__ void cp_wait1()  { asm volatile("cp.async.wait_group 1;" ::: "memory"); }

__device__ __forceinline__ void mma_bf16(float c[4], uint32_t a0, uint32_t a1,
                                         uint32_t a2, uint32_t a3,
                                         uint32_t b0, uint32_t b1) {
    asm volatile(
        "mma.sync.aligned.m16n8k16.row.col.f32.bf16.bf16.f32 "
        "{%0,%1,%2,%3}, {%4,%5,%6,%7}, {%8,%9}, {%0,%1,%2,%3};"
        : "+f"(c[0]), "+f"(c[1]), "+f"(c[2]), "+f"(c[3])
        : "r"(a0), "r"(a1), "r"(a2), "r"(a3), "r"(b0), "r"(b1));
}

template <int EPI, bool PACK, int BM>
__global__ void __launch_bounds__(256, 2) mmagemm_k(const uint2* __restrict__ A,
                                                    const uint2* __restrict__ B,
                                                    const float* __restrict__ bias,
                                                    const float* __restrict__ res,
                                                    void* __restrict__ Cout,
                                                    int M, int N, int K2) {
    // A stride: banks (8tg+2g) distinct per half-warp need stride*2 ≡ 8 mod 32
    constexpr int ASTRU = (BM == 128) ? 132 : 68;
    constexpr int BSTRU = 132;
    constexpr int ATILE = KP * ASTRU;
    constexpr int BTILE = KP * BSTRU;
    constexpr int STAGE = ATILE + BTILE;
    constexpr int MI = BM / 32;   // m16 tiles per warp (warp tile BM/2 x 32)

    extern __shared__ uint2 smp[];
    uint32_t smem_base = (uint32_t)__cvta_generic_to_shared(smp);

    int tid = threadIdx.x;
    int lane = tid & 31;
    int warp = tid >> 5;
    int warpM = warp & 1;
    int warpN = warp >> 1;
    int g = lane >> 2;
    int tg = lane & 3;

    int bmBase = blockIdx.y * BM;
    int bnBase = blockIdx.x * GBN;

    float acc[MI][4][4];
#pragma unroll
    for (int mi = 0; mi < MI; ++mi)
#pragma unroll
        for (int ni = 0; ni < 4; ++ni)
#pragma unroll
            for (int r = 0; r < 4; ++r) acc[mi][ni][r] = 0.f;

    int spr = tid >> 4;      // pair-row 0..15
    int scu = tid & 15;      // 16B-column unit
    const uint2* Abase = A + bmBase;
    const uint2* Bbase = B + bnBase;

    int ntile = (K2 + KP - 1) / KP;

    auto stage_fn = [&](int t, int s) {
        int p = t * KP + spr;
        const uint2* Ar = Abase + (long)p * M;
        const uint2* Br = Bbase + (long)p * N;
        uint32_t aoff = smem_base + (uint32_t)((s * STAGE + spr * ASTRU) * 8);
        uint32_t boff = smem_base + (uint32_t)((s * STAGE + ATILE + spr * BSTRU) * 8);
        int kok = (p < K2) ? 16 : 0;
#pragma unroll
        for (int c = 0; c < BM / 32; ++c) {
            int cu = scu + 16 * c;
            cp16(aoff + cu * 16, Ar + 2 * cu, kok);   // M multiple of BM -> in-bounds
        }
#pragma unroll
        for (int c = 0; c < 4; ++c) {
            int cu = scu + 16 * c;
            int n0 = bnBase + 2 * cu;
            int sz = (kok == 0) ? 0 : ((n0 + 1 < N) ? 16 : ((n0 < N) ? 8 : 0));
            cp16(boff + cu * 16, Br + 2 * cu, sz);
        }
    };

    stage_fn(0, 0);
    cp_commit();
    if (ntile > 1) stage_fn(1, 1);
    cp_commit();

    for (int t = 0; t < ntile; ++t) {
        cp_wait1();
        __syncthreads();
        int s = t & 1;
        const uint2 (*As)[ASTRU] = (const uint2(*)[ASTRU])(smp + s * STAGE);
        const uint2 (*Bs)[BSTRU] = (const uint2(*)[BSTRU])(smp + s * STAGE + ATILE);

#pragma unroll
        for (int ck = 0; ck < 2; ++ck) {
            int c8 = ck * 8;
            uint2 b0[4], b1[4];
#pragma unroll
            for (int ni = 0; ni < 4; ++ni) {
                int n = warpN * 32 + ni * 8 + g;
                b0[ni] = Bs[c8 + tg][n];
                b1[ni] = Bs[c8 + tg + 4][n];
            }
#pragma unroll
            for (int mi = 0; mi < MI; ++mi) {
                int m = warpM * (BM / 2) + mi * 16 + g;
                uint2 a0 = As[c8 + tg][m];
                uint2 a1 = As[c8 + tg][m + 8];
                uint2 a2 = As[c8 + tg + 4][m];
                uint2 a3 = As[c8 + tg + 4][m + 8];
#pragma unroll
                for (int ni = 0; ni < 4; ++ni)
                    mma_bf16(acc[mi][ni], a0.x, a1.x, a2.x, a3.x, b0[ni].x, b1[ni].x);
#pragma unroll
                for (int ni = 0; ni < 4; ++ni)
                    mma_bf16(acc[mi][ni], a0.x, a1.x, a2.x, a3.x, b0[ni].y, b1[ni].y);
#pragma unroll
                for (int ni = 0; ni < 4; ++ni)
                    mma_bf16(acc[mi][ni], a0.y, a1.y, a2.y, a3.y, b0[ni].x, b1[ni].x);
            }
        }
        __syncthreads();
        if (t + 2 < ntile) stage_fn(t + 2, s);
        cp_commit();
    }

    // ---- epilogue ----  c0=(g,2tg) c1=(g,2tg+1) c2=(g+8,2tg) c3=(g+8,2tg+1)
    float* Cf = (float*)Cout;
    uint2* Cp = (uint2*)Cout;
#pragma unroll
    for (int mi = 0; mi < MI; ++mi) {
        int row0 = bmBase + warpM * (BM / 2) + mi * 16 + g;
#pragma unroll
        for (int ni = 0; ni < 4; ++ni) {
            int col = bnBase + warpN * 32 + ni * 8 + 2 * tg;
            if (col >= N) continue;
            float b0 = bias[col], b1 = bias[col + 1];
#pragma unroll
            for (int rh = 0; rh < 2; ++rh) {
                int row = row0 + rh * 8;
                float v0 = acc[mi][ni][rh * 2 + 0] + b0;
                float v1 = acc[mi][ni][rh * 2 + 1] + b1;
                if (EPI == 1) {
                    v0 = v0 / (1.f + expf(-v0));
                    v1 = v1 / (1.f + expf(-v1));
                } else if (EPI == 2) {
                    v0 = 0.5f * v0 * (1.f + erff(v0 * 0.70710678118654752f));
                    v1 = 0.5f * v1 * (1.f + erff(v1 * 0.70710678118654752f));
                } else if (EPI == 3) {
                    v0 += res[(long)row * N + col];
                    v1 += res[(long)row * N + col + 1];
                } else if (EPI == 4) {
                    v0 *= res[(long)row * N + col];
                    v1 *= res[(long)row * N + col + 1];
                }
                if (PACK) {
                    Cp[(long)(col >> 1) * M + row] = pack_pair(v0, v1);
                } else {
                    Cf[(long)row * N + col] = v0;
                    Cf[(long)row * N + col + 1] = v1;
                }
            }
        }
    }
}

// ---------------- host ----------------
template <int EPI, bool PACK>
static void launch_gemm(const uint2* A, const uint2* B, const float* bias,
                        const float* res, void* C, int M, int N, int K2) {
    int gx = (N + GBN - 1) / GBN;
    int blocks128 = gx * (M / 128);
    if (blocks128 < 296 && (M % 64) == 0) {
        constexpr int SM64 = 2 * (KP * 68 + KP * 132) * (int)sizeof(uint2);
        cudaFuncSetAttribute(mmagemm_k<EPI, PACK, 64>,
                             cudaFuncAttributeMaxDynamicSharedMemorySize, SM64);
        mmagemm_k<EPI, PACK, 64><<<dim3(gx, M / 64), 256, SM64>>>(
            A, B, bias, res, C, M, N, K2);
    } else {
        constexpr int SM128 = 2 * (KP * 132 + KP * 132) * (int)sizeof(uint2);
        cudaFuncSetAttribute(mmagemm_k<EPI, PACK, 128>,
                             cudaFuncAttributeMaxDynamicSharedMemorySize, SM128);
        mmagemm_k<EPI, PACK, 128><<<dim3(gx, M / 128), 256, SM128>>>(
            A, B, bias, res, C, M, N, K2);
    }
}

static inline void conv_w(const float* W, uint2* out, long K2total, int N) {
    long n = K2total * N;
    convert_w_k<<<(unsigned)((n + 255) / 256), 256>>>(W, out, n, N);
}

extern "C" void kernel_launch(void* const* d_in, const int* in_sizes, int n_in,
                              void* d_out, int out_size) {
    const float* in_hs   = (const float*)d_in[0];
    const float* fmask   = (const float*)d_in[1];
    const float* wmask   = (const float*)d_in[2];
    const float* cosd    = (const float*)d_in[3];
    const float* sind    = (const float*)d_in[4];
    const float* norm1_w = (const float*)d_in[5];
    const float* norm2_w = (const float*)d_in[6];
    const float* qkv_w   = (const float*)d_in[7];
    const float* qkv_b   = (const float*)d_in[8];
    const float* proj_w  = (const float*)d_in[9];
    const float* proj_b  = (const float*)d_in[10];
    const float* gate_w  = (const float*)d_in[11];
    const float* gate_b  = (const float*)d_in[12];
    const float* up_w    = (const float*)d_in[13];
    const float* up_b    = (const float*)d_in[14];
    const float* down_w  = (const float*)d_in[15];
    const float* down_b  = (const float*)d_in[16];
    const float* ln_q_w  = (const float*)d_in[17];
    const float* fc1_w   = (const float*)d_in[18];
    const float* fc1_b   = (const float*)d_in[19];
    const float* fc2_w   = (const float*)d_in[20];
    const float* fc2_b   = (const float*)d_in[21];
    float* out = (float*)d_out;

    float *hs, *qkv, *q, *k, *v, *gate;
    uint2 *wqkv, *wproj, *wgate, *wup, *wdown, *wfc1, *wfc2, *xpk, *attpk, *gatepk;
    cudaGetSymbolAddress((void**)&hs, g_hs);
    cudaGetSymbolAddress((void**)&qkv, g_qkv);
    cudaGetSymbolAddress((void**)&q, g_q);
    cudaGetSymbolAddress((void**)&k, g_k);
    cudaGetSymbolAddress((void**)&v, g_v);
    cudaGetSymbolAddress((void**)&gate, g_gate);
    cudaGetSymbolAddress((void**)&wqkv, g_wqkv);
    cudaGetSymbolAddress((void**)&wproj, g_wproj);
    cudaGetSymbolAddress((void**)&wgate, g_wgate);
    cudaGetSymbolAddress((void**)&wup, g_wup);
    cudaGetSymbolAddress((void**)&wdown, g_wdown);
    cudaGetSymbolAddress((void**)&wfc1, g_wfc1);
    cudaGetSymbolAddress((void**)&wfc2, g_wfc2);
    cudaGetSymbolAddress((void**)&xpk, g_xpk);
    cudaGetSymbolAddress((void**)&attpk, g_attpk);
    cudaGetSymbolAddress((void**)&gatepk, g_gatepk);

    const int nhid = S_LEN * HID;
    // launch order: 1 copy, 2 conv qkv, 3 conv proj, 4 rmsnorm, 5 conv gate,
    // 6 = first qkv GEMM (ncu -s 5 -c 1 capture target)
    copy_k<<<(nhid + 255) / 256, 256>>>(in_hs, hs, nhid);                       // 1
    conv_w(qkv_w, wqkv, (long)NLAYER * HID2, 3 * HID);                          // 2
    conv_w(proj_w, wproj, (long)NLAYER * HID2, HID);                            // 3
    rmsnorm_pack_k<false><<<S_LEN, 256>>>(hs, norm1_w, xpk);                    // 4
    conv_w(gate_w, wgate, (long)NLAYER * HID2, INTER);                          // 5
    launch_gemm<0, false>(xpk, wqkv, qkv_b, nullptr, qkv, S_LEN, 3 * HID, HID2); // 6
    conv_w(up_w, wup, (long)NLAYER * HID2, INTER);
    conv_w(down_w, wdown, (long)NLAYER * INTER2, HID);
    conv_w(fc1_w, wfc1, MERGED / 2, MERGED);
    conv_w(fc2_w, wfc2, MERGED / 2, OUTDIM);

    for (int i = 0; i < NLAYER; ++i) {
        int full = (i == 3 || i == 7) ? 1 : 0;
        if (i > 0) {
            rmsnorm_pack_k<false><<<S_LEN, 256>>>(hs, norm1_w + (long)i * HID, xpk);
            launch_gemm<0, false>(xpk, wqkv + (long)i * HID2 * 3 * HID,
                                  qkv_b + (long)i * 3 * HID, nullptr,
                                  qkv, S_LEN, 3 * HID, HID2);
        }
        rope_split_k<<<(nhid + 255) / 256, 256>>>(qkv, cosd, sind, q, k, v);
        attn_k<<<dim3(S_LEN / 64, NH), 256>>>(q, k, v, full ? fmask : wmask,
                                              full ? 0 : 1, attpk);
        launch_gemm<3, false>(attpk, wproj + (long)i * HID2 * HID,
                              proj_b + (long)i * HID, hs, hs, S_LEN, HID, HID2);
        rmsnorm_pack_k<false><<<S_LEN, 256>>>(hs, norm2_w + (long)i * HID, xpk);
        launch_gemm<1, false>(xpk, wgate + (long)i * HID2 * INTER,
                              gate_b + (long)i * INTER, nullptr,
                              gate, S_LEN, INTER, HID2);
        launch_gemm<4, true>(xpk, wup + (long)i * HID2 * INTER,
                             up_b + (long)i * INTER, gate,
                             gatepk, S_LEN, INTER, HID2);
        launch_gemm<3, false>(gatepk, wdown + (long)i * INTER2 * HID,
                              down_b + (long)i * HID, hs, hs, S_LEN, HID, INTER2);
    }

    // patch merger
    rmsnorm_pack_k<true><<<S_LEN, 256>>>(hs, ln_q_w, xpk);   // merger view [512 x 5120]
    launch_gemm<2, true>(xpk, wfc1, fc1_b, nullptr, attpk, MTOK, MERGED, MERGED / 2);
    launch_gemm<0, false>(attpk, wfc2, fc2_b, nullptr, out, MTOK, OUTDIM, MERGED / 2);
}

// round 10
// speedup vs baseline: 2.1131x; 1.2662x over previous
#include <cuda_runtime.h>
#include <cuda_bf16.h>
#include <math.h>
#include <stdint.h>

#define S_LEN 2048
#define HID 1280
#define NH 16
#define HD 80
#define INTER 3420
#define NLAYER 8
#define WIN 64
#define MERGED 5120
#define OUTDIM 3584
#define MTOK 512
#define HID2 (HID / 2)       // 640 pairs
#define INTER2 (INTER / 2)   // 1710 pairs

// ---------------- scratch ----------------
__device__ float g_hs  [S_LEN * HID];
__device__ float g_qkv [S_LEN * 3 * HID];
__device__ float g_gate[S_LEN * INTER];
__device__ uint2 g_wqkv [NLAYER * HID2 * 3 * HID];
__device__ uint2 g_wproj[NLAYER * HID2 * HID];
__device__ uint2 g_wgate[NLAYER * HID2 * INTER];
__device__ uint2 g_wup  [NLAYER * HID2 * INTER];
__device__ uint2 g_wdown[NLAYER * INTER2 * HID];
__device__ uint2 g_wfc1 [2560 * MERGED];
__device__ uint2 g_wfc2 [2560 * OUTDIM];
__device__ uint2 g_xpk  [2560 * 2048];
__device__ uint2 g_attpk[2560 * 2048];
__device__ uint2 g_gatepk[INTER2 * S_LEN];
__device__ uint2 g_qp[NH * 40 * S_LEN];    // Q packed k-major over d
__device__ uint2 g_kp[NH * 40 * S_LEN];    // K packed k-major over d
__device__ uint2 g_vp[NH * (S_LEN / 2) * HD];  // V packed pairs over kv

// ---------------- packing helpers ----------------
__device__ __forceinline__ void split_bf16(float x, uint16_t& b, uint16_t& s) {
    __nv_bfloat16 hb = __float2bfloat16(x);
    float r = x - __bfloat162float(hb);
    __nv_bfloat16 hs = __float2bfloat16(r);
    b = *(uint16_t*)&hb;
    s = *(uint16_t*)&hs;
}

__device__ __forceinline__ uint2 pack_pair(float lo, float hi) {
    uint16_t bl, sl, bh, sh;
    split_bf16(lo, bl, sl);
    split_bf16(hi, bh, sh);
    return make_uint2((uint32_t)bl | ((uint32_t)bh << 16),
                      (uint32_t)sl | ((uint32_t)sh << 16));
}

// ---------------- elementwise ----------------
__global__ void copy_k(const float* __restrict__ src, float* __restrict__ dst, int n) {
    int i = blockIdx.x * blockDim.x + threadIdx.x;
    if (i < n) dst[i] = src[i];
}

__global__ void convert_w_k(const float* __restrict__ W, uint2* __restrict__ out,
                            long total, int N) {
    long idx = (long)blockIdx.x * blockDim.x + threadIdx.x;
    if (idx >= total) return;
    long p = idx / N;
    int c = (int)(idx - p * N);
    out[idx] = pack_pair(W[(2 * p) * N + c], W[(2 * p + 1) * N + c]);
}

template <bool MERGER>
__global__ void __launch_bounds__(256) rmsnorm_pack_k(const float* __restrict__ x,
                                                      const float* __restrict__ w,
                                                      uint2* __restrict__ y) {
    int row = blockIdx.x;
    const float* xr = x + (long)row * HID;
    float ss = 0.f;
    for (int i = threadIdx.x; i < HID; i += 256) { float v = xr[i]; ss += v * v; }
    __shared__ float red[8];
    for (int o = 16; o > 0; o >>= 1) ss += __shfl_xor_sync(0xffffffffu, ss, o);
    if ((threadIdx.x & 31) == 0) red[threadIdx.x >> 5] = ss;
    __syncthreads();
    if (threadIdx.x < 32) {
        float v = (threadIdx.x < 8) ? red[threadIdx.x] : 0.f;
        for (int o = 4; o > 0; o >>= 1) v += __shfl_xor_sync(0xffffffffu, v, o);
        if (threadIdx.x == 0) red[0] = v;
    }
    __syncthreads();
    float inv = rsqrtf(red[0] / (float)HID + 1e-6f);
    for (int j = threadIdx.x; j < HID2; j += 256) {
        float v0 = xr[2 * j] * inv * w[2 * j];
        float v1 = xr[2 * j + 1] * inv * w[2 * j + 1];
        uint2 pk = pack_pair(v0, v1);
        if (MERGER)
            y[((long)((row & 3) * HID2 + j)) * MTOK + (row >> 2)] = pk;
        else
            y[(long)j * S_LEN + row] = pk;
    }
}

// ---------------- rope + pack q,k (k-major over d) and v (pairs over kv) ----------------
// grid (S/64, NH), 256 threads, dynamic smem 3*64*81 floats
__global__ void __launch_bounds__(256) rope_pack_k(const float* __restrict__ qkv,
                                                   const float* __restrict__ cs,
                                                   const float* __restrict__ sn,
                                                   uint2* __restrict__ Qp,
                                                   uint2* __restrict__ Kp,
                                                   uint2* __restrict__ Vp) {
    extern __shared__ float smf[];
    float (*sq)[81] = (float(*)[81])smf;
    float (*sk)[81] = (float(*)[81])(smf + 64 * 81);
    float (*sv)[81] = (float(*)[81])(smf + 2 * 64 * 81);
    int h = blockIdx.y;
    int s0 = blockIdx.x * 64;
    int tid = threadIdx.x;

    for (int idx = tid; idx < 64 * HD; idx += 256) {
        int si = idx / HD, d = idx % HD;
        int s = s0 + si;
        const float* base = qkv + (long)s * (3 * HID) + h * HD;
        float qv = base[d];
        float kv = base[HID + d];
        float vv = base[2 * HID + d];
        float c = cs[s * HD + d];
        float si_ = sn[s * HD + d];
        int dr = (d < HD / 2) ? (d + HD / 2) : (d - HD / 2);
        float sgn = (d < HD / 2) ? -1.f : 1.f;
        float qr = sgn * base[dr];
        float kr = sgn * base[HID + dr];
        sq[si][d] = qv * c + qr * si_;
        sk[si][d] = kv * c + kr * si_;
        sv[si][d] = vv;
    }
    __syncthreads();
    // q,k packed k-major: [h*40 + j][s]
    for (int idx = tid; idx < 40 * 64; idx += 256) {
        int j = idx >> 6, si = idx & 63;
        long o = ((long)h * 40 + j) * S_LEN + s0 + si;
        Qp[o] = pack_pair(sq[si][2 * j], sq[si][2 * j + 1]);
        Kp[o] = pack_pair(sk[si][2 * j], sk[si][2 * j + 1]);
    }
    // v pairs over s: [h*1024 + s0/2 + r][d]
    for (int idx = tid; idx < 32 * HD; idx += 256) {
        int r = idx / HD, d = idx % HD;
        Vp[((long)h * (S_LEN / 2) + (s0 >> 1) + r) * HD + d] =
            pack_pair(sv[2 * r][d], sv[2 * r + 1][d]);
    }
}

// ---------------- tensor-core flash attention (bf16x3) ----------------
// block = 64 q-rows x 1 head, 128 threads (4 warps, warp = 16 q-rows).
// smem: Qs[40][68], Ks[40][68], Vs[32][84] uint2.
#define QSTR 68
#define VSTR 84
#define ATT_SMEM ((40 * QSTR * 2 + 32 * VSTR) * (int)sizeof(uint2))

__device__ __forceinline__ void mma_bf16(float c[4], uint32_t a0, uint32_t a1,
                                         uint32_t a2, uint32_t a3,
                                         uint32_t b0, uint32_t b1) {
    asm volatile(
        "mma.sync.aligned.m16n8k16.row.col.f32.bf16.bf16.f32 "
        "{%0,%1,%2,%3}, {%4,%5,%6,%7}, {%8,%9}, {%0,%1,%2,%3};"
        : "+f"(c[0]), "+f"(c[1]), "+f"(c[2]), "+f"(c[3])
        : "r"(a0), "r"(a1), "r"(a2), "r"(a3), "r"(b0), "r"(b1));
}

__device__ __forceinline__ uint32_t pack_big(float lo, float hi) {
    __nv_bfloat162 h2 = __floats2bfloat162_rn(lo, hi);
    return *(uint32_t*)&h2;
}

__global__ void __launch_bounds__(128) attn_mma_k(const uint2* __restrict__ Qp,
                                                  const uint2* __restrict__ Kp,
                                                  const uint2* __restrict__ Vp,
                                                  const float* __restrict__ mask,
                                                  int windowed,
                                                  uint2* __restrict__ Opk) {
    extern __shared__ uint2 smu[];
    uint2 (*Qs)[QSTR] = (uint2(*)[QSTR])smu;
    uint2 (*Ks)[QSTR] = (uint2(*)[QSTR])(smu + 40 * QSTR);
    uint2 (*Vs)[VSTR] = (uint2(*)[VSTR])(smu + 2 * 40 * QSTR);

    int h = blockIdx.y;
    int q0 = blockIdx.x * 64;
    int tid = threadIdx.x;
    int w = tid >> 5;
    int lane = tid & 31;
    int g = lane >> 2;
    int tg = lane & 3;

    // load Q tile (64 q-rows x 40 pairs)
    for (int idx = tid; idx < 40 * 64; idx += 128) {
        int p = idx >> 6, c = idx & 63;
        Qs[p][c] = Qp[((long)h * 40 + p) * S_LEN + q0 + c];
    }

    float O[10][4];
#pragma unroll
    for (int ni = 0; ni < 10; ++ni)
#pragma unroll
        for (int r = 0; r < 4; ++r) O[ni][r] = 0.f;
    float m0 = -3.0e38f, m1 = -3.0e38f, l0 = 0.f, l1 = 0.f;

    const float scale = 0.11180339887498949f;
    const float NEG = -3.0e38f;
    int qa = q0 + w * 16 + g;

    int kvs = windowed ? q0 : 0;
    int kve = windowed ? q0 + 64 : S_LEN;

    for (int kv0 = kvs; kv0 < kve; kv0 += 64) {
        __syncthreads();
        for (int idx = tid; idx < 40 * 64; idx += 128) {
            int p = idx >> 6, c = idx & 63;
            Ks[p][c] = Kp[((long)h * 40 + p) * S_LEN + kv0 + c];
        }
        for (int idx = tid; idx < 32 * HD; idx += 128) {
            int r = idx / HD, d = idx % HD;
            Vs[r][d] = Vp[((long)h * (S_LEN / 2) + (kv0 >> 1) + r) * HD + d];
        }
        __syncthreads();

        // ---- S = Q K^T ----
        float s[8][4];
#pragma unroll
        for (int ni = 0; ni < 8; ++ni)
#pragma unroll
            for (int r = 0; r < 4; ++r) s[ni][r] = 0.f;
#pragma unroll
        for (int ch = 0; ch < 5; ++ch) {
            int c8 = ch * 8;
            uint2 a0 = Qs[c8 + tg][w * 16 + g];
            uint2 a1 = Qs[c8 + tg][w * 16 + g + 8];
            uint2 a2 = Qs[c8 + 4 + tg][w * 16 + g];
            uint2 a3 = Qs[c8 + 4 + tg][w * 16 + g + 8];
#pragma unroll
            for (int ni = 0; ni < 8; ++ni) {
                uint2 b0 = Ks[c8 + tg][ni * 8 + g];
                uint2 b1 = Ks[c8 + 4 + tg][ni * 8 + g];
                mma_bf16(s[ni], a0.x, a1.x, a2.x, a3.x, b0.x, b1.x);
                mma_bf16(s[ni], a0.x, a1.x, a2.x, a3.x, b0.y, b1.y);
                mma_bf16(s[ni], a0.y, a1.y, a2.y, a3.y, b0.x, b1.x);
            }
        }

        // ---- scale + mask ----
#pragma unroll
        for (int ni = 0; ni < 8; ++ni) {
            int col2 = ni * 8 + 2 * tg;
            float2 ma, mb;
            if (windowed) {
                const float* mb_ = mask + ((long)(q0 >> 6) * 64 + (w * 16 + g)) * 64;
                ma = *(const float2*)(mb_ + col2);
                mb = *(const float2*)(mb_ + 8 * 64 + col2);
            } else {
                ma = *(const float2*)(mask + (long)qa * S_LEN + kv0 + col2);
                mb = *(const float2*)(mask + (long)(qa + 8) * S_LEN + kv0 + col2);
            }
            s[ni][0] = s[ni][0] * scale + (1.f - ma.x) * NEG;
            s[ni][1] = s[ni][1] * scale + (1.f - ma.y) * NEG;
            s[ni][2] = s[ni][2] * scale + (1.f - mb.x) * NEG;
            s[ni][3] = s[ni][3] * scale + (1.f - mb.y) * NEG;
        }

        // ---- online softmax ----
        float t0 = -3.0e38f, t1 = -3.0e38f;
#pragma unroll
        for (int ni = 0; ni < 8; ++ni) {
            t0 = fmaxf(t0, fmaxf(s[ni][0], s[ni][1]));
            t1 = fmaxf(t1, fmaxf(s[ni][2], s[ni][3]));
        }
        t0 = fmaxf(t0, __shfl_xor_sync(0xffffffffu, t0, 1));
        t0 = fmaxf(t0, __shfl_xor_sync(0xffffffffu, t0, 2));
        t1 = fmaxf(t1, __shfl_xor_sync(0xffffffffu, t1, 1));
        t1 = fmaxf(t1, __shfl_xor_sync(0xffffffffu, t1, 2));
        float mn0 = fmaxf(m0, t0), mn1 = fmaxf(m1, t1);
        float corr0 = __expf(m0 - mn0), corr1 = __expf(m1 - mn1);
#pragma unroll
        for (int ni = 0; ni < 10; ++ni) {
            O[ni][0] *= corr0; O[ni][1] *= corr0;
            O[ni][2] *= corr1; O[ni][3] *= corr1;
        }
        float sum0 = 0.f, sum1 = 0.f;
#pragma unroll
        for (int ni = 0; ni < 8; ++ni) {
            s[ni][0] = __expf(s[ni][0] - mn0);
            s[ni][1] = __expf(s[ni][1] - mn0);
            s[ni][2] = __expf(s[ni][2] - mn1);
            s[ni][3] = __expf(s[ni][3] - mn1);
            sum0 += s[ni][0] + s[ni][1];
            sum1 += s[ni][2] + s[ni][3];
        }
        sum0 += __shfl_xor_sync(0xffffffffu, sum0, 1);
        sum0 += __shfl_xor_sync(0xffffffffu, sum0, 2);
        sum1 += __shfl_xor_sync(0xffffffffu, sum1, 1);
        sum1 += __shfl_xor_sync(0xffffffffu, sum1, 2);
        l0 = l0 * corr0 + sum0;
        l1 = l1 * corr1 + sum1;
        m0 = mn0; m1 = mn1;

        // ---- O += P V ----
#pragma unroll
        for (int ck = 0; ck < 4; ++ck) {
            // A fragments from P registers (big + small split)
            uint2 p00 = pack_pair(s[2 * ck][0], s[2 * ck][1]);
            uint2 p01 = pack_pair(s[2 * ck][2], s[2 * ck][3]);
            uint2 p10 = pack_pair(s[2 * ck + 1][0], s[2 * ck + 1][1]);
            uint2 p11 = pack_pair(s[2 * ck + 1][2], s[2 * ck + 1][3]);
#pragma unroll
            for (int ni = 0; ni < 10; ++ni) {
                uint2 b0 = Vs[ck * 8 + tg][ni * 8 + g];
                uint2 b1 = Vs[ck * 8 + 4 + tg][ni * 8 + g];
                mma_bf16(O[ni], p00.x, p01.x, p10.x, p11.x, b0.x, b1.x);
                mma_bf16(O[ni], p00.x, p01.x, p10.x, p11.x, b0.y, b1.y);
                mma_bf16(O[ni], p00.y, p01.y, p10.y, p11.y, b0.x, b1.x);
            }
        }
    }

    float invl0 = 1.f / l0, invl1 = 1.f / l1;
#pragma unroll
    for (int ni = 0; ni < 10; ++ni) {
        long pr = (long)h * 40 + ni * 4 + tg;
        Opk[pr * S_LEN + qa] = pack_pair(O[ni][0] * invl0, O[ni][1] * invl0);
        Opk[pr * S_LEN + qa + 8] = pack_pair(O[ni][2] * invl1, O[ni][3] * invl1);
    }
}

// ---------------- bf16x3 tensor-core GEMM, cp.async double-buffered ----------------
#define GBN 128
#define KP 16

__device__ __forceinline__ void cp16(uint32_t dst, const void* src, int sz) {
    asm volatile("cp.async.cg.shared.global [%0], [%1], 16, %2;"
                 :: "r"(dst), "l"(src), "r"(sz));
}
__device__ __forceinline__ void cp_commit() { asm volatile("cp.async.commit_group;" ::: "memory"); }
__device__ __forceinline__ void cp_wait1()  { asm volatile("cp.async.wait_group 1;" ::: "memory"); }

template <int EPI, bool PACK, int BM>
__global__ void __launch_bounds__(256, 2) mmagemm_k(const uint2* __restrict__ A,
                                                    const uint2* __restrict__ B,
                                                    const float* __restrict__ bias,
                                                    const float* __restrict__ res,
                                                    void* __restrict__ Cout,
                                                    int M, int N, int K2) {
    constexpr int ASTRU = (BM == 128) ? 132 : 68;
    constexpr int BSTRU = 132;
    constexpr int ATILE = KP * ASTRU;
    constexpr int BTILE = KP * BSTRU;
    constexpr int STAGE = ATILE + BTILE;
    constexpr int MI = BM / 32;

    extern __shared__ uint2 smp[];
    uint32_t smem_base = (uint32_t)__cvta_generic_to_shared(smp);

    int tid = threadIdx.x;
    int lane = tid & 31;
    int warp = tid >> 5;
    int warpM = warp & 1;
    int warpN = warp >> 1;
    int g = lane >> 2;
    int tg = lane & 3;

    int bmBase = blockIdx.y * BM;
    int bnBase = blockIdx.x * GBN;

    float acc[MI][4][4];
#pragma unroll
    for (int mi = 0; mi < MI; ++mi)
#pragma unroll
        for (int ni = 0; ni < 4; ++ni)
#pragma unroll
            for (int r = 0; r < 4; ++r) acc[mi][ni][r] = 0.f;

    int spr = tid >> 4;
    int scu = tid & 15;
    const uint2* Abase = A + bmBase;
    const uint2* Bbase = B + bnBase;

    int ntile = (K2 + KP - 1) / KP;

    auto stage_fn = [&](int t, int s) {
        int p = t * KP + spr;
        const uint2* Ar = Abase + (long)p * M;
        const uint2* Br = Bbase + (long)p * N;
        uint32_t aoff = smem_base + (uint32_t)((s * STAGE + spr * ASTRU) * 8);
        uint32_t boff = smem_base + (uint32_t)((s * STAGE + ATILE + spr * BSTRU) * 8);
        int kok = (p < K2) ? 16 : 0;
#pragma unroll
        for (int c = 0; c < BM / 32; ++c) {
            int cu = scu + 16 * c;
            cp16(aoff + cu * 16, Ar + 2 * cu, kok);
        }
#pragma unroll
        for (int c = 0; c < 4; ++c) {
            int cu = scu + 16 * c;
            int n0 = bnBase + 2 * cu;
            int sz = (kok == 0) ? 0 : ((n0 + 1 < N) ? 16 : ((n0 < N) ? 8 : 0));
            cp16(boff + cu * 16, Br + 2 * cu, sz);
        }
    };

    stage_fn(0, 0);
    cp_commit();
    if (ntile > 1) stage_fn(1, 1);
    cp_commit();

    for (int t = 0; t < ntile; ++t) {
        cp_wait1();
        __syncthreads();
        int s = t & 1;
        const uint2 (*As)[ASTRU] = (const uint2(*)[ASTRU])(smp + s * STAGE);
        const uint2 (*Bs)[BSTRU] = (const uint2(*)[BSTRU])(smp + s * STAGE + ATILE);

#pragma unroll
        for (int ck = 0; ck < 2; ++ck) {
            int c8 = ck * 8;
            uint2 b0[4], b1[4];
#pragma unroll
            for (int ni = 0; ni < 4; ++ni) {
                int n = warpN * 32 + ni * 8 + g;
                b0[ni] = Bs[c8 + tg][n];
                b1[ni] = Bs[c8 + tg + 4][n];
            }
#pragma unroll
            for (int mi = 0; mi < MI; ++mi) {
                int m = warpM * (BM / 2) + mi * 16 + g;
                uint2 a0 = As[c8 + tg][m];
                uint2 a1 = As[c8 + tg][m + 8];
                uint2 a2 = As[c8 + tg + 4][m];
                uint2 a3 = As[c8 + tg + 4][m + 8];
#pragma unroll
                for (int ni = 0; ni < 4; ++ni)
                    mma_bf16(acc[mi][ni], a0.x, a1.x, a2.x, a3.x, b0[ni].x, b1[ni].x);
#pragma unroll
                for (int ni = 0; ni < 4; ++ni)
                    mma_bf16(acc[mi][ni], a0.x, a1.x, a2.x, a3.x, b0[ni].y, b1[ni].y);
#pragma unroll
                for (int ni = 0; ni < 4; ++ni)
                    mma_bf16(acc[mi][ni], a0.y, a1.y, a2.y, a3.y, b0[ni].x, b1[ni].x);
            }
        }
        __syncthreads();
        if (t + 2 < ntile) stage_fn(t + 2, s);
        cp_commit();
    }

    float* Cf = (float*)Cout;
    uint2* Cp = (uint2*)Cout;
#pragma unroll
    for (int mi = 0; mi < MI; ++mi) {
        int row0 = bmBase + warpM * (BM / 2) + mi * 16 + g;
#pragma unroll
        for (int ni = 0; ni < 4; ++ni) {
            int col = bnBase + warpN * 32 + ni * 8 + 2 * tg;
            if (col >= N) continue;
            float b0 = bias[col], b1 = bias[col + 1];
#pragma unroll
            for (int rh = 0; rh < 2; ++rh) {
                int row = row0 + rh * 8;
                float v0 = acc[mi][ni][rh * 2 + 0] + b0;
                float v1 = acc[mi][ni][rh * 2 + 1] + b1;
                if (EPI == 1) {
                    v0 = v0 / (1.f + expf(-v0));
                    v1 = v1 / (1.f + expf(-v1));
                } else if (EPI == 2) {
                    v0 = 0.5f * v0 * (1.f + erff(v0 * 0.70710678118654752f));
                    v1 = 0.5f * v1 * (1.f + erff(v1 * 0.70710678118654752f));
                } else if (EPI == 3) {
                    v0 += res[(long)row * N + col];
                    v1 += res[(long)row * N + col + 1];
                } else if (EPI == 4) {
                    v0 *= res[(long)row * N + col];
                    v1 *= res[(long)row * N + col + 1];
                }
                if (PACK) {
                    Cp[(long)(col >> 1) * M + row] = pack_pair(v0, v1);
                } else {
                    Cf[(long)row * N + col] = v0;
                    Cf[(long)row * N + col + 1] = v1;
                }
            }
        }
    }
}

// ---------------- host ----------------
template <int EPI, bool PACK>
static void launch_gemm(const uint2* A, const uint2* B, const float* bias,
                        const float* res, void* C, int M, int N, int K2) {
    int gx = (N + GBN - 1) / GBN;
    int blocks128 = gx * (M / 128);
    if (blocks128 < 296 && (M % 64) == 0) {
        constexpr int SM64 = 2 * (KP * 68 + KP * 132) * (int)sizeof(uint2);
        cudaFuncSetAttribute(mmagemm_k<EPI, PACK, 64>,
                             cudaFuncAttributeMaxDynamicSharedMemorySize, SM64);
        mmagemm_k<EPI, PACK, 64><<<dim3(gx, M / 64), 256, SM64>>>(
            A, B, bias, res, C, M, N, K2);
    } else {
        constexpr int SM128 = 2 * (KP * 132 + KP * 132) * (int)sizeof(uint2);
        cudaFuncSetAttribute(mmagemm_k<EPI, PACK, 128>,
                             cudaFuncAttributeMaxDynamicSharedMemorySize, SM128);
        mmagemm_k<EPI, PACK, 128><<<dim3(gx, M / 128), 256, SM128>>>(
            A, B, bias, res, C, M, N, K2);
    }
}

static inline void conv_w(const float* W, uint2* out, long K2total, int N) {
    long n = K2total * N;
    convert_w_k<<<(unsigned)((n + 255) / 256), 256>>>(W, out, n, N);
}

extern "C" void kernel_launch(void* const* d_in, const int* in_sizes, int n_in,
                              void* d_out, int out_size) {
    const float* in_hs   = (const float*)d_in[0];
    const float* fmask   = (const float*)d_in[1];
    const float* wmask   = (const float*)d_in[2];
    const float* cosd    = (const float*)d_in[3];
    const float* sind    = (const float*)d_in[4];
    const float* norm1_w = (const float*)d_in[5];
    const float* norm2_w = (const float*)d_in[6];
    const float* qkv_w   = (const float*)d_in[7];
    const float* qkv_b   = (const float*)d_in[8];
    const float* proj_w  = (const float*)d_in[9];
    const float* proj_b  = (const float*)d_in[10];
    const float* gate_w  = (const float*)d_in[11];
    const float* gate_b  = (const float*)d_in[12];
    const float* up_w    = (const float*)d_in[13];
    const float* up_b    = (const float*)d_in[14];
    const float* down_w  = (const float*)d_in[15];
    const float* down_b  = (const float*)d_in[16];
    const float* ln_q_w  = (const float*)d_in[17];
    const float* fc1_w   = (const float*)d_in[18];
    const float* fc1_b   = (const float*)d_in[19];
    const float* fc2_w   = (const float*)d_in[20];
    const float* fc2_b   = (const float*)d_in[21];
    float* out = (float*)d_out;

    float *hs, *qkv, *gate;
    uint2 *wqkv, *wproj, *wgate, *wup, *wdown, *wfc1, *wfc2;
    uint2 *xpk, *attpk, *gatepk, *qp, *kp, *vp;
    cudaGetSymbolAddress((void**)&hs, g_hs);
    cudaGetSymbolAddress((void**)&qkv, g_qkv);
    cudaGetSymbolAddress((void**)&gate, g_gate);
    cudaGetSymbolAddress((void**)&wqkv, g_wqkv);
    cudaGetSymbolAddress((void**)&wproj, g_wproj);
    cudaGetSymbolAddress((void**)&wgate, g_wgate);
    cudaGetSymbolAddress((void**)&wup, g_wup);
    cudaGetSymbolAddress((void**)&wdown, g_wdown);
    cudaGetSymbolAddress((void**)&wfc1, g_wfc1);
    cudaGetSymbolAddress((void**)&wfc2, g_wfc2);
    cudaGetSymbolAddress((void**)&xpk, g_xpk);
    cudaGetSymbolAddress((void**)&attpk, g_attpk);
    cudaGetSymbolAddress((void**)&gatepk, g_gatepk);
    cudaGetSymbolAddress((void**)&qp, g_qp);
    cudaGetSymbolAddress((void**)&kp, g_kp);
    cudaGetSymbolAddress((void**)&vp, g_vp);

    const int nhid = S_LEN * HID;
    const int ROPE_SMEM = 3 * 64 * 81 * (int)sizeof(float);
    cudaFuncSetAttribute(rope_pack_k, cudaFuncAttributeMaxDynamicSharedMemorySize, ROPE_SMEM);
    cudaFuncSetAttribute(attn_mma_k, cudaFuncAttributeMaxDynamicSharedMemorySize, ATT_SMEM);

    // launch order: 1 copy, 2 conv_qkv, 3 rmsnorm, 4 = qkv GEMM (ncu capture)
    copy_k<<<(nhid + 255) / 256, 256>>>(in_hs, hs, nhid);
    conv_w(qkv_w, wqkv, (long)NLAYER * HID2, 3 * HID);
    rmsnorm_pack_k<false><<<S_LEN, 256>>>(hs, norm1_w, xpk);
    launch_gemm<0, false>(xpk, wqkv, qkv_b, nullptr, qkv, S_LEN, 3 * HID, HID2);
    conv_w(proj_w, wproj, (long)NLAYER * HID2, HID);
    conv_w(gate_w, wgate, (long)NLAYER * HID2, INTER);
    conv_w(up_w, wup, (long)NLAYER * HID2, INTER);
    conv_w(down_w, wdown, (long)NLAYER * INTER2, HID);
    conv_w(fc1_w, wfc1, MERGED / 2, MERGED);
    conv_w(fc2_w, wfc2, MERGED / 2, OUTDIM);

    for (int i = 0; i < NLAYER; ++i) {
        int full = (i == 3 || i == 7) ? 1 : 0;
        if (i > 0) {
            rmsnorm_pack_k<false><<<S_LEN, 256>>>(hs, norm1_w + (long)i * HID, xpk);
            launch_gemm<0, false>(xpk, wqkv + (long)i * HID2 * 3 * HID,
                                  qkv_b + (long)i * 3 * HID, nullptr,
                                  qkv, S_LEN, 3 * HID, HID2);
        }
        rope_pack_k<<<dim3(S_LEN / 64, NH), 256, ROPE_SMEM>>>(qkv, cosd, sind, qp, kp, vp);
        attn_mma_k<<<dim3(S_LEN / 64, NH), 128, ATT_SMEM>>>(
            qp, kp, vp, full ? fmask : wmask, full ? 0 : 1, attpk);
        launch_gemm<3, false>(attpk, wproj + (long)i * HID2 * HID,
                              proj_b + (long)i * HID, hs, hs, S_LEN, HID, HID2);
        rmsnorm_pack_k<false><<<S_LEN, 256>>>(hs, norm2_w + (long)i * HID, xpk);
        launch_gemm<1, false>(xpk, wgate + (long)i * HID2 * INTER,
                              gate_b + (long)i * INTER, nullptr,
                              gate, S_LEN, INTER, HID2);
        launch_gemm<4, true>(xpk, wup + (long)i * HID2 * INTER,
                             up_b + (long)i * INTER, gate,
                             gatepk, S_LEN, INTER, HID2);
        launch_gemm<3, false>(gatepk, wdown + (long)i * INTER2 * HID,
                              down_b + (long)i * HID, hs, hs, S_LEN, HID, INTER2);
    }

    // patch merger
    rmsnorm_pack_k<true><<<S_LEN, 256>>>(hs, ln_q_w, xpk);
    launch_gemm<2, true>(xpk, wfc1, fc1_b, nullptr, attpk, MTOK, MERGED, MERGED / 2);
    launch_gemm<0, false>(attpk, wfc2, fc2_b, nullptr, out, MTOK, OUTDIM, MERGED / 2);
}

// round 11
// speedup vs baseline: 2.1184x; 1.0025x over previous
#include <cuda_runtime.h>
#include <cuda_bf16.h>
#include <math.h>
#include <stdint.h>

#define S_LEN 2048
#define HID 1280
#define NH 16
#define HD 80
#define INTER 3420
#define NLAYER 8
#define WIN 64
#define MERGED 5120
#define OUTDIM 3584
#define MTOK 512
#define HID2 (HID / 2)       // 640 pairs
#define INTER2 (INTER / 2)   // 1710 pairs

// ---------------- scratch ----------------
__device__ float g_hs  [S_LEN * HID];
__device__ float g_qkv [S_LEN * 3 * HID];
__device__ float g_gate[S_LEN * INTER];
__device__ uint2 g_wqkv [NLAYER * HID2 * 3 * HID];
__device__ uint2 g_wproj[NLAYER * HID2 * HID];
__device__ uint2 g_wgate[NLAYER * HID2 * INTER];
__device__ uint2 g_wup  [NLAYER * HID2 * INTER];
__device__ uint2 g_wdown[NLAYER * INTER2 * HID];
__device__ uint2 g_wfc1 [2560 * MERGED];
__device__ uint2 g_wfc2 [2560 * OUTDIM];
__device__ uint2 g_xpk  [2560 * 2048];
__device__ uint2 g_attpk[2560 * 2048];
__device__ uint2 g_gatepk[INTER2 * S_LEN];
__device__ uint2 g_qp[NH * 40 * S_LEN];    // Q packed k-major over d
__device__ uint2 g_kp[NH * 40 * S_LEN];    // K packed k-major over d
__device__ uint2 g_vp[NH * (S_LEN / 2) * HD];  // V packed pairs over kv

// ---------------- packing helpers ----------------
__device__ __forceinline__ void split_bf16(float x, uint16_t& b, uint16_t& s) {
    __nv_bfloat16 hb = __float2bfloat16(x);
    float r = x - __bfloat162float(hb);
    __nv_bfloat16 hs = __float2bfloat16(r);
    b = *(uint16_t*)&hb;
    s = *(uint16_t*)&hs;
}

__device__ __forceinline__ uint2 pack_pair(float lo, float hi) {
    uint16_t bl, sl, bh, sh;
    split_bf16(lo, bl, sl);
    split_bf16(hi, bh, sh);
    return make_uint2((uint32_t)bl | ((uint32_t)bh << 16),
                      (uint32_t)sl | ((uint32_t)sh << 16));
}

// ---------------- elementwise ----------------
__global__ void copy_k(const float* __restrict__ src, float* __restrict__ dst, int n) {
    int i = blockIdx.x * blockDim.x + threadIdx.x;
    if (i < n) dst[i] = src[i];
}

__global__ void convert_w_k(const float* __restrict__ W, uint2* __restrict__ out,
                            long total, int N) {
    long idx = (long)blockIdx.x * blockDim.x + threadIdx.x;
    if (idx >= total) return;
    long p = idx / N;
    int c = (int)(idx - p * N);
    out[idx] = pack_pair(W[(2 * p) * N + c], W[(2 * p + 1) * N + c]);
}

template <bool MERGER>
__global__ void __launch_bounds__(256) rmsnorm_pack_k(const float* __restrict__ x,
                                                      const float* __restrict__ w,
                                                      uint2* __restrict__ y) {
    int row = blockIdx.x;
    const float* xr = x + (long)row * HID;
    float ss = 0.f;
    for (int i = threadIdx.x; i < HID; i += 256) { float v = xr[i]; ss += v * v; }
    __shared__ float red[8];
    for (int o = 16; o > 0; o >>= 1) ss += __shfl_xor_sync(0xffffffffu, ss, o);
    if ((threadIdx.x & 31) == 0) red[threadIdx.x >> 5] = ss;
    __syncthreads();
    if (threadIdx.x < 32) {
        float v = (threadIdx.x < 8) ? red[threadIdx.x] : 0.f;
        for (int o = 4; o > 0; o >>= 1) v += __shfl_xor_sync(0xffffffffu, v, o);
        if (threadIdx.x == 0) red[0] = v;
    }
    __syncthreads();
    float inv = rsqrtf(red[0] / (float)HID + 1e-6f);
    for (int j = threadIdx.x; j < HID2; j += 256) {
        float v0 = xr[2 * j] * inv * w[2 * j];
        float v1 = xr[2 * j + 1] * inv * w[2 * j + 1];
        uint2 pk = pack_pair(v0, v1);
        if (MERGER)
            y[((long)((row & 3) * HID2 + j)) * MTOK + (row >> 2)] = pk;
        else
            y[(long)j * S_LEN + row] = pk;
    }
}

// ---------------- rope + pack q,k (k-major over d) and v (pairs over kv) ----------------
// grid (S/64, NH), 256 threads, dynamic smem 3*64*81 floats
__global__ void __launch_bounds__(256) rope_pack_k(const float* __restrict__ qkv,
                                                   const float* __restrict__ cs,
                                                   const float* __restrict__ sn,
                                                   uint2* __restrict__ Qp,
                                                   uint2* __restrict__ Kp,
                                                   uint2* __restrict__ Vp) {
    extern __shared__ float smf[];
    float (*sq)[81] = (float(*)[81])smf;
    float (*sk)[81] = (float(*)[81])(smf + 64 * 81);
    float (*sv)[81] = (float(*)[81])(smf + 2 * 64 * 81);
    int h = blockIdx.y;
    int s0 = blockIdx.x * 64;
    int tid = threadIdx.x;

    for (int idx = tid; idx < 64 * HD; idx += 256) {
        int si = idx / HD, d = idx % HD;
        int s = s0 + si;
        const float* base = qkv + (long)s * (3 * HID) + h * HD;
        float qv = base[d];
        float kv = base[HID + d];
        float vv = base[2 * HID + d];
        float c = cs[s * HD + d];
        float si_ = sn[s * HD + d];
        int dr = (d < HD / 2) ? (d + HD / 2) : (d - HD / 2);
        float sgn = (d < HD / 2) ? -1.f : 1.f;
        float qr = sgn * base[dr];
        float kr = sgn * base[HID + dr];
        sq[si][d] = qv * c + qr * si_;
        sk[si][d] = kv * c + kr * si_;
        sv[si][d] = vv;
    }
    __syncthreads();
    // q,k packed k-major: [h*40 + j][s]
    for (int idx = tid; idx < 40 * 64; idx += 256) {
        int j = idx >> 6, si = idx & 63;
        long o = ((long)h * 40 + j) * S_LEN + s0 + si;
        Qp[o] = pack_pair(sq[si][2 * j], sq[si][2 * j + 1]);
        Kp[o] = pack_pair(sk[si][2 * j], sk[si][2 * j + 1]);
    }
    // v pairs over s: [h*1024 + s0/2 + r][d]
    for (int idx = tid; idx < 32 * HD; idx += 256) {
        int r = idx / HD, d = idx % HD;
        Vp[((long)h * (S_LEN / 2) + (s0 >> 1) + r) * HD + d] =
            pack_pair(sv[2 * r][d], sv[2 * r + 1][d]);
    }
}

// ---------------- tensor-core flash attention (bf16x3) ----------------
// block = 64 q-rows x 1 head, 128 threads (4 warps, warp = 16 q-rows).
// smem: Qs[40][68], Ks[40][68], Vs[32][84] uint2.
#define QSTR 68
#define VSTR 84
#define ATT_SMEM ((40 * QSTR * 2 + 32 * VSTR) * (int)sizeof(uint2))

__device__ __forceinline__ void mma_bf16(float c[4], uint32_t a0, uint32_t a1,
                                         uint32_t a2, uint32_t a3,
                                         uint32_t b0, uint32_t b1) {
    asm volatile(
        "mma.sync.aligned.m16n8k16.row.col.f32.bf16.bf16.f32 "
        "{%0,%1,%2,%3}, {%4,%5,%6,%7}, {%8,%9}, {%0,%1,%2,%3};"
        : "+f"(c[0]), "+f"(c[1]), "+f"(c[2]), "+f"(c[3])
        : "r"(a0), "r"(a1), "r"(a2), "r"(a3), "r"(b0), "r"(b1));
}

__device__ __forceinline__ uint32_t pack_big(float lo, float hi) {
    __nv_bfloat162 h2 = __floats2bfloat162_rn(lo, hi);
    return *(uint32_t*)&h2;
}

__global__ void __launch_bounds__(128) attn_mma_k(const uint2* __restrict__ Qp,
                                                  const uint2* __restrict__ Kp,
                                                  const uint2* __restrict__ Vp,
                                                  const float* __restrict__ mask,
                                                  int windowed,
                                                  uint2* __restrict__ Opk) {
    extern __shared__ uint2 smu[];
    uint2 (*Qs)[QSTR] = (uint2(*)[QSTR])smu;
    uint2 (*Ks)[QSTR] = (uint2(*)[QSTR])(smu + 40 * QSTR);
    uint2 (*Vs)[VSTR] = (uint2(*)[VSTR])(smu + 2 * 40 * QSTR);

    int h = blockIdx.y;
    int q0 = blockIdx.x * 64;
    int tid = threadIdx.x;
    int w = tid >> 5;
    int lane = tid & 31;
    int g = lane >> 2;
    int tg = lane & 3;

    // load Q tile (64 q-rows x 40 pairs)
    for (int idx = tid; idx < 40 * 64; idx += 128) {
        int p = idx >> 6, c = idx & 63;
        Qs[p][c] = Qp[((long)h * 40 + p) * S_LEN + q0 + c];
    }

    float O[10][4];
#pragma unroll
    for (int ni = 0; ni < 10; ++ni)
#pragma unroll
        for (int r = 0; r < 4; ++r) O[ni][r] = 0.f;
    float m0 = -3.0e38f, m1 = -3.0e38f, l0 = 0.f, l1 = 0.f;

    const float scale = 0.11180339887498949f;
    const float NEG = -3.0e38f;
    int qa = q0 + w * 16 + g;

    int kvs = windowed ? q0 : 0;
    int kve = windowed ? q0 + 64 : S_LEN;

    for (int kv0 = kvs; kv0 < kve; kv0 += 64) {
        __syncthreads();
        for (int idx = tid; idx < 40 * 64; idx += 128) {
            int p = idx >> 6, c = idx & 63;
            Ks[p][c] = Kp[((long)h * 40 + p) * S_LEN + kv0 + c];
        }
        for (int idx = tid; idx < 32 * HD; idx += 128) {
            int r = idx / HD, d = idx % HD;
            Vs[r][d] = Vp[((long)h * (S_LEN / 2) + (kv0 >> 1) + r) * HD + d];
        }
        __syncthreads();

        // ---- S = Q K^T ----
        float s[8][4];
#pragma unroll
        for (int ni = 0; ni < 8; ++ni)
#pragma unroll
            for (int r = 0; r < 4; ++r) s[ni][r] = 0.f;
#pragma unroll
        for (int ch = 0; ch < 5; ++ch) {
            int c8 = ch * 8;
            uint2 a0 = Qs[c8 + tg][w * 16 + g];
            uint2 a1 = Qs[c8 + tg][w * 16 + g + 8];
            uint2 a2 = Qs[c8 + 4 + tg][w * 16 + g];
            uint2 a3 = Qs[c8 + 4 + tg][w * 16 + g + 8];
#pragma unroll
            for (int ni = 0; ni < 8; ++ni) {
                uint2 b0 = Ks[c8 + tg][ni * 8 + g];
                uint2 b1 = Ks[c8 + 4 + tg][ni * 8 + g];
                mma_bf16(s[ni], a0.x, a1.x, a2.x, a3.x, b0.x, b1.x);
                mma_bf16(s[ni], a0.x, a1.x, a2.x, a3.x, b0.y, b1.y);
                mma_bf16(s[ni], a0.y, a1.y, a2.y, a3.y, b0.x, b1.x);
            }
        }

        // ---- scale + mask ----
#pragma unroll
        for (int ni = 0; ni < 8; ++ni) {
            int col2 = ni * 8 + 2 * tg;
            float2 ma, mb;
            if (windowed) {
                const float* mb_ = mask + ((long)(q0 >> 6) * 64 + (w * 16 + g)) * 64;
                ma = *(const float2*)(mb_ + col2);
                mb = *(const float2*)(mb_ + 8 * 64 + col2);
            } else {
                ma = *(const float2*)(mask + (long)qa * S_LEN + kv0 + col2);
                mb = *(const float2*)(mask + (long)(qa + 8) * S_LEN + kv0 + col2);
            }
            s[ni][0] = s[ni][0] * scale + (1.f - ma.x) * NEG;
            s[ni][1] = s[ni][1] * scale + (1.f - ma.y) * NEG;
            s[ni][2] = s[ni][2] * scale + (1.f - mb.x) * NEG;
            s[ni][3] = s[ni][3] * scale + (1.f - mb.y) * NEG;
        }

        // ---- online softmax ----
        float t0 = -3.0e38f, t1 = -3.0e38f;
#pragma unroll
        for (int ni = 0; ni < 8; ++ni) {
            t0 = fmaxf(t0, fmaxf(s[ni][0], s[ni][1]));
            t1 = fmaxf(t1, fmaxf(s[ni][2], s[ni][3]));
        }
        t0 = fmaxf(t0, __shfl_xor_sync(0xffffffffu, t0, 1));
        t0 = fmaxf(t0, __shfl_xor_sync(0xffffffffu, t0, 2));
        t1 = fmaxf(t1, __shfl_xor_sync(0xffffffffu, t1, 1));
        t1 = fmaxf(t1, __shfl_xor_sync(0xffffffffu, t1, 2));
        float mn0 = fmaxf(m0, t0), mn1 = fmaxf(m1, t1);
        float corr0 = __expf(m0 - mn0), corr1 = __expf(m1 - mn1);
#pragma unroll
        for (int ni = 0; ni < 10; ++ni) {
            O[ni][0] *= corr0; O[ni][1] *= corr0;
            O[ni][2] *= corr1; O[ni][3] *= corr1;
        }
        float sum0 = 0.f, sum1 = 0.f;
#pragma unroll
        for (int ni = 0; ni < 8; ++ni) {
            s[ni][0] = __expf(s[ni][0] - mn0);
            s[ni][1] = __expf(s[ni][1] - mn0);
            s[ni][2] = __expf(s[ni][2] - mn1);
            s[ni][3] = __expf(s[ni][3] - mn1);
            sum0 += s[ni][0] + s[ni][1];
            sum1 += s[ni][2] + s[ni][3];
        }
        sum0 += __shfl_xor_sync(0xffffffffu, sum0, 1);
        sum0 += __shfl_xor_sync(0xffffffffu, sum0, 2);
        sum1 += __shfl_xor_sync(0xffffffffu, sum1, 1);
        sum1 += __shfl_xor_sync(0xffffffffu, sum1, 2);
        l0 = l0 * corr0 + sum0;
        l1 = l1 * corr1 + sum1;
        m0 = mn0; m1 = mn1;

        // ---- O += P V ----
#pragma unroll
        for (int ck = 0; ck < 4; ++ck) {
            // A fragments from P registers (big + small split)
            uint2 p00 = pack_pair(s[2 * ck][0], s[2 * ck][1]);
            uint2 p01 = pack_pair(s[2 * ck][2], s[2 * ck][3]);
            uint2 p10 = pack_pair(s[2 * ck + 1][0], s[2 * ck + 1][1]);
            uint2 p11 = pack_pair(s[2 * ck + 1][2], s[2 * ck + 1][3]);
#pragma unroll
            for (int ni = 0; ni < 10; ++ni) {
                uint2 b0 = Vs[ck * 8 + tg][ni * 8 + g];
                uint2 b1 = Vs[ck * 8 + 4 + tg][ni * 8 + g];
                mma_bf16(O[ni], p00.x, p01.x, p10.x, p11.x, b0.x, b1.x);
                mma_bf16(O[ni], p00.x, p01.x, p10.x, p11.x, b0.y, b1.y);
                mma_bf16(O[ni], p00.y, p01.y, p10.y, p11.y, b0.x, b1.x);
            }
        }
    }

    float invl0 = 1.f / l0, invl1 = 1.f / l1;
#pragma unroll
    for (int ni = 0; ni < 10; ++ni) {
        long pr = (long)h * 40 + ni * 4 + tg;
        Opk[pr * S_LEN + qa] = pack_pair(O[ni][0] * invl0, O[ni][1] * invl0);
        Opk[pr * S_LEN + qa + 8] = pack_pair(O[ni][2] * invl1, O[ni][3] * invl1);
    }
}

// ---------------- bf16x3 tensor-core GEMM, cp.async double-buffered ----------------
#define GBN 128
#define KP 16

__device__ __forceinline__ void cp16(uint32_t dst, const void* src, int sz) {
    asm volatile("cp.async.cg.shared.global [%0], [%1], 16, %2;"
                 :: "r"(dst), "l"(src), "r"(sz));
}
__device__ __forceinline__ void cp_commit() { asm volatile("cp.async.commit_group;" ::: "memory"); }
__device__ __forceinline__ void cp_wait1()  { asm volatile("cp.async.wait_group 1;" ::: "memory"); }

template <int EPI, bool PACK, int BM>
__global__ void __launch_bounds__(256, 2) mmagemm_k(const uint2* __restrict__ A,
                                                    const uint2* __restrict__ B,
                                                    const float* __restrict__ bias,
                                                    const float* __restrict__ res,
                                                    void* __restrict__ Cout,
                                                    int M, int N, int K2) {
    constexpr int ASTRU = (BM == 128) ? 132 : 68;
    constexpr int BSTRU = 132;
    constexpr int ATILE = KP * ASTRU;
    constexpr int BTILE = KP * BSTRU;
    constexpr int STAGE = ATILE + BTILE;
    constexpr int MI = BM / 32;

    extern __shared__ uint2 smp[];
    uint32_t smem_base = (uint32_t)__cvta_generic_to_shared(smp);

    int tid = threadIdx.x;
    int lane = tid & 31;
    int warp = tid >> 5;
    int warpM = warp & 1;
    int warpN = warp >> 1;
    int g = lane >> 2;
    int tg = lane & 3;

    int bmBase = blockIdx.y * BM;
    int bnBase = blockIdx.x * GBN;

    float acc[MI][4][4];
#pragma unroll
    for (int mi = 0; mi < MI; ++mi)
#pragma unroll
        for (int ni = 0; ni < 4; ++ni)
#pragma unroll
            for (int r = 0; r < 4; ++r) acc[mi][ni][r] = 0.f;

    int spr = tid >> 4;
    int scu = tid & 15;
    const uint2* Abase = A + bmBase;
    const uint2* Bbase = B + bnBase;

    int ntile = (K2 + KP - 1) / KP;

    auto stage_fn = [&](int t, int s) {
        int p = t * KP + spr;
        const uint2* Ar = Abase + (long)p * M;
        const uint2* Br = Bbase + (long)p * N;
        uint32_t aoff = smem_base + (uint32_t)((s * STAGE + spr * ASTRU) * 8);
        uint32_t boff = smem_base + (uint32_t)((s * STAGE + ATILE + spr * BSTRU) * 8);
        int kok = (p < K2) ? 16 : 0;
#pragma unroll
        for (int c = 0; c < BM / 32; ++c) {
            int cu = scu + 16 * c;
            cp16(aoff + cu * 16, Ar + 2 * cu, kok);
        }
#pragma unroll
        for (int c = 0; c < 4; ++c) {
            int cu = scu + 16 * c;
            int n0 = bnBase + 2 * cu;
            int sz = (kok == 0) ? 0 : ((n0 + 1 < N) ? 16 : ((n0 < N) ? 8 : 0));
            cp16(boff + cu * 16, Br + 2 * cu, sz);
        }
    };

    stage_fn(0, 0);
    cp_commit();
    if (ntile > 1) stage_fn(1, 1);
    cp_commit();

    for (int t = 0; t < ntile; ++t) {
        cp_wait1();
        __syncthreads();
        int s = t & 1;
        const uint2 (*As)[ASTRU] = (const uint2(*)[ASTRU])(smp + s * STAGE);
        const uint2 (*Bs)[BSTRU] = (const uint2(*)[BSTRU])(smp + s * STAGE + ATILE);

#pragma unroll
        for (int ck = 0; ck < 2; ++ck) {
            int c8 = ck * 8;
            uint2 b0[4], b1[4];
#pragma unroll
            for (int ni = 0; ni < 4; ++ni) {
                int n = warpN * 32 + ni * 8 + g;
                b0[ni] = Bs[c8 + tg][n];
                b1[ni] = Bs[c8 + tg + 4][n];
            }
#pragma unroll
            for (int mi = 0; mi < MI; ++mi) {
                int m = warpM * (BM / 2) + mi * 16 + g;
                uint2 a0 = As[c8 + tg][m];
                uint2 a1 = As[c8 + tg][m + 8];
                uint2 a2 = As[c8 + tg + 4][m];
                uint2 a3 = As[c8 + tg + 4][m + 8];
#pragma unroll
                for (int ni = 0; ni < 4; ++ni)
                    mma_bf16(acc[mi][ni], a0.x, a1.x, a2.x, a3.x, b0[ni].x, b1[ni].x);
#pragma unroll
                for (int ni = 0; ni < 4; ++ni)
                    mma_bf16(acc[mi][ni], a0.x, a1.x, a2.x, a3.x, b0[ni].y, b1[ni].y);
#pragma unroll
                for (int ni = 0; ni < 4; ++ni)
                    mma_bf16(acc[mi][ni], a0.y, a1.y, a2.y, a3.y, b0[ni].x, b1[ni].x);
            }
        }
        __syncthreads();
        if (t + 2 < ntile) stage_fn(t + 2, s);
        cp_commit();
    }

    float* Cf = (float*)Cout;
    uint2* Cp = (uint2*)Cout;
#pragma unroll
    for (int mi = 0; mi < MI; ++mi) {
        int row0 = bmBase + warpM * (BM / 2) + mi * 16 + g;
#pragma unroll
        for (int ni = 0; ni < 4; ++ni) {
            int col = bnBase + warpN * 32 + ni * 8 + 2 * tg;
            if (col >= N) continue;
            float b0 = bias[col], b1 = bias[col + 1];
#pragma unroll
            for (int rh = 0; rh < 2; ++rh) {
                int row = row0 + rh * 8;
                float v0 = acc[mi][ni][rh * 2 + 0] + b0;
                float v1 = acc[mi][ni][rh * 2 + 1] + b1;
                if (EPI == 1) {
                    v0 = v0 / (1.f + expf(-v0));
                    v1 = v1 / (1.f + expf(-v1));
                } else if (EPI == 2) {
                    v0 = 0.5f * v0 * (1.f + erff(v0 * 0.70710678118654752f));
                    v1 = 0.5f * v1 * (1.f + erff(v1 * 0.70710678118654752f));
                } else if (EPI == 3) {
                    v0 += res[(long)row * N + col];
                    v1 += res[(long)row * N + col + 1];
                } else if (EPI == 4) {
                    v0 *= res[(long)row * N + col];
                    v1 *= res[(long)row * N + col + 1];
                }
                if (PACK) {
                    Cp[(long)(col >> 1) * M + row] = pack_pair(v0, v1);
                } else {
                    Cf[(long)row * N + col] = v0;
                    Cf[(long)row * N + col + 1] = v1;
                }
            }
        }
    }
}

// ---------------- host ----------------
template <int EPI, bool PACK>
static void launch_gemm(const uint2* A, const uint2* B, const float* bias,
                        const float* res, void* C, int M, int N, int K2) {
    int gx = (N + GBN - 1) / GBN;
    int blocks128 = gx * (M / 128);
    if (blocks128 < 296 && (M % 64) == 0) {
        constexpr int SM64 = 2 * (KP * 68 + KP * 132) * (int)sizeof(uint2);
        cudaFuncSetAttribute(mmagemm_k<EPI, PACK, 64>,
                             cudaFuncAttributeMaxDynamicSharedMemorySize, SM64);
        mmagemm_k<EPI, PACK, 64><<<dim3(gx, M / 64), 256, SM64>>>(
            A, B, bias, res, C, M, N, K2);
    } else {
        constexpr int SM128 = 2 * (KP * 132 + KP * 132) * (int)sizeof(uint2);
        cudaFuncSetAttribute(mmagemm_k<EPI, PACK, 128>,
                             cudaFuncAttributeMaxDynamicSharedMemorySize, SM128);
        mmagemm_k<EPI, PACK, 128><<<dim3(gx, M / 128), 256, SM128>>>(
            A, B, bias, res, C, M, N, K2);
    }
}

static inline void conv_w(const float* W, uint2* out, long K2total, int N) {
    long n = K2total * N;
    convert_w_k<<<(unsigned)((n + 255) / 256), 256>>>(W, out, n, N);
}

extern "C" void kernel_launch(void* const* d_in, const int* in_sizes, int n_in,
                              void* d_out, int out_size) {
    const float* in_hs   = (const float*)d_in[0];
    const float* fmask   = (const float*)d_in[1];
    const float* wmask   = (const float*)d_in[2];
    const float* cosd    = (const float*)d_in[3];
    const float* sind    = (const float*)d_in[4];
    const float* norm1_w = (const float*)d_in[5];
    const float* norm2_w = (const float*)d_in[6];
    const float* qkv_w   = (const float*)d_in[7];
    const float* qkv_b   = (const float*)d_in[8];
    const float* proj_w  = (const float*)d_in[9];
    const float* proj_b  = (const float*)d_in[10];
    const float* gate_w  = (const float*)d_in[11];
    const float* gate_b  = (const float*)d_in[12];
    const float* up_w    = (const float*)d_in[13];
    const float* up_b    = (const float*)d_in[14];
    const float* down_w  = (const float*)d_in[15];
    const float* down_b  = (const float*)d_in[16];
    const float* ln_q_w  = (const float*)d_in[17];
    const float* fc1_w   = (const float*)d_in[18];
    const float* fc1_b   = (const float*)d_in[19];
    const float* fc2_w   = (const float*)d_in[20];
    const float* fc2_b   = (const float*)d_in[21];
    float* out = (float*)d_out;

    float *hs, *qkv, *gate;
    uint2 *wqkv, *wproj, *wgate, *wup, *wdown, *wfc1, *wfc2;
    uint2 *xpk, *attpk, *gatepk, *qp, *kp, *vp;
    cudaGetSymbolAddress((void**)&hs, g_hs);
    cudaGetSymbolAddress((void**)&qkv, g_qkv);
    cudaGetSymbolAddress((void**)&gate, g_gate);
    cudaGetSymbolAddress((void**)&wqkv, g_wqkv);
    cudaGetSymbolAddress((void**)&wproj, g_wproj);
    cudaGetSymbolAddress((void**)&wgate, g_wgate);
    cudaGetSymbolAddress((void**)&wup, g_wup);
    cudaGetSymbolAddress((void**)&wdown, g_wdown);
    cudaGetSymbolAddress((void**)&wfc1, g_wfc1);
    cudaGetSymbolAddress((void**)&wfc2, g_wfc2);
    cudaGetSymbolAddress((void**)&xpk, g_xpk);
    cudaGetSymbolAddress((void**)&attpk, g_attpk);
    cudaGetSymbolAddress((void**)&gatepk, g_gatepk);
    cudaGetSymbolAddress((void**)&qp, g_qp);
    cudaGetSymbolAddress((void**)&kp, g_kp);
    cudaGetSymbolAddress((void**)&vp, g_vp);

    const int nhid = S_LEN * HID;
    const int ROPE_SMEM = 3 * 64 * 81 * (int)sizeof(float);
    cudaFuncSetAttribute(rope_pack_k, cudaFuncAttributeMaxDynamicSharedMemorySize, ROPE_SMEM);
    cudaFuncSetAttribute(attn_mma_k, cudaFuncAttributeMaxDynamicSharedMemorySize, ATT_SMEM);

    // launch order: 1 copy, 2 conv_qkv, 3 rmsnorm, 4 = qkv GEMM (ncu capture)
    copy_k<<<(nhid + 255) / 256, 256>>>(in_hs, hs, nhid);
    conv_w(qkv_w, wqkv, (long)NLAYER * HID2, 3 * HID);
    rmsnorm_pack_k<false><<<S_LEN, 256>>>(hs, norm1_w, xpk);
    launch_gemm<0, false>(xpk, wqkv, qkv_b, nullptr, qkv, S_LEN, 3 * HID, HID2);
    conv_w(proj_w, wproj, (long)NLAYER * HID2, HID);
    conv_w(gate_w, wgate, (long)NLAYER * HID2, INTER);
    conv_w(up_w, wup, (long)NLAYER * HID2, INTER);
    conv_w(down_w, wdown, (long)NLAYER * INTER2, HID);
    conv_w(fc1_w, wfc1, MERGED / 2, MERGED);
    conv_w(fc2_w, wfc2, MERGED / 2, OUTDIM);

    for (int i = 0; i < NLAYER; ++i) {
        int full = (i == 3 || i == 7) ? 1 : 0;
        if (i > 0) {
            rmsnorm_pack_k<false><<<S_LEN, 256>>>(hs, norm1_w + (long)i * HID, xpk);
            launch_gemm<0, false>(xpk, wqkv + (long)i * HID2 * 3 * HID,
                                  qkv_b + (long)i * 3 * HID, nullptr,
                                  qkv, S_LEN, 3 * HID, HID2);
        }
        rope_pack_k<<<dim3(S_LEN / 64, NH), 256, ROPE_SMEM>>>(qkv, cosd, sind, qp, kp, vp);
        attn_mma_k<<<dim3(S_LEN / 64, NH), 128, ATT_SMEM>>>(
            qp, kp, vp, full ? fmask : wmask, full ? 0 : 1, attpk);
        launch_gemm<3, false>(attpk, wproj + (long)i * HID2 * HID,
                              proj_b + (long)i * HID, hs, hs, S_LEN, HID, HID2);
        rmsnorm_pack_k<false><<<S_LEN, 256>>>(hs, norm2_w + (long)i * HID, xpk);
        launch_gemm<1, false>(xpk, wgate + (long)i * HID2 * INTER,
                              gate_b + (long)i * INTER, nullptr,
                              gate, S_LEN, INTER, HID2);
        launch_gemm<4, true>(xpk, wup + (long)i * HID2 * INTER,
                             up_b + (long)i * INTER, gate,
                             gatepk, S_LEN, INTER, HID2);
        launch_gemm<3, false>(gatepk, wdown + (long)i * INTER2 * HID,
                              down_b + (long)i * HID, hs, hs, S_LEN, HID, INTER2);
    }

    // patch merger
    rmsnorm_pack_k<true><<<S_LEN, 256>>>(hs, ln_q_w, xpk);
    launch_gemm<2, true>(xpk, wfc1, fc1_b, nullptr, attpk, MTOK, MERGED, MERGED / 2);
    launch_gemm<0, false>(attpk, wfc2, fc2_b, nullptr, out, MTOK, OUTDIM, MERGED / 2);
}

// round 13
// speedup vs baseline: 2.1449x; 1.0125x over previous
#include <cuda_runtime.h>
#include <cuda_bf16.h>
#include <math.h>
#include <stdint.h>

#define S_LEN 2048
#define HID 1280
#define NH 16
#define HD 80
#define INTER 3420
#define INTERP 3424
#define NLAYER 8
#define MERGED 5120
#define OUTDIM 3584
#define MTOK 512

// ---------------- scratch ----------------
__device__ float g_hs[S_LEN * HID];
__device__ float g_qkv[S_LEN * 3 * HID];
__device__ float g_gate[S_LEN * INTER];
__device__ __nv_bfloat16 g_wqkvB[NLAYER * 3840 * HID], g_wqkvS[NLAYER * 3840 * HID];
__device__ __nv_bfloat16 g_wprojB[NLAYER * HID * HID], g_wprojS[NLAYER * HID * HID];
__device__ __nv_bfloat16 g_wgateB[NLAYER * INTER * HID], g_wgateS[NLAYER * INTER * HID];
__device__ __nv_bfloat16 g_wupB[NLAYER * INTER * HID], g_wupS[NLAYER * INTER * HID];
__device__ __nv_bfloat16 g_wdownB[NLAYER * HID * INTERP], g_wdownS[NLAYER * HID * INTERP];
__device__ __nv_bfloat16 g_wfc1B[MERGED * MERGED], g_wfc1S[MERGED * MERGED];
__device__ __nv_bfloat16 g_wfc2B[OUTDIM * MERGED], g_wfc2S[OUTDIM * MERGED];
__device__ __nv_bfloat16 g_xB[S_LEN * HID], g_xS[S_LEN * HID];
__device__ __nv_bfloat16 g_aB[S_LEN * HID], g_aS[S_LEN * HID];
__device__ __nv_bfloat16 g_gB[S_LEN * INTERP], g_gS[S_LEN * INTERP];
__device__ uint2 g_qp[NH * 40 * S_LEN], g_kp[NH * 40 * S_LEN], g_vp[NH * (S_LEN / 2) * HD];

// ---------------- helpers ----------------
__device__ __forceinline__ void split_bf16(float x, uint16_t& b, uint16_t& s) {
    __nv_bfloat16 hb = __float2bfloat16(x);
    float r = x - __bfloat162float(hb);
    __nv_bfloat16 hs = __float2bfloat16(r);
    b = *(uint16_t*)&hb; s = *(uint16_t*)&hs;
}
__device__ __forceinline__ uint2 pack_pair(float lo, float hi) {
    uint16_t bl, sl, bh, sh;
    split_bf16(lo, bl, sl); split_bf16(hi, bh, sh);
    return make_uint2((uint32_t)bl | ((uint32_t)bh << 16), (uint32_t)sl | ((uint32_t)sh << 16));
}
__device__ __forceinline__ void store_plane2(__nv_bfloat16* B, __nv_bfloat16* S,
                                             long off, float v0, float v1) {
    uint16_t b0, s0, b1, s1;
    split_bf16(v0, b0, s0); split_bf16(v1, b1, s1);
    *(uint32_t*)(B + off) = (uint32_t)b0 | ((uint32_t)b1 << 16);
    *(uint32_t*)(S + off) = (uint32_t)s0 | ((uint32_t)s1 << 16);
}

// ---------------- elementwise ----------------
__global__ void copy_k(const float* __restrict__ src, float* __restrict__ dst, int n) {
    int i = blockIdx.x * blockDim.x + threadIdx.x;
    if (i < n) dst[i] = src[i];
}

// W[L][K][N] fp32 -> planes [L][N][ldw] bf16 (transpose)
__global__ void __launch_bounds__(256) convT_k(const float* __restrict__ W,
                                               __nv_bfloat16* __restrict__ outB,
                                               __nv_bfloat16* __restrict__ outS,
                                               int K, int N, int ldw) {
    __shared__ float tile[32][33];
    int l = blockIdx.z;
    const float* Wl = W + (long)l * K * N;
    long obase = (long)l * N * ldw;
    int n0 = blockIdx.x * 32, k0 = blockIdx.y * 32;
    int tx = threadIdx.x & 31, ty = threadIdx.x >> 5;
    for (int i = ty; i < 32; i += 8) {
        int k = k0 + i, n = n0 + tx;
        tile[i][tx] = (k < K && n < N) ? Wl[(long)k * N + n] : 0.f;
    }
    __syncthreads();
    for (int i = ty; i < 32; i += 8) {
        int n = n0 + i, k = k0 + tx;
        if (n < N && k < K) {
            uint16_t b, s;
            split_bf16(tile[tx][i], b, s);
            outB[obase + (long)n * ldw + k] = *(__nv_bfloat16*)&b;
            outS[obase + (long)n * ldw + k] = *(__nv_bfloat16*)&s;
        }
    }
}

template <bool MERGER>
__global__ void __launch_bounds__(256) rmsnorm_plane_k(const float* __restrict__ x,
                                                       const float* __restrict__ w,
                                                       __nv_bfloat16* __restrict__ yB,
                                                       __nv_bfloat16* __restrict__ yS) {
    int row = blockIdx.x;
    const float* xr = x + (long)row * HID;
    float ss = 0.f;
    for (int i = threadIdx.x; i < HID; i += 256) { float v = xr[i]; ss += v * v; }
    __shared__ float red[8];
    for (int o = 16; o > 0; o >>= 1) ss += __shfl_xor_sync(0xffffffffu, ss, o);
    if ((threadIdx.x & 31) == 0) red[threadIdx.x >> 5] = ss;
    __syncthreads();
    if (threadIdx.x < 32) {
        float v = (threadIdx.x < 8) ? red[threadIdx.x] : 0.f;
        for (int o = 4; o > 0; o >>= 1) v += __shfl_xor_sync(0xffffffffu, v, o);
        if (threadIdx.x == 0) red[0] = v;
    }
    __syncthreads();
    float inv = rsqrtf(red[0] / (float)HID + 1e-6f);
    long base = MERGER ? ((long)(row >> 2) * MERGED + (row & 3) * HID) : ((long)row * HID);
    for (int j = 2 * threadIdx.x; j < HID; j += 512)
        store_plane2(yB, yS, base + j, xr[j] * inv * w[j], xr[j + 1] * inv * w[j + 1]);
}

// rope + pack q,k k-major over d; v pairs over kv
__global__ void __launch_bounds__(256) rope_pack_k(const float* __restrict__ qkv,
                                                   const float* __restrict__ cs,
                                                   const float* __restrict__ sn,
                                                   uint2* __restrict__ Qp,
                                                   uint2* __restrict__ Kp,
                                                   uint2* __restrict__ Vp) {
    extern __shared__ float smf[];
    float (*sq)[81] = (float(*)[81])smf;
    float (*sk)[81] = (float(*)[81])(smf + 64 * 81);
    float (*sv)[81] = (float(*)[81])(smf + 2 * 64 * 81);
    int h = blockIdx.y, s0 = blockIdx.x * 64, tid = threadIdx.x;
    for (int idx = tid; idx < 64 * HD; idx += 256) {
        int si = idx / HD, d = idx % HD;
        int s = s0 + si;
        const float* base = qkv + (long)s * (3 * HID) + h * HD;
        float qv = base[d], kv = base[HID + d], vv = base[2 * HID + d];
        float c = cs[s * HD + d], si_ = sn[s * HD + d];
        int dr = (d < HD / 2) ? (d + HD / 2) : (d - HD / 2);
        float sgn = (d < HD / 2) ? -1.f : 1.f;
        sq[si][d] = qv * c + sgn * base[dr] * si_;
        sk[si][d] = kv * c + sgn * base[HID + dr] * si_;
        sv[si][d] = vv;
    }
    __syncthreads();
    for (int idx = tid; idx < 40 * 64; idx += 256) {
        int j = idx >> 6, si = idx & 63;
        long o = ((long)h * 40 + j) * S_LEN + s0 + si;
        Qp[o] = pack_pair(sq[si][2 * j], sq[si][2 * j + 1]);
        Kp[o] = pack_pair(sk[si][2 * j], sk[si][2 * j + 1]);
    }
    for (int idx = tid; idx < 32 * HD; idx += 256) {
        int r = idx / HD, d = idx % HD;
        Vp[((long)h * (S_LEN / 2) + (s0 >> 1) + r) * HD + d] = pack_pair(sv[2 * r][d], sv[2 * r + 1][d]);
    }
}

// ---------------- flash attention (mma.sync bf16x3), plane output ----------------
#define QSTR 68
#define VSTR 84
#define ATT_SMEM ((40 * QSTR * 2 + 32 * VSTR) * (int)sizeof(uint2))

__device__ __forceinline__ void mma_bf16(float c[4], uint32_t a0, uint32_t a1,
                                         uint32_t a2, uint32_t a3, uint32_t b0, uint32_t b1) {
    asm volatile(
        "mma.sync.aligned.m16n8k16.row.col.f32.bf16.bf16.f32 "
        "{%0,%1,%2,%3}, {%4,%5,%6,%7}, {%8,%9}, {%0,%1,%2,%3};"
        : "+f"(c[0]), "+f"(c[1]), "+f"(c[2]), "+f"(c[3])
        : "r"(a0), "r"(a1), "r"(a2), "r"(a3), "r"(b0), "r"(b1));
}

__global__ void __launch_bounds__(128) attn_mma_k(const uint2* __restrict__ Qp,
                                                  const uint2* __restrict__ Kp,
                                                  const uint2* __restrict__ Vp,
                                                  const float* __restrict__ mask,
                                                  int windowed,
                                                  __nv_bfloat16* __restrict__ Ob,
                                                  __nv_bfloat16* __restrict__ Os) {
    extern __shared__ uint2 smu[];
    uint2 (*Qs)[QSTR] = (uint2(*)[QSTR])smu;
    uint2 (*Ks)[QSTR] = (uint2(*)[QSTR])(smu + 40 * QSTR);
    uint2 (*Vs)[VSTR] = (uint2(*)[VSTR])(smu + 2 * 40 * QSTR);
    int h = blockIdx.y, q0 = blockIdx.x * 64, tid = threadIdx.x;
    int w = tid >> 5, lane = tid & 31, g = lane >> 2, tg = lane & 3;

    for (int idx = tid; idx < 40 * 64; idx += 128) {
        int p = idx >> 6, c = idx & 63;
        Qs[p][c] = Qp[((long)h * 40 + p) * S_LEN + q0 + c];
    }
    float O[10][4];
#pragma unroll
    for (int ni = 0; ni < 10; ++ni) { O[ni][0] = O[ni][1] = O[ni][2] = O[ni][3] = 0.f; }
    float m0 = -3.0e38f, m1 = -3.0e38f, l0 = 0.f, l1 = 0.f;
    const float scale = 0.11180339887498949f;
    const float NEG = -3.0e38f;
    int qa = q0 + w * 16 + g;
    int kvs = windowed ? q0 : 0;
    int kve = windowed ? q0 + 64 : S_LEN;

    for (int kv0 = kvs; kv0 < kve; kv0 += 64) {
        __syncthreads();
        for (int idx = tid; idx < 40 * 64; idx += 128) {
            int p = idx >> 6, c = idx & 63;
            Ks[p][c] = Kp[((long)h * 40 + p) * S_LEN + kv0 + c];
        }
        for (int idx = tid; idx < 32 * HD; idx += 128) {
            int r = idx / HD, d = idx % HD;
            Vs[r][d] = Vp[((long)h * (S_LEN / 2) + (kv0 >> 1) + r) * HD + d];
        }
        __syncthreads();

        float s[8][4];
#pragma unroll
        for (int ni = 0; ni < 8; ++ni) { s[ni][0] = s[ni][1] = s[ni][2] = s[ni][3] = 0.f; }
#pragma unroll
        for (int ch = 0; ch < 5; ++ch) {
            int c8 = ch * 8;
            uint2 a0 = Qs[c8 + tg][w * 16 + g];
            uint2 a1 = Qs[c8 + tg][w * 16 + g + 8];
            uint2 a2 = Qs[c8 + 4 + tg][w * 16 + g];
            uint2 a3 = Qs[c8 + 4 + tg][w * 16 + g + 8];
#pragma unroll
            for (int ni = 0; ni < 8; ++ni) {
                uint2 b0 = Ks[c8 + tg][ni * 8 + g];
                uint2 b1 = Ks[c8 + 4 + tg][ni * 8 + g];
                mma_bf16(s[ni], a0.x, a1.x, a2.x, a3.x, b0.x, b1.x);
                mma_bf16(s[ni], a0.x, a1.x, a2.x, a3.x, b0.y, b1.y);
                mma_bf16(s[ni], a0.y, a1.y, a2.y, a3.y, b0.x, b1.x);
            }
        }
#pragma unroll
        for (int ni = 0; ni < 8; ++ni) {
            int col2 = ni * 8 + 2 * tg;
            float2 ma, mb;
            if (windowed) {
                const float* mb_ = mask + ((long)(q0 >> 6) * 64 + (w * 16 + g)) * 64;
                ma = *(const float2*)(mb_ + col2);
                mb = *(const float2*)(mb_ + 8 * 64 + col2);
            } else {
                ma = *(const float2*)(mask + (long)qa * S_LEN + kv0 + col2);
                mb = *(const float2*)(mask + (long)(qa + 8) * S_LEN + kv0 + col2);
            }
            s[ni][0] = s[ni][0] * scale + (1.f - ma.x) * NEG;
            s[ni][1] = s[ni][1] * scale + (1.f - ma.y) * NEG;
            s[ni][2] = s[ni][2] * scale + (1.f - mb.x) * NEG;
            s[ni][3] = s[ni][3] * scale + (1.f - mb.y) * NEG;
        }
        float t0 = -3.0e38f, t1 = -3.0e38f;
#pragma unroll
        for (int ni = 0; ni < 8; ++ni) {
            t0 = fmaxf(t0, fmaxf(s[ni][0], s[ni][1]));
            t1 = fmaxf(t1, fmaxf(s[ni][2], s[ni][3]));
        }
        t0 = fmaxf(t0, __shfl_xor_sync(0xffffffffu, t0, 1));
        t0 = fmaxf(t0, __shfl_xor_sync(0xffffffffu, t0, 2));
        t1 = fmaxf(t1, __shfl_xor_sync(0xffffffffu, t1, 1));
        t1 = fmaxf(t1, __shfl_xor_sync(0xffffffffu, t1, 2));
        float mn0 = fmaxf(m0, t0), mn1 = fmaxf(m1, t1);
        float corr0 = __expf(m0 - mn0), corr1 = __expf(m1 - mn1);
#pragma unroll
        for (int ni = 0; ni < 10; ++ni) {
            O[ni][0] *= corr0; O[ni][1] *= corr0;
            O[ni][2] *= corr1; O[ni][3] *= corr1;
        }
        float sum0 = 0.f, sum1 = 0.f;
#pragma unroll
        for (int ni = 0; ni < 8; ++ni) {
            s[ni][0] = __expf(s[ni][0] - mn0);
            s[ni][1] = __expf(s[ni][1] - mn0);
            s[ni][2] = __expf(s[ni][2] - mn1);
            s[ni][3] = __expf(s[ni][3] - mn1);
            sum0 += s[ni][0] + s[ni][1];
            sum1 += s[ni][2] + s[ni][3];
        }
        sum0 += __shfl_xor_sync(0xffffffffu, sum0, 1);
        sum0 += __shfl_xor_sync(0xffffffffu, sum0, 2);
        sum1 += __shfl_xor_sync(0xffffffffu, sum1, 1);
        sum1 += __shfl_xor_sync(0xffffffffu, sum1, 2);
        l0 = l0 * corr0 + sum0;
        l1 = l1 * corr1 + sum1;
        m0 = mn0; m1 = mn1;
#pragma unroll
        for (int ck = 0; ck < 4; ++ck) {
            uint2 p00 = pack_pair(s[2 * ck][0], s[2 * ck][1]);
            uint2 p01 = pack_pair(s[2 * ck][2], s[2 * ck][3]);
            uint2 p10 = pack_pair(s[2 * ck + 1][0], s[2 * ck + 1][1]);
            uint2 p11 = pack_pair(s[2 * ck + 1][2], s[2 * ck + 1][3]);
#pragma unroll
            for (int ni = 0; ni < 10; ++ni) {
                uint2 b0 = Vs[ck * 8 + tg][ni * 8 + g];
                uint2 b1 = Vs[ck * 8 + 4 + tg][ni * 8 + g];
                mma_bf16(O[ni], p00.x, p01.x, p10.x, p11.x, b0.x, b1.x);
                mma_bf16(O[ni], p00.x, p01.x, p10.x, p11.x, b0.y, b1.y);
                mma_bf16(O[ni], p00.y, p01.y, p10.y, p11.y, b0.x, b1.x);
            }
        }
    }
    float invl0 = 1.f / l0, invl1 = 1.f / l1;
#pragma unroll
    for (int ni = 0; ni < 10; ++ni) {
        int col = h * HD + ni * 8 + 2 * tg;
        store_plane2(Ob, Os, (long)qa * HID + col, O[ni][0] * invl0, O[ni][1] * invl0);
        store_plane2(Ob, Os, (long)(qa + 8) * HID + col, O[ni][2] * invl1, O[ni][3] * invl1);
    }
}

// ---------------- plane GEMM: ldmatrix + mma.sync bf16x3, cp.async 2-stage ----------------
// A planes [M][lda] row-major, W planes [N][ldw] row-major. BK=32 bf16, row stride 80B.
#define RSTR 80

__device__ __forceinline__ void cp16(uint32_t dst, const void* src, int sz) {
    asm volatile("cp.async.cg.shared.global [%0], [%1], 16, %2;" :: "r"(dst), "l"(src), "r"(sz));
}
__device__ __forceinline__ void cp_commit() { asm volatile("cp.async.commit_group;" ::: "memory"); }
__device__ __forceinline__ void cp_wait1()  { asm volatile("cp.async.wait_group 1;" ::: "memory"); }

__device__ __forceinline__ void ldsm4(uint32_t& r0, uint32_t& r1, uint32_t& r2, uint32_t& r3,
                                      uint32_t addr) {
    asm volatile("ldmatrix.sync.aligned.m8n8.x4.shared.b16 {%0,%1,%2,%3}, [%4];"
                 : "=r"(r0), "=r"(r1), "=r"(r2), "=r"(r3) : "r"(addr));
}

template <int EPI, bool PACK, int BM>
__global__ void __launch_bounds__(256, 2) pgemm_k(
    const __nv_bfloat16* __restrict__ Apb, const __nv_bfloat16* __restrict__ Aps,
    const __nv_bfloat16* __restrict__ Wpb, const __nv_bfloat16* __restrict__ Wps,
    const float* __restrict__ bias, const float* __restrict__ res,
    float* __restrict__ Cf, __nv_bfloat16* __restrict__ Cb, __nv_bfloat16* __restrict__ Cs,
    int M, int N, int K, int lda, int ldw, int ldc) {
    constexpr int ATILE = BM * RSTR;      // bytes per A plane tile
    constexpr int BTILE = 128 * RSTR;     // bytes per B plane tile
    constexpr int STAGE = 2 * ATILE + 2 * BTILE;
    constexpr int MI = BM / 32;
    constexpr int NCP = (2 * BM + 256) * 4;   // cp16 ops per stage

    extern __shared__ char dsm[];
    uint32_t base = (uint32_t)__cvta_generic_to_shared(dsm);

    int tid = threadIdx.x;
    int lane = tid & 31;
    int warp = tid >> 5;
    int warpM = warp & 1;
    int warpN = warp >> 1;
    int g = lane >> 2;
    int tg = lane & 3;

    int bmBase = blockIdx.y * BM;
    int bnBase = blockIdx.x * 128;

    float acc[MI][4][4];
#pragma unroll
    for (int mi = 0; mi < MI; ++mi)
#pragma unroll
        for (int ni = 0; ni < 4; ++ni)
#pragma unroll
            for (int r = 0; r < 4; ++r) acc[mi][ni][r] = 0.f;

    int ntile = (K + 31) / 32;

    auto stage_fn = [&](int t, int s) {
        int k0 = t * 32;
        uint32_t sb = base + s * STAGE;
#pragma unroll
        for (int u = tid; u < NCP; u += 256) {
            int ru = u >> 2, c = u & 3;
            int kb = k0 + c * 8;
            int sz = 2 * (K - kb);
            sz = sz < 0 ? 0 : (sz > 16 ? 16 : sz);
            uint32_t dst;
            const __nv_bfloat16* src;
            if (ru < BM) {
                dst = sb + ru * RSTR + c * 16;
                src = Apb + (long)(bmBase + ru) * lda + kb;
            } else if (ru < 2 * BM) {
                int r = ru - BM;
                dst = sb + ATILE + r * RSTR + c * 16;
                src = Aps + (long)(bmBase + r) * lda + kb;
            } else if (ru < 2 * BM + 128) {
                int r = ru - 2 * BM;
                dst = sb + 2 * ATILE + r * RSTR + c * 16;
                src = Wpb + (long)(bnBase + r) * ldw + kb;
                if (bnBase + r >= N) sz = 0;
            } else {
                int r = ru - 2 * BM - 128;
                dst = sb + 2 * ATILE + BTILE + r * RSTR + c * 16;
                src = Wps + (long)(bnBase + r) * ldw + kb;
                if (bnBase + r >= N) sz = 0;
            }
            cp16(dst, src, sz);
        }
    };

    stage_fn(0, 0);
    cp_commit();
    if (ntile > 1) stage_fn(1, 1);
    cp_commit();

    for (int t = 0; t < ntile; ++t) {
        cp_wait1();
        __syncthreads();
        uint32_t sb = base + (t & 1) * STAGE;

#pragma unroll
        for (int kc = 0; kc < 2; ++kc) {
            // B fragments (big+small) for 4 ni via 2 x4-ldmatrix per plane
            uint32_t bb[4][2], bs[4][2];
            {
                uint32_t brow_lo = (uint32_t)(warpN * 32 + ((lane >> 4) << 3) + (lane & 7));
                uint32_t koffB = (uint32_t)(kc * 32 + (((lane >> 3) & 1) << 4));
#pragma unroll
                for (int p = 0; p < 2; ++p) {
                    uint32_t off = (brow_lo + p * 16) * RSTR + koffB;
                    ldsm4(bb[2 * p][0], bb[2 * p][1], bb[2 * p + 1][0], bb[2 * p + 1][1],
                          sb + 2 * ATILE + off);
                    ldsm4(bs[2 * p][0], bs[2 * p][1], bs[2 * p + 1][0], bs[2 * p + 1][1],
                          sb + 2 * ATILE + BTILE + off);
                }
            }
            uint32_t aoffc = (uint32_t)(kc * 32 + ((lane >> 4) << 4));
#pragma unroll
            for (int mi = 0; mi < MI; ++mi) {
                uint32_t arow = (uint32_t)(warpM * (BM / 2) + mi * 16 + (lane & 15));
                uint32_t off = arow * RSTR + aoffc;
                uint32_t a0, a1, a2, a3, s0, s1, s2, s3;
                ldsm4(a0, a1, a2, a3, sb + off);
                ldsm4(s0, s1, s2, s3, sb + ATILE + off);
#pragma unroll
                for (int ni = 0; ni < 4; ++ni)
                    mma_bf16(acc[mi][ni], a0, a1, a2, a3, bb[ni][0], bb[ni][1]);
#pragma unroll
                for (int ni = 0; ni < 4; ++ni)
                    mma_bf16(acc[mi][ni], a0, a1, a2, a3, bs[ni][0], bs[ni][1]);
#pragma unroll
                for (int ni = 0; ni < 4; ++ni)
                    mma_bf16(acc[mi][ni], s0, s1, s2, s3, bb[ni][0], bb[ni][1]);
            }
        }
        __syncthreads();
        if (t + 2 < ntile) stage_fn(t + 2, t & 1);
        cp_commit();
    }

    // ---- epilogue: c0=(g,2tg) c1=(g,2tg+1) c2=(g+8,2tg) c3=(g+8,2tg+1) ----
#pragma unroll
    for (int mi = 0; mi < MI; ++mi) {
        int row0 = bmBase + warpM * (BM / 2) + mi * 16 + g;
#pragma unroll
        for (int ni = 0; ni < 4; ++ni) {
            int col = bnBase + warpN * 32 + ni * 8 + 2 * tg;
            if (col >= N) continue;
            float b0 = bias[col], b1 = bias[col + 1];
#pragma unroll
            for (int rh = 0; rh < 2; ++rh) {
                int row = row0 + rh * 8;
                float v0 = acc[mi][ni][rh * 2 + 0] + b0;
                float v1 = acc[mi][ni][rh * 2 + 1] + b1;
                if (EPI == 1) {
                    v0 = v0 / (1.f + expf(-v0));
                    v1 = v1 / (1.f + expf(-v1));
                } else if (EPI == 2) {
                    v0 = 0.5f * v0 * (1.f + erff(v0 * 0.70710678118654752f));
                    v1 = 0.5f * v1 * (1.f + erff(v1 * 0.70710678118654752f));
                } else if (EPI == 3) {
                    v0 += res[(long)row * N + col];
                    v1 += res[(long)row * N + col + 1];
                } else if (EPI == 4) {
                    v0 *= res[(long)row * N + col];
                    v1 *= res[(long)row * N + col + 1];
                }
                if (PACK) store_plane2(Cb, Cs, (long)row * ldc + col, v0, v1);
                else *(float2*)(Cf + (long)row * ldc + col) = make_float2(v0, v1);
            }
        }
    }
}

// ---------------- host ----------------
template <int EPI, bool PACK>
static void launch_pg(const __nv_bfloat16* Ab, const __nv_bfloat16* As,
                      const __nv_bfloat16* Wb, const __nv_bfloat16* Ws,
                      const float* bias, const float* res,
                      float* Cf, __nv_bfloat16* Cb, __nv_bfloat16* Cs,
                      int M, int N, int K, int lda, int ldw, int ldc) {
    int gx = (N + 127) / 128;
    if (gx * (M / 128) < 296 && (M % 64) == 0) {
        constexpr int SM = 2 * (2 * 64 * RSTR + 2 * 128 * RSTR);
        cudaFuncSetAttribute(pgemm_k<EPI, PACK, 64>,
                             cudaFuncAttributeMaxDynamicSharedMemorySize, SM);
        pgemm_k<EPI, PACK, 64><<<dim3(gx, M / 64), 256, SM>>>(
            Ab, As, Wb, Ws, bias, res, Cf, Cb, Cs, M, N, K, lda, ldw, ldc);
    } else {
        constexpr int SM = 2 * (2 * 128 * RSTR + 2 * 128 * RSTR);
        cudaFuncSetAttribute(pgemm_k<EPI, PACK, 128>,
                             cudaFuncAttributeMaxDynamicSharedMemorySize, SM);
        pgemm_k<EPI, PACK, 128><<<dim3(gx, M / 128), 256, SM>>>(
            Ab, As, Wb, Ws, bias, res, Cf, Cb, Cs, M, N, K, lda, ldw, ldc);
    }
}

static inline void convT(const float* W, __nv_bfloat16* outB, __nv_bfloat16* outS,
                         int K, int N, int L, int ldw) {
    dim3 grid((N + 31) / 32, (K + 31) / 32, L);
    convT_k<<<grid, 256>>>(W, outB, outS, K, N, ldw);
}

#define SYM(p, g) cudaGetSymbolAddress((void**)&p, g)

extern "C" void kernel_launch(void* const* d_in, const int* in_sizes, int n_in,
                              void* d_out, int out_size) {
    const float* in_hs   = (const float*)d_in[0];
    const float* fmask   = (const float*)d_in[1];
    const float* wmask   = (const float*)d_in[2];
    const float* cosd    = (const float*)d_in[3];
    const float* sind    = (const float*)d_in[4];
    const float* norm1_w = (const float*)d_in[5];
    const float* norm2_w = (const float*)d_in[6];
    const float* qkv_w   = (const float*)d_in[7];
    const float* qkv_b   = (const float*)d_in[8];
    const float* proj_w  = (const float*)d_in[9];
    const float* proj_b  = (const float*)d_in[10];
    const float* gate_w  = (const float*)d_in[11];
    const float* gate_b  = (const float*)d_in[12];
    const float* up_w    = (const float*)d_in[13];
    const float* up_b    = (const float*)d_in[14];
    const float* down_w  = (const float*)d_in[15];
    const float* down_b  = (const float*)d_in[16];
    const float* ln_q_w  = (const float*)d_in[17];
    const float* fc1_w   = (const float*)d_in[18];
    const float* fc1_b   = (const float*)d_in[19];
    const float* fc2_w   = (const float*)d_in[20];
    const float* fc2_b   = (const float*)d_in[21];
    float* out = (float*)d_out;

    float *hs, *qkv, *gate;
    __nv_bfloat16 *wqkvB, *wqkvS, *wprojB, *wprojS, *wgateB, *wgateS, *wupB, *wupS;
    __nv_bfloat16 *wdownB, *wdownS, *wfc1B, *wfc1S, *wfc2B, *wfc2S;
    __nv_bfloat16 *xB, *xS, *aB, *aS, *gB, *gS;
    uint2 *qp, *kp, *vp;
    SYM(hs, g_hs); SYM(qkv, g_qkv); SYM(gate, g_gate);
    SYM(wqkvB, g_wqkvB); SYM(wqkvS, g_wqkvS);
    SYM(wprojB, g_wprojB); SYM(wprojS, g_wprojS);
    SYM(wgateB, g_wgateB); SYM(wgateS, g_wgateS);
    SYM(wupB, g_wupB); SYM(wupS, g_wupS);
    SYM(wdownB, g_wdownB); SYM(wdownS, g_wdownS);
    SYM(wfc1B, g_wfc1B); SYM(wfc1S, g_wfc1S);
    SYM(wfc2B, g_wfc2B); SYM(wfc2S, g_wfc2S);
    SYM(xB, g_xB); SYM(xS, g_xS); SYM(aB, g_aB); SYM(aS, g_aS);
    SYM(gB, g_gB); SYM(gS, g_gS);
    SYM(qp, g_qp); SYM(kp, g_kp); SYM(vp, g_vp);

    const int nhid = S_LEN * HID;
    const int ROPE_SMEM = 3 * 64 * 81 * (int)sizeof(float);
    cudaFuncSetAttribute(rope_pack_k, cudaFuncAttributeMaxDynamicSharedMemorySize, ROPE_SMEM);
    cudaFuncSetAttribute(attn_mma_k, cudaFuncAttributeMaxDynamicSharedMemorySize, ATT_SMEM);

    // 1 copy, 2 convT qkv, 3 rmsnorm, 4 qkv GEMM (ncu capture target)
    copy_k<<<(nhid + 255) / 256, 256>>>(in_hs, hs, nhid);
    convT(qkv_w, wqkvB, wqkvS, HID, 3 * HID, NLAYER, HID);
    rmsnorm_plane_k<false><<<S_LEN, 256>>>(hs, norm1_w, xB, xS);
    launch_pg<0, false>(xB, xS, wqkvB, wqkvS, qkv_b, nullptr, qkv, nullptr, nullptr,
                        S_LEN, 3 * HID, HID, HID, HID, 3 * HID);
    convT(proj_w, wprojB, wprojS, HID, HID, NLAYER, HID);
    convT(gate_w, wgateB, wgateS, HID, INTER, NLAYER, HID);
    convT(up_w, wupB, wupS, HID, INTER, NLAYER, HID);
    convT(down_w, wdownB, wdownS, INTER, HID, NLAYER, INTERP);
    convT(fc1_w, wfc1B, wfc1S, MERGED, MERGED, 1, MERGED);
    convT(fc2_w, wfc2B, wfc2S, MERGED, OUTDIM, 1, MERGED);

    for (int i = 0; i < NLAYER; ++i) {
        int full = (i == 3 || i == 7) ? 1 : 0;
        if (i > 0) {
            rmsnorm_plane_k<false><<<S_LEN, 256>>>(hs, norm1_w + (long)i * HID, xB, xS);
            launch_pg<0, false>(xB, xS, wqkvB + (long)i * 3840 * HID, wqkvS + (long)i * 3840 * HID,
                                qkv_b + (long)i * 3 * HID, nullptr, qkv, nullptr, nullptr,
                                S_LEN, 3 * HID, HID, HID, HID, 3 * HID);
        }
        rope_pack_k<<<dim3(S_LEN / 64, NH), 256, ROPE_SMEM>>>(qkv, cosd, sind, qp, kp, vp);
        attn_mma_k<<<dim3(S_LEN / 64, NH), 128, ATT_SMEM>>>(
            qp, kp, vp, full ? fmask : wmask, full ? 0 : 1, aB, aS);
        launch_pg<3, false>(aB, aS, wprojB + (long)i * HID * HID, wprojS + (long)i * HID * HID,
                            proj_b + (long)i * HID, hs, hs, nullptr, nullptr,
                            S_LEN, HID, HID, HID, HID, HID);
        rmsnorm_plane_k<false><<<S_LEN, 256>>>(hs, norm2_w + (long)i * HID, xB, xS);
        launch_pg<1, false>(xB, xS, wgateB + (long)i * INTER * HID, wgateS + (long)i * INTER * HID,
                            gate_b + (long)i * INTER, nullptr, gate, nullptr, nullptr,
                            S_LEN, INTER, HID, HID, HID, INTER);
        launch_pg<4, true>(xB, xS, wupB + (long)i * INTER * HID, wupS + (long)i * INTER * HID,
                           up_b + (long)i * INTER, gate, nullptr, gB, gS,
                           S_LEN, INTER, HID, HID, HID, INTERP);
        launch_pg<3, false>(gB, gS, wdownB + (long)i * HID * INTERP, wdownS + (long)i * HID * INTERP,
                            down_b + (long)i * HID, hs, hs, nullptr, nullptr,
                            S_LEN, HID, INTER, INTERP, INTERP, HID);
    }

    // patch merger
    rmsnorm_plane_k<true><<<S_LEN, 256>>>(hs, ln_q_w, xB, xS);
    launch_pg<2, true>(xB, xS, wfc1B, wfc1S, fc1_b, nullptr, nullptr, aB, aS,
                       MTOK, MERGED, MERGED, MERGED, MERGED, MERGED);
    launch_pg<0, false>(aB, aS, wfc2B, wfc2S, fc2_b, nullptr, out, nullptr, nullptr,
                        MTOK, OUTDIM, MERGED, MERGED, MERGED, OUTDIM);
}

// round 14
// speedup vs baseline: 2.2088x; 1.0298x over previous
#include <cuda_runtime.h>
#include <cuda_bf16.h>
#include <math.h>
#include <stdint.h>

#define S_LEN 2048
#define HID 1280
#define NH 16
#define HD 80
#define INTER 3420
#define INTERP 3424
#define NLAYER 8
#define MERGED 5120
#define OUTDIM 3584
#define MTOK 512

// ---------------- scratch ----------------
__device__ float g_hs[S_LEN * HID];
__device__ float g_qkv[S_LEN * 3 * HID];
__device__ __nv_bfloat16 g_wqkvB[NLAYER * 3840 * HID], g_wqkvS[NLAYER * 3840 * HID];
__device__ __nv_bfloat16 g_wprojB[NLAYER * HID * HID], g_wprojS[NLAYER * HID * HID];
__device__ __nv_bfloat16 g_wguB[NLAYER * 2 * INTER * HID], g_wguS[NLAYER * 2 * INTER * HID];
__device__ __nv_bfloat16 g_wdownB[NLAYER * HID * INTERP], g_wdownS[NLAYER * HID * INTERP];
__device__ __nv_bfloat16 g_wfc1B[MERGED * MERGED], g_wfc1S[MERGED * MERGED];
__device__ __nv_bfloat16 g_wfc2B[OUTDIM * MERGED], g_wfc2S[OUTDIM * MERGED];
__device__ __nv_bfloat16 g_xB[S_LEN * HID], g_xS[S_LEN * HID];
__device__ __nv_bfloat16 g_aB[S_LEN * HID], g_aS[S_LEN * HID];
__device__ __nv_bfloat16 g_gB[S_LEN * INTERP], g_gS[S_LEN * INTERP];
__device__ uint2 g_qp[NH * 40 * S_LEN], g_kp[NH * 40 * S_LEN], g_vp[NH * (S_LEN / 2) * HD];

// ---------------- helpers ----------------
__device__ __forceinline__ void split_bf16(float x, uint16_t& b, uint16_t& s) {
    __nv_bfloat16 hb = __float2bfloat16(x);
    float r = x - __bfloat162float(hb);
    __nv_bfloat16 hs = __float2bfloat16(r);
    b = *(uint16_t*)&hb; s = *(uint16_t*)&hs;
}
__device__ __forceinline__ uint2 pack_pair(float lo, float hi) {
    uint16_t bl, sl, bh, sh;
    split_bf16(lo, bl, sl); split_bf16(hi, bh, sh);
    return make_uint2((uint32_t)bl | ((uint32_t)bh << 16), (uint32_t)sl | ((uint32_t)sh << 16));
}
__device__ __forceinline__ void store_plane2(__nv_bfloat16* B, __nv_bfloat16* S,
                                             long off, float v0, float v1) {
    uint16_t b0, s0, b1, s1;
    split_bf16(v0, b0, s0); split_bf16(v1, b1, s1);
    *(uint32_t*)(B + off) = (uint32_t)b0 | ((uint32_t)b1 << 16);
    *(uint32_t*)(S + off) = (uint32_t)s0 | ((uint32_t)s1 << 16);
}

// ---------------- elementwise ----------------
__global__ void copy_k(const float* __restrict__ src, float* __restrict__ dst, int n) {
    int i = blockIdx.x * blockDim.x + threadIdx.x;
    if (i < n) dst[i] = src[i];
}

// W[L][K][N] fp32 -> planes [L][N][ldw] bf16 (transpose), uint32 writes
__global__ void __launch_bounds__(256) convT_k(const float* __restrict__ W,
                                               __nv_bfloat16* __restrict__ outB,
                                               __nv_bfloat16* __restrict__ outS,
                                               int K, int N, int ldw) {
    __shared__ float tile[32][33];
    int l = blockIdx.z;
    const float* Wl = W + (long)l * K * N;
    long obase = (long)l * N * ldw;
    int n0 = blockIdx.x * 32, k0 = blockIdx.y * 32;
    int tx = threadIdx.x & 31, ty = threadIdx.x >> 5;
    for (int i = ty; i < 32; i += 8) {
        int k = k0 + i, n = n0 + tx;
        tile[i][tx] = (k < K && n < N) ? Wl[(long)k * N + n] : 0.f;
    }
    __syncthreads();
    int kp = threadIdx.x & 15, nr = threadIdx.x >> 4;
#pragma unroll
    for (int pass = 0; pass < 2; ++pass) {
        int i = nr + pass * 16;
        int n = n0 + i, k = k0 + 2 * kp;
        if (n < N && k < K) {
            uint16_t b0, s0, b1, s1;
            split_bf16(tile[2 * kp][i], b0, s0);
            split_bf16(tile[2 * kp + 1][i], b1, s1);
            *(uint32_t*)(outB + obase + (long)n * ldw + k) = (uint32_t)b0 | ((uint32_t)b1 << 16);
            *(uint32_t*)(outS + obase + (long)n * ldw + k) = (uint32_t)s0 | ((uint32_t)s1 << 16);
        }
    }
}

// gate/up interleaved: out row 2j = gate col j, row 2j+1 = up col j
__global__ void __launch_bounds__(256) convT2_k(const float* __restrict__ Wg,
                                                const float* __restrict__ Wu,
                                                __nv_bfloat16* __restrict__ outB,
                                                __nv_bfloat16* __restrict__ outS) {
    __shared__ float tg_[32][33];
    __shared__ float tu_[32][33];
    int l = blockIdx.z;
    const float* Wgl = Wg + (long)l * HID * INTER;
    const float* Wul = Wu + (long)l * HID * INTER;
    long obase = (long)l * 2 * INTER * HID;
    int n0 = blockIdx.x * 32, k0 = blockIdx.y * 32;
    int tx = threadIdx.x & 31, ty = threadIdx.x >> 5;
    for (int i = ty; i < 32; i += 8) {
        int k = k0 + i, n = n0 + tx;
        float gv = (k < HID && n < INTER) ? Wgl[(long)k * INTER + n] : 0.f;
        float uv = (k < HID && n < INTER) ? Wul[(long)k * INTER + n] : 0.f;
        tg_[i][tx] = gv; tu_[i][tx] = uv;
    }
    __syncthreads();
    int kp = threadIdx.x & 15, nr = threadIdx.x >> 4;
#pragma unroll
    for (int pass = 0; pass < 2; ++pass) {
        int i = nr + pass * 16;
        int n = n0 + i, k = k0 + 2 * kp;
        if (n < INTER && k < HID) {
            uint16_t b0, s0, b1, s1;
            split_bf16(tg_[2 * kp][i], b0, s0);
            split_bf16(tg_[2 * kp + 1][i], b1, s1);
            *(uint32_t*)(outB + obase + (long)(2 * n) * HID + k) = (uint32_t)b0 | ((uint32_t)b1 << 16);
            *(uint32_t*)(outS + obase + (long)(2 * n) * HID + k) = (uint32_t)s0 | ((uint32_t)s1 << 16);
            split_bf16(tu_[2 * kp][i], b0, s0);
            split_bf16(tu_[2 * kp + 1][i], b1, s1);
            *(uint32_t*)(outB + obase + (long)(2 * n + 1) * HID + k) = (uint32_t)b0 | ((uint32_t)b1 << 16);
            *(uint32_t*)(outS + obase + (long)(2 * n + 1) * HID + k) = (uint32_t)s0 | ((uint32_t)s1 << 16);
        }
    }
}

// warp-per-row rmsnorm -> planes
template <bool MERGER>
__global__ void __launch_bounds__(256) rmsnorm_plane_k(const float* __restrict__ x,
                                                       const float* __restrict__ w,
                                                       __nv_bfloat16* __restrict__ yB,
                                                       __nv_bfloat16* __restrict__ yS) {
    int row = blockIdx.x * 8 + (threadIdx.x >> 5);
    int lane = threadIdx.x & 31;
    const float* xr = x + (long)row * HID;
    float2 v[20];
    float ss = 0.f;
#pragma unroll
    for (int i = 0; i < 20; ++i) {
        v[i] = *(const float2*)(xr + i * 64 + 2 * lane);
        ss += v[i].x * v[i].x + v[i].y * v[i].y;
    }
#pragma unroll
    for (int o = 16; o > 0; o >>= 1) ss += __shfl_xor_sync(0xffffffffu, ss, o);
    float inv = rsqrtf(ss / (float)HID + 1e-6f);
    long base = MERGER ? ((long)(row >> 2) * MERGED + (row & 3) * HID) : ((long)row * HID);
#pragma unroll
    for (int i = 0; i < 20; ++i) {
        int col = i * 64 + 2 * lane;
        float2 wv = *(const float2*)(w + col);
        store_plane2(yB, yS, base + col, v[i].x * inv * wv.x, v[i].y * inv * wv.y);
    }
}

// rope + pack q,k k-major over d; v pairs over kv
__global__ void __launch_bounds__(256) rope_pack_k(const float* __restrict__ qkv,
                                                   const float* __restrict__ cs,
                                                   const float* __restrict__ sn,
                                                   uint2* __restrict__ Qp,
                                                   uint2* __restrict__ Kp,
                                                   uint2* __restrict__ Vp) {
    extern __shared__ float smf[];
    float (*sq)[81] = (float(*)[81])smf;
    float (*sk)[81] = (float(*)[81])(smf + 64 * 81);
    float (*sv)[81] = (float(*)[81])(smf + 2 * 64 * 81);
    int h = blockIdx.y, s0 = blockIdx.x * 64, tid = threadIdx.x;
    for (int idx = tid; idx < 64 * HD; idx += 256) {
        int si = idx / HD, d = idx % HD;
        int s = s0 + si;
        const float* base = qkv + (long)s * (3 * HID) + h * HD;
        float qv = base[d], kv = base[HID + d], vv = base[2 * HID + d];
        float c = cs[s * HD + d], si_ = sn[s * HD + d];
        int dr = (d < HD / 2) ? (d + HD / 2) : (d - HD / 2);
        float sgn = (d < HD / 2) ? -1.f : 1.f;
        sq[si][d] = qv * c + sgn * base[dr] * si_;
        sk[si][d] = kv * c + sgn * base[HID + dr] * si_;
        sv[si][d] = vv;
    }
    __syncthreads();
    for (int idx = tid; idx < 40 * 64; idx += 256) {
        int j = idx >> 6, si = idx & 63;
        long o = ((long)h * 40 + j) * S_LEN + s0 + si;
        Qp[o] = pack_pair(sq[si][2 * j], sq[si][2 * j + 1]);
        Kp[o] = pack_pair(sk[si][2 * j], sk[si][2 * j + 1]);
    }
    for (int idx = tid; idx < 32 * HD; idx += 256) {
        int r = idx / HD, d = idx % HD;
        Vp[((long)h * (S_LEN / 2) + (s0 >> 1) + r) * HD + d] = pack_pair(sv[2 * r][d], sv[2 * r + 1][d]);
    }
}

// ---------------- flash attention (mma.sync bf16x3), plane output ----------------
#define QSTR 68
#define VSTR 84
#define ATT_SMEM ((40 * QSTR * 2 + 32 * VSTR) * (int)sizeof(uint2))

__device__ __forceinline__ void mma_bf16(float c[4], uint32_t a0, uint32_t a1,
                                         uint32_t a2, uint32_t a3, uint32_t b0, uint32_t b1) {
    asm volatile(
        "mma.sync.aligned.m16n8k16.row.col.f32.bf16.bf16.f32 "
        "{%0,%1,%2,%3}, {%4,%5,%6,%7}, {%8,%9}, {%0,%1,%2,%3};"
        : "+f"(c[0]), "+f"(c[1]), "+f"(c[2]), "+f"(c[3])
        : "r"(a0), "r"(a1), "r"(a2), "r"(a3), "r"(b0), "r"(b1));
}

__global__ void __launch_bounds__(128) attn_mma_k(const uint2* __restrict__ Qp,
                                                  const uint2* __restrict__ Kp,
                                                  const uint2* __restrict__ Vp,
                                                  const float* __restrict__ mask,
                                                  int windowed,
                                                  __nv_bfloat16* __restrict__ Ob,
                                                  __nv_bfloat16* __restrict__ Os) {
    extern __shared__ uint2 smu[];
    uint2 (*Qs)[QSTR] = (uint2(*)[QSTR])smu;
    uint2 (*Ks)[QSTR] = (uint2(*)[QSTR])(smu + 40 * QSTR);
    uint2 (*Vs)[VSTR] = (uint2(*)[VSTR])(smu + 2 * 40 * QSTR);
    int h = blockIdx.y, q0 = blockIdx.x * 64, tid = threadIdx.x;
    int w = tid >> 5, lane = tid & 31, g = lane >> 2, tg = lane & 3;

    for (int idx = tid; idx < 40 * 64; idx += 128) {
        int p = idx >> 6, c = idx & 63;
        Qs[p][c] = Qp[((long)h * 40 + p) * S_LEN + q0 + c];
    }
    float O[10][4];
#pragma unroll
    for (int ni = 0; ni < 10; ++ni) { O[ni][0] = O[ni][1] = O[ni][2] = O[ni][3] = 0.f; }
    float m0 = -3.0e38f, m1 = -3.0e38f, l0 = 0.f, l1 = 0.f;
    const float scale = 0.11180339887498949f;
    const float NEG = -3.0e38f;
    int qa = q0 + w * 16 + g;
    int kvs = windowed ? q0 : 0;
    int kve = windowed ? q0 + 64 : S_LEN;

    for (int kv0 = kvs; kv0 < kve; kv0 += 64) {
        __syncthreads();
        for (int idx = tid; idx < 40 * 64; idx += 128) {
            int p = idx >> 6, c = idx & 63;
            Ks[p][c] = Kp[((long)h * 40 + p) * S_LEN + kv0 + c];
        }
        for (int idx = tid; idx < 32 * HD; idx += 128) {
            int r = idx / HD, d = idx % HD;
            Vs[r][d] = Vp[((long)h * (S_LEN / 2) + (kv0 >> 1) + r) * HD + d];
        }
        __syncthreads();

        float s[8][4];
#pragma unroll
        for (int ni = 0; ni < 8; ++ni) { s[ni][0] = s[ni][1] = s[ni][2] = s[ni][3] = 0.f; }
#pragma unroll
        for (int ch = 0; ch < 5; ++ch) {
            int c8 = ch * 8;
            uint2 a0 = Qs[c8 + tg][w * 16 + g];
            uint2 a1 = Qs[c8 + tg][w * 16 + g + 8];
            uint2 a2 = Qs[c8 + 4 + tg][w * 16 + g];
            uint2 a3 = Qs[c8 + 4 + tg][w * 16 + g + 8];
#pragma unroll
            for (int ni = 0; ni < 8; ++ni) {
                uint2 b0 = Ks[c8 + tg][ni * 8 + g];
                uint2 b1 = Ks[c8 + 4 + tg][ni * 8 + g];
                mma_bf16(s[ni], a0.x, a1.x, a2.x, a3.x, b0.x, b1.x);
                mma_bf16(s[ni], a0.x, a1.x, a2.x, a3.x, b0.y, b1.y);
                mma_bf16(s[ni], a0.y, a1.y, a2.y, a3.y, b0.x, b1.x);
            }
        }
#pragma unroll
        for (int ni = 0; ni < 8; ++ni) {
            int col2 = ni * 8 + 2 * tg;
            float2 ma, mb;
            if (windowed) {
                const float* mb_ = mask + ((long)(q0 >> 6) * 64 + (w * 16 + g)) * 64;
                ma = *(const float2*)(mb_ + col2);
                mb = *(const float2*)(mb_ + 8 * 64 + col2);
            } else {
                ma = *(const float2*)(mask + (long)qa * S_LEN + kv0 + col2);
                mb = *(const float2*)(mask + (long)(qa + 8) * S_LEN + kv0 + col2);
            }
            s[ni][0] = s[ni][0] * scale + (1.f - ma.x) * NEG;
            s[ni][1] = s[ni][1] * scale + (1.f - ma.y) * NEG;
            s[ni][2] = s[ni][2] * scale + (1.f - mb.x) * NEG;
            s[ni][3] = s[ni][3] * scale + (1.f - mb.y) * NEG;
        }
        float t0 = -3.0e38f, t1 = -3.0e38f;
#pragma unroll
        for (int ni = 0; ni < 8; ++ni) {
            t0 = fmaxf(t0, fmaxf(s[ni][0], s[ni][1]));
            t1 = fmaxf(t1, fmaxf(s[ni][2], s[ni][3]));
        }
        t0 = fmaxf(t0, __shfl_xor_sync(0xffffffffu, t0, 1));
        t0 = fmaxf(t0, __shfl_xor_sync(0xffffffffu, t0, 2));
        t1 = fmaxf(t1, __shfl_xor_sync(0xffffffffu, t1, 1));
        t1 = fmaxf(t1, __shfl_xor_sync(0xffffffffu, t1, 2));
        float mn0 = fmaxf(m0, t0), mn1 = fmaxf(m1, t1);
        float corr0 = __expf(m0 - mn0), corr1 = __expf(m1 - mn1);
#pragma unroll
        for (int ni = 0; ni < 10; ++ni) {
            O[ni][0] *= corr0; O[ni][1] *= corr0;
            O[ni][2] *= corr1; O[ni][3] *= corr1;
        }
        float sum0 = 0.f, sum1 = 0.f;
#pragma unroll
        for (int ni = 0; ni < 8; ++ni) {
            s[ni][0] = __expf(s[ni][0] - mn0);
            s[ni][1] = __expf(s[ni][1] - mn0);
            s[ni][2] = __expf(s[ni][2] - mn1);
            s[ni][3] = __expf(s[ni][3] - mn1);
            sum0 += s[ni][0] + s[ni][1];
            sum1 += s[ni][2] + s[ni][3];
        }
        sum0 += __shfl_xor_sync(0xffffffffu, sum0, 1);
        sum0 += __shfl_xor_sync(0xffffffffu, sum0, 2);
        sum1 += __shfl_xor_sync(0xffffffffu, sum1, 1);
        sum1 += __shfl_xor_sync(0xffffffffu, sum1, 2);
        l0 = l0 * corr0 + sum0;
        l1 = l1 * corr1 + sum1;
        m0 = mn0; m1 = mn1;
#pragma unroll
        for (int ck = 0; ck < 4; ++ck) {
            uint2 p00 = pack_pair(s[2 * ck][0], s[2 * ck][1]);
            uint2 p01 = pack_pair(s[2 * ck][2], s[2 * ck][3]);
            uint2 p10 = pack_pair(s[2 * ck + 1][0], s[2 * ck + 1][1]);
            uint2 p11 = pack_pair(s[2 * ck + 1][2], s[2 * ck + 1][3]);
#pragma unroll
            for (int ni = 0; ni < 10; ++ni) {
                uint2 b0 = Vs[ck * 8 + tg][ni * 8 + g];
                uint2 b1 = Vs[ck * 8 + 4 + tg][ni * 8 + g];
                mma_bf16(O[ni], p00.x, p01.x, p10.x, p11.x, b0.x, b1.x);
                mma_bf16(O[ni], p00.x, p01.x, p10.x, p11.x, b0.y, b1.y);
                mma_bf16(O[ni], p00.y, p01.y, p10.y, p11.y, b0.x, b1.x);
            }
        }
    }
    float invl0 = 1.f / l0, invl1 = 1.f / l1;
#pragma unroll
    for (int ni = 0; ni < 10; ++ni) {
        int col = h * HD + ni * 8 + 2 * tg;
        store_plane2(Ob, Os, (long)qa * HID + col, O[ni][0] * invl0, O[ni][1] * invl0);
        store_plane2(Ob, Os, (long)(qa + 8) * HID + col, O[ni][2] * invl1, O[ni][3] * invl1);
    }
}

// ---------------- persistent plane GEMM: ldmatrix + mma.sync bf16x3 ----------------
// EPI: 0 none, 2 GELU, 3 +=res, 5 fused silu(gate)*up (interleaved cols) PACK.
#define RSTR 80
#define MAXCTAS 296

__device__ __forceinline__ void cp16(uint32_t dst, const void* src, int sz) {
    asm volatile("cp.async.cg.shared.global [%0], [%1], 16, %2;" :: "r"(dst), "l"(src), "r"(sz));
}
__device__ __forceinline__ void cp_commit() { asm volatile("cp.async.commit_group;" ::: "memory"); }
__device__ __forceinline__ void cp_wait1()  { asm volatile("cp.async.wait_group 1;" ::: "memory"); }

__device__ __forceinline__ void ldsm4(uint32_t& r0, uint32_t& r1, uint32_t& r2, uint32_t& r3,
                                      uint32_t addr) {
    asm volatile("ldmatrix.sync.aligned.m8n8.x4.shared.b16 {%0,%1,%2,%3}, [%4];"
                 : "=r"(r0), "=r"(r1), "=r"(r2), "=r"(r3) : "r"(addr));
}

template <int EPI, bool PACK, int BM>
__global__ void __launch_bounds__(256, 2) pgemm_k(
    const __nv_bfloat16* __restrict__ Apb, const __nv_bfloat16* __restrict__ Aps,
    const __nv_bfloat16* __restrict__ Wpb, const __nv_bfloat16* __restrict__ Wps,
    const float* __restrict__ bias, const float* __restrict__ bias2,
    const float* __restrict__ res,
    float* __restrict__ Cf, __nv_bfloat16* __restrict__ Cb, __nv_bfloat16* __restrict__ Cs,
    int M, int N, int K, int lda, int ldw, int ldc) {
    constexpr int ATILE = BM * RSTR;
    constexpr int BTILE = 128 * RSTR;
    constexpr int STAGE = 2 * ATILE + 2 * BTILE;
    constexpr int MI = BM / 32;
    constexpr int NCP = (2 * BM + 256) * 4;

    extern __shared__ char dsm[];
    uint32_t base = (uint32_t)__cvta_generic_to_shared(dsm);

    int tid = threadIdx.x;
    int lane = tid & 31;
    int warp = tid >> 5;
    int warpM = warp & 1;
    int warpN = warp >> 1;
    int g = lane >> 2;
    int tg = lane & 3;

    int gx = (N + 127) / 128;
    int ntiles = gx * (M / BM);
    int ntile = (K + 31) / 32;

    for (int tile = blockIdx.x; tile < ntiles; tile += gridDim.x) {
        int bmBase = (tile / gx) * BM;
        int bnBase = (tile % gx) * 128;

        float acc[MI][4][4];
#pragma unroll
        for (int mi = 0; mi < MI; ++mi)
#pragma unroll
            for (int ni = 0; ni < 4; ++ni)
#pragma unroll
                for (int r = 0; r < 4; ++r) acc[mi][ni][r] = 0.f;

        auto stage_fn = [&](int t, int s) {
            int k0 = t * 32;
            uint32_t sb = base + s * STAGE;
#pragma unroll
            for (int u = tid; u < NCP; u += 256) {
                int ru = u >> 2, c = u & 3;
                int kb = k0 + c * 8;
                int sz = 2 * (K - kb);
                sz = sz < 0 ? 0 : (sz > 16 ? 16 : sz);
                uint32_t dst;
                const __nv_bfloat16* src;
                if (ru < BM) {
                    dst = sb + ru * RSTR + c * 16;
                    src = Apb + (long)(bmBase + ru) * lda + kb;
                } else if (ru < 2 * BM) {
                    int r = ru - BM;
                    dst = sb + ATILE + r * RSTR + c * 16;
                    src = Aps + (long)(bmBase + r) * lda + kb;
                } else if (ru < 2 * BM + 128) {
                    int r = ru - 2 * BM;
                    dst = sb + 2 * ATILE + r * RSTR + c * 16;
                    src = Wpb + (long)(bnBase + r) * ldw + kb;
                    if (bnBase + r >= N) sz = 0;
                } else {
                    int r = ru - 2 * BM - 128;
                    dst = sb + 2 * ATILE + BTILE + r * RSTR + c * 16;
                    src = Wps + (long)(bnBase + r) * ldw + kb;
                    if (bnBase + r >= N) sz = 0;
                }
                cp16(dst, src, sz);
            }
        };

        stage_fn(0, 0);
        cp_commit();
        if (ntile > 1) stage_fn(1, 1);
        cp_commit();

        for (int t = 0; t < ntile; ++t) {
            cp_wait1();
            __syncthreads();
            uint32_t sb = base + (t & 1) * STAGE;

#pragma unroll
            for (int kc = 0; kc < 2; ++kc) {
                uint32_t bb[4][2], bs[4][2];
                {
                    uint32_t brow_lo = (uint32_t)(warpN * 32 + ((lane >> 4) << 3) + (lane & 7));
                    uint32_t koffB = (uint32_t)(kc * 32 + (((lane >> 3) & 1) << 4));
#pragma unroll
                    for (int p = 0; p < 2; ++p) {
                        uint32_t off = (brow_lo + p * 16) * RSTR + koffB;
                        ldsm4(bb[2 * p][0], bb[2 * p][1], bb[2 * p + 1][0], bb[2 * p + 1][1],
                              sb + 2 * ATILE + off);
                        ldsm4(bs[2 * p][0], bs[2 * p][1], bs[2 * p + 1][0], bs[2 * p + 1][1],
                              sb + 2 * ATILE + BTILE + off);
                    }
                }
                uint32_t aoffc = (uint32_t)(kc * 32 + ((lane >> 4) << 4));
#pragma unroll
                for (int mi = 0; mi < MI; ++mi) {
                    uint32_t arow = (uint32_t)(warpM * (BM / 2) + mi * 16 + (lane & 15));
                    uint32_t off = arow * RSTR + aoffc;
                    uint32_t a0, a1, a2, a3, s0, s1, s2, s3;
                    ldsm4(a0, a1, a2, a3, sb + off);
                    ldsm4(s0, s1, s2, s3, sb + ATILE + off);
#pragma unroll
                    for (int ni = 0; ni < 4; ++ni)
                        mma_bf16(acc[mi][ni], a0, a1, a2, a3, bb[ni][0], bb[ni][1]);
#pragma unroll
                    for (int ni = 0; ni < 4; ++ni)
                        mma_bf16(acc[mi][ni], a0, a1, a2, a3, bs[ni][0], bs[ni][1]);
#pragma unroll
                    for (int ni = 0; ni < 4; ++ni)
                        mma_bf16(acc[mi][ni], s0, s1, s2, s3, bb[ni][0], bb[ni][1]);
                }
            }
            __syncthreads();
            if (t + 2 < ntile) stage_fn(t + 2, t & 1);
            cp_commit();
        }

        // ---- epilogue ----
#pragma unroll
        for (int mi = 0; mi < MI; ++mi) {
            int row0 = bmBase + warpM * (BM / 2) + mi * 16 + g;
#pragma unroll
            for (int ni = 0; ni < 4; ++ni) {
                int col = bnBase + warpN * 32 + ni * 8 + 2 * tg;
                if (col >= N) continue;
#pragma unroll
                for (int rh = 0; rh < 2; ++rh) {
                    int row = row0 + rh * 8;
                    float v0 = acc[mi][ni][rh * 2 + 0];
                    float v1 = acc[mi][ni][rh * 2 + 1];
                    if (EPI == 5) {
                        int j = col >> 1;
                        float gv = v0 + bias[j];
                        float uv = v1 + bias2[j];
                        float r = (gv / (1.f + expf(-gv))) * uv;
                        uint16_t b, s;
                        split_bf16(r, b, s);
                        Cb[(long)row * ldc + j] = *(__nv_bfloat16*)&b;
                        Cs[(long)row * ldc + j] = *(__nv_bfloat16*)&s;
                    } else {
                        v0 += bias[col];
                        v1 += bias[col + 1];
                        if (EPI == 2) {
                            v0 = 0.5f * v0 * (1.f + erff(v0 * 0.70710678118654752f));
                            v1 = 0.5f * v1 * (1.f + erff(v1 * 0.70710678118654752f));
                        } else if (EPI == 3) {
                            v0 += res[(long)row * N + col];
                            v1 += res[(long)row * N + col + 1];
                        }
                        if (PACK) store_plane2(Cb, Cs, (long)row * ldc + col, v0, v1);
                        else *(float2*)(Cf + (long)row * ldc + col) = make_float2(v0, v1);
                    }
                }
            }
        }
        __syncthreads();
    }
}

// ---------------- host ----------------
template <int EPI, bool PACK>
static void launch_pg(const __nv_bfloat16* Ab, const __nv_bfloat16* As,
                      const __nv_bfloat16* Wb, const __nv_bfloat16* Ws,
                      const float* bias, const float* bias2, const float* res,
                      float* Cf, __nv_bfloat16* Cb, __nv_bfloat16* Cs,
                      int M, int N, int K, int lda, int ldw, int ldc) {
    int gx = (N + 127) / 128;
    int t128 = gx * (M / 128);
    if (t128 < MAXCTAS && (M % 64) == 0) {
        int nt = gx * (M / 64);
        int grid = nt < MAXCTAS ? nt : MAXCTAS;
        constexpr int SM = 2 * (2 * 64 * RSTR + 2 * 128 * RSTR);
        cudaFuncSetAttribute(pgemm_k<EPI, PACK, 64>,
                             cudaFuncAttributeMaxDynamicSharedMemorySize, SM);
        pgemm_k<EPI, PACK, 64><<<grid, 256, SM>>>(
            Ab, As, Wb, Ws, bias, bias2, res, Cf, Cb, Cs, M, N, K, lda, ldw, ldc);
    } else {
        int grid = t128 < MAXCTAS ? t128 : MAXCTAS;
        constexpr int SM = 2 * (2 * 128 * RSTR + 2 * 128 * RSTR);
        cudaFuncSetAttribute(pgemm_k<EPI, PACK, 128>,
                             cudaFuncAttributeMaxDynamicSharedMemorySize, SM);
        pgemm_k<EPI, PACK, 128><<<grid, 256, SM>>>(
            Ab, As, Wb, Ws, bias, bias2, res, Cf, Cb, Cs, M, N, K, lda, ldw, ldc);
    }
}

static inline void convT(const float* W, __nv_bfloat16* outB, __nv_bfloat16* outS,
                         int K, int N, int L, int ldw) {
    dim3 grid((N + 31) / 32, (K + 31) / 32, L);
    convT_k<<<grid, 256>>>(W, outB, outS, K, N, ldw);
}

#define SYM(p, g) cudaGetSymbolAddress((void**)&p, g)

extern "C" void kernel_launch(void* const* d_in, const int* in_sizes, int n_in,
                              void* d_out, int out_size) {
    const float* in_hs   = (const float*)d_in[0];
    const float* fmask   = (const float*)d_in[1];
    const float* wmask   = (const float*)d_in[2];
    const float* cosd    = (const float*)d_in[3];
    const float* sind    = (const float*)d_in[4];
    const float* norm1_w = (const float*)d_in[5];
    const float* norm2_w = (const float*)d_in[6];
    const float* qkv_w   = (const float*)d_in[7];
    const float* qkv_b   = (const float*)d_in[8];
    const float* proj_w  = (const float*)d_in[9];
    const float* proj_b  = (const float*)d_in[10];
    const float* gate_w  = (const float*)d_in[11];
    const float* gate_b  = (const float*)d_in[12];
    const float* up_w    = (const float*)d_in[13];
    const float* up_b    = (const float*)d_in[14];
    const float* down_w  = (const float*)d_in[15];
    const float* down_b  = (const float*)d_in[16];
    const float* ln_q_w  = (const float*)d_in[17];
    const float* fc1_w   = (const float*)d_in[18];
    const float* fc1_b   = (const float*)d_in[19];
    const float* fc2_w   = (const float*)d_in[20];
    const float* fc2_b   = (const float*)d_in[21];
    float* out = (float*)d_out;

    float *hs, *qkv;
    __nv_bfloat16 *wqkvB, *wqkvS, *wprojB, *wprojS, *wguB, *wguS;
    __nv_bfloat16 *wdownB, *wdownS, *wfc1B, *wfc1S, *wfc2B, *wfc2S;
    __nv_bfloat16 *xB, *xS, *aB, *aS, *gB, *gS;
    uint2 *qp, *kp, *vp;
    SYM(hs, g_hs); SYM(qkv, g_qkv);
    SYM(wqkvB, g_wqkvB); SYM(wqkvS, g_wqkvS);
    SYM(wprojB, g_wprojB); SYM(wprojS, g_wprojS);
    SYM(wguB, g_wguB); SYM(wguS, g_wguS);
    SYM(wdownB, g_wdownB); SYM(wdownS, g_wdownS);
    SYM(wfc1B, g_wfc1B); SYM(wfc1S, g_wfc1S);
    SYM(wfc2B, g_wfc2B); SYM(wfc2S, g_wfc2S);
    SYM(xB, g_xB); SYM(xS, g_xS); SYM(aB, g_aB); SYM(aS, g_aS);
    SYM(gB, g_gB); SYM(gS, g_gS);
    SYM(qp, g_qp); SYM(kp, g_kp); SYM(vp, g_vp);

    const int nhid = S_LEN * HID;
    const int ROPE_SMEM = 3 * 64 * 81 * (int)sizeof(float);
    cudaFuncSetAttribute(rope_pack_k, cudaFuncAttributeMaxDynamicSharedMemorySize, ROPE_SMEM);
    cudaFuncSetAttribute(attn_mma_k, cudaFuncAttributeMaxDynamicSharedMemorySize, ATT_SMEM);

    // 1 copy, 2 convT qkv, 3 rmsnorm, 4 qkv GEMM (ncu capture target)
    copy_k<<<(nhid + 255) / 256, 256>>>(in_hs, hs, nhid);
    convT(qkv_w, wqkvB, wqkvS, HID, 3 * HID, NLAYER, HID);
    rmsnorm_plane_k<false><<<S_LEN / 8, 256>>>(hs, norm1_w, xB, xS);
    launch_pg<0, false>(xB, xS, wqkvB, wqkvS, qkv_b, nullptr, nullptr,
                        qkv, nullptr, nullptr, S_LEN, 3 * HID, HID, HID, HID, 3 * HID);
    convT(proj_w, wprojB, wprojS, HID, HID, NLAYER, HID);
    {
        dim3 grid((INTER + 31) / 32, (HID + 31) / 32, NLAYER);
        convT2_k<<<grid, 256>>>(gate_w, up_w, wguB, wguS);
    }
    convT(down_w, wdownB, wdownS, INTER, HID, NLAYER, INTERP);
    convT(fc1_w, wfc1B, wfc1S, MERGED, MERGED, 1, MERGED);
    convT(fc2_w, wfc2B, wfc2S, MERGED, OUTDIM, 1, MERGED);

    for (int i = 0; i < NLAYER; ++i) {
        int full = (i == 3 || i == 7) ? 1 : 0;
        if (i > 0) {
            rmsnorm_plane_k<false><<<S_LEN / 8, 256>>>(hs, norm1_w + (long)i * HID, xB, xS);
            launch_pg<0, false>(xB, xS, wqkvB + (long)i * 3840 * HID, wqkvS + (long)i * 3840 * HID,
                                qkv_b + (long)i * 3 * HID, nullptr, nullptr,
                                qkv, nullptr, nullptr, S_LEN, 3 * HID, HID, HID, HID, 3 * HID);
        }
        rope_pack_k<<<dim3(S_LEN / 64, NH), 256, ROPE_SMEM>>>(qkv, cosd, sind, qp, kp, vp);
        attn_mma_k<<<dim3(S_LEN / 64, NH), 128, ATT_SMEM>>>(
            qp, kp, vp, full ? fmask : wmask, full ? 0 : 1, aB, aS);
        launch_pg<3, false>(aB, aS, wprojB + (long)i * HID * HID, wprojS + (long)i * HID * HID,
                            proj_b + (long)i * HID, nullptr, hs,
                            hs, nullptr, nullptr, S_LEN, HID, HID, HID, HID, HID);
        rmsnorm_plane_k<false><<<S_LEN / 8, 256>>>(hs, norm2_w + (long)i * HID, xB, xS);
        // fused gate+up: interleaved N = 2*INTER, writes packed gB/gS [row][INTERP]
        launch_pg<5, true>(xB, xS, wguB + (long)i * 2 * INTER * HID, wguS + (long)i * 2 * INTER * HID,
                           gate_b + (long)i * INTER, up_b + (long)i * INTER, nullptr,
                           nullptr, gB, gS, S_LEN, 2 * INTER, HID, HID, HID, INTERP);
        launch_pg<3, false>(gB, gS, wdownB + (long)i * HID * INTERP, wdownS + (long)i * HID * INTERP,
                            down_b + (long)i * HID, nullptr, hs,
                            hs, nullptr, nullptr, S_LEN, HID, INTER, INTERP, INTERP, HID);
    }

    // patch merger
    rmsnorm_plane_k<true><<<S_LEN / 8, 256>>>(hs, ln_q_w, xB, xS);
    launch_pg<2, true>(xB, xS, wfc1B, wfc1S, fc1_b, nullptr, nullptr,
                       nullptr, aB, aS, MTOK, MERGED, MERGED, MERGED, MERGED, MERGED);
    launch_pg<0, false>(aB, aS, wfc2B, wfc2S, fc2_b, nullptr, nullptr,
                        out, nullptr, nullptr, MTOK, OUTDIM, MERGED, MERGED, MERGED, OUTDIM);
}